// round 3
// baseline (speedup 1.0000x reference)
#include <cuda_runtime.h>

// ---------------- problem constants ----------------
// B=1024, N_TOK=65, C=768, H=12, D=64, L=256
#define NBATCH 1024
#define NT     65
#define CH     768
#define NH     12
#define DH     64

// scratch (device globals: allocation-free rule). 16B-aligned for float4 access.
__device__ __align__(16) float g_q[51118080];     // [B,H,NT,DH]
__device__ __align__(16) float g_k[51118080];
__device__ __align__(16) float g_v[51118080];
__device__ __align__(16) float g_bias[51916800];  // [B,H,65,65]
__device__ __align__(16) float g_att[51118080];   // [B,NT,CH]  (post-attention, pre-proj)
__device__ __align__(16) float g_lat1[524288];    // [1024,512]
__device__ __align__(16) float g_lat2[3145728];   // [1024,3072]

// ---------------- generic 64x64x16 fp32 GEMM: C = A(MxK) @ Bw(NxK)^T ----------------
// MODE 0: scatter epilogue into g_q/g_k/g_v (qkv projection)
// MODE 1: plain row-major store to Cout with ldc
#define BM 64
#define BN 64
#define BK 16

template<int MODE>
__global__ __launch_bounds__(256)
void gemm64(const float* __restrict__ A, int lda,
            const float* __restrict__ Bw,
            float* __restrict__ Cout, int ldc,
            int M, int N, int K)
{
    __shared__ __align__(16) float As[BK][BM + 4];
    __shared__ __align__(16) float Bs[BK][BN + 4];

    const int tid = threadIdx.x;
    const int tx = tid & 15;          // 0..15 -> 4 cols each
    const int ty = tid >> 4;          // 0..15 -> 4 rows each
    const int bm = blockIdx.y * BM;
    const int bn = blockIdx.x * BN;

    const int lr = tid >> 2;          // 0..63
    const int lc = (tid & 3) << 2;    // 0,4,8,12

    float acc[4][4];
#pragma unroll
    for (int i = 0; i < 4; i++)
#pragma unroll
        for (int j = 0; j < 4; j++) acc[i][j] = 0.f;

    const float* Aptr = A + (size_t)(bm + lr) * lda + lc;   // M always multiple of 64 here
    const bool   bok  = (bn + lr) < N;
    const float* Bptr = Bw + (size_t)(bn + lr) * K + lc;

    for (int k0 = 0; k0 < K; k0 += BK) {
        float4 av = *(const float4*)(Aptr + k0);
        float4 bv = bok ? *(const float4*)(Bptr + k0) : make_float4(0.f, 0.f, 0.f, 0.f);

        As[lc + 0][lr] = av.x; As[lc + 1][lr] = av.y;
        As[lc + 2][lr] = av.z; As[lc + 3][lr] = av.w;
        Bs[lc + 0][lr] = bv.x; Bs[lc + 1][lr] = bv.y;
        Bs[lc + 2][lr] = bv.z; Bs[lc + 3][lr] = bv.w;
        __syncthreads();

#pragma unroll
        for (int kk = 0; kk < BK; kk++) {
            float4 a4 = *(const float4*)&As[kk][ty * 4];
            float4 b4 = *(const float4*)&Bs[kk][tx * 4];
            float ar[4] = {a4.x, a4.y, a4.z, a4.w};
            float br[4] = {b4.x, b4.y, b4.z, b4.w};
#pragma unroll
            for (int i = 0; i < 4; i++)
#pragma unroll
                for (int j = 0; j < 4; j++)
                    acc[i][j] += ar[i] * br[j];
        }
        __syncthreads();
    }

#pragma unroll
    for (int i = 0; i < 4; i++) {
        const int m = bm + ty * 4 + i;
#pragma unroll
        for (int j = 0; j < 4; j++) {
            const int n = bn + tx * 4 + j;
            if (n >= N) continue;
            const float v = acc[i][j];
            if (MODE == 0) {
                // n in [0, 2304): s*768 + h*64 + d ; m = b*65 + t
                const int s   = n / CH;
                const int rem = n - s * CH;
                const int h   = rem >> 6;
                const int d   = rem & 63;
                const int b   = m / NT;
                const int t   = m - b * NT;
                const size_t idx = (((size_t)(b * NH + h)) * NT + t) * DH + d;
                float* dst = (s == 0) ? g_q : (s == 1) ? g_k : g_v;
                dst[idx] = v;
            } else {
                Cout[(size_t)m * ldc + n] = v;
            }
        }
    }
}

// ---------------- per-head-dim LayerNorm on q (x scale) and k ----------------
__global__ __launch_bounds__(256)
void qk_ln_kernel(const float* __restrict__ qn_g, const float* __restrict__ qn_b,
                  const float* __restrict__ kn_g, const float* __restrict__ kn_b)
{
    const long long R = (long long)NBATCH * NH * NT;  // 798720
    long long wg = (((long long)blockIdx.x * blockDim.x) + threadIdx.x) >> 5;
    if (wg >= 2 * R) return;
    const int lane = threadIdx.x & 31;
    const bool isK = (wg >= R);
    const long long row = isK ? (wg - R) : wg;
    float* base = (isK ? g_k : g_q) + row * DH;

    float x0 = base[lane], x1 = base[lane + 32];
    float s = x0 + x1, ss = x0 * x0 + x1 * x1;
#pragma unroll
    for (int o = 16; o; o >>= 1) {
        s  += __shfl_xor_sync(0xffffffffu, s,  o);
        ss += __shfl_xor_sync(0xffffffffu, ss, o);
    }
    const float mean = s * (1.f / 64.f);
    const float var  = ss * (1.f / 64.f) - mean * mean;
    const float inv  = rsqrtf(var + 1e-5f);
    const float* g = isK ? kn_g : qn_g;
    const float* b = isK ? kn_b : qn_b;
    const float scale = isK ? 1.f : 0.125f;   // D^-0.5 = 1/8 applied to q after LN
    base[lane]      = ((x0 - mean) * inv * g[lane]      + b[lane])      * scale;
    base[lane + 32] = ((x1 - mean) * inv * g[lane + 32] + b[lane + 32]) * scale;
}

// ---------------- block reduce (sum, sumsq) for 256-thread blocks ----------------
__device__ __forceinline__ float2 block_reduce2(float s, float ss, float* shm)
{
#pragma unroll
    for (int o = 16; o; o >>= 1) {
        s  += __shfl_xor_sync(0xffffffffu, s,  o);
        ss += __shfl_xor_sync(0xffffffffu, ss, o);
    }
    const int w = threadIdx.x >> 5, lane = threadIdx.x & 31;
    if (lane == 0) { shm[w] = s; shm[8 + w] = ss; }
    __syncthreads();
    if (threadIdx.x < 32) {
        s  = (lane < 8) ? shm[lane]     : 0.f;
        ss = (lane < 8) ? shm[8 + lane] : 0.f;
#pragma unroll
        for (int o = 4; o; o >>= 1) {
            s  += __shfl_xor_sync(0xffffffffu, s,  o);
            ss += __shfl_xor_sync(0xffffffffu, ss, o);
        }
        if (lane == 0) { shm[0] = s; shm[1] = ss; }
    }
    __syncthreads();
    return make_float2(shm[0], shm[1]);
}

// ---------------- LN + SiLU over 512-wide rows ----------------
__global__ __launch_bounds__(256)
void ln_silu512(float* __restrict__ data, const float* __restrict__ g, const float* __restrict__ b)
{
    __shared__ float shm[16];
    const int row = blockIdx.x, tid = threadIdx.x;
    float* p = data + (size_t)row * 512;
    float x0 = p[tid], x1 = p[tid + 256];
    float2 r = block_reduce2(x0 + x1, x0 * x0 + x1 * x1, shm);
    const float mean = r.x * (1.f / 512.f);
    const float var  = r.y * (1.f / 512.f) - mean * mean;
    const float inv  = rsqrtf(var + 1e-5f);
    float y0 = (x0 - mean) * inv * g[tid]       + b[tid];
    float y1 = (x1 - mean) * inv * g[tid + 256] + b[tid + 256];
    p[tid]       = y0 / (1.f + __expf(-y0));
    p[tid + 256] = y1 / (1.f + __expf(-y1));
}

// ---------------- LN over 3072-wide rows ----------------
__global__ __launch_bounds__(256)
void ln3072(float* __restrict__ data, const float* __restrict__ g, const float* __restrict__ b)
{
    __shared__ float shm[16];
    const int row = blockIdx.x, tid = threadIdx.x;
    float* p = data + (size_t)row * 3072;
    float x[12];
    float s = 0.f, ss = 0.f;
#pragma unroll
    for (int i = 0; i < 12; i++) {
        x[i] = p[tid + i * 256];
        s += x[i]; ss += x[i] * x[i];
    }
    float2 r = block_reduce2(s, ss, shm);
    const float mean = r.x * (1.f / 3072.f);
    const float var  = r.y * (1.f / 3072.f) - mean * mean;
    const float inv  = rsqrtf(var + 1e-5f);
#pragma unroll
    for (int i = 0; i < 12; i++) {
        const int c = tid + i * 256;
        p[c] = (x[i] - mean) * inv * g[c] + b[c];
    }
}

// ---------------- fused attention: per (b,h) block ----------------
// smem: sV FIRST (16B-aligned float4 traffic), K padded to stride 65
// (conflict-free column reads), per-warp P rows.
__global__ __launch_bounds__(256)
void attn_kernel()
{
    __shared__ __align__(16) float sV[NT * DH];   // 4160 floats, offset 0 -> float4-safe
    __shared__ __align__(16) float sK[NT * 65];   // 4225 (scalar access only)
    __shared__ __align__(16) float sP[8 * 65];    // per-warp softmax row (scalar)

    const int bh  = blockIdx.x;
    const int tid = threadIdx.x;
    const size_t base = (size_t)bh * (NT * DH);

    const float4* k4 = (const float4*)(g_k + base);
    const float4* v4 = (const float4*)(g_v + base);
    for (int i = tid; i < NT * (DH / 4); i += 256) {   // 1040 float4s
        ((float4*)sV)[i] = v4[i];
        float4 kv = k4[i];
        const int r = i >> 4, c = (i & 15) << 2;
        float* d = sK + r * 65 + c;
        d[0] = kv.x; d[1] = kv.y; d[2] = kv.z; d[3] = kv.w;
    }
    __syncthreads();

    const int w = tid >> 5, lane = tid & 31;
    const float* bp = g_bias + (size_t)bh * (NT * NT);
    const float* gq = g_q + base;
    const int b = bh / NH, h = bh - b * NH;

    for (int i = w; i < NT; i += 8) {
        // Q row into registers (broadcast via shuffles)
        float q0 = gq[i * DH + lane];
        float q1 = gq[i * DH + lane + 32];
        float qreg[64];
#pragma unroll
        for (int d = 0; d < 32; d++) qreg[d]      = __shfl_sync(0xffffffffu, q0, d);
#pragma unroll
        for (int d = 0; d < 32; d++) qreg[32 + d] = __shfl_sync(0xffffffffu, q1, d);

        // scores: s[j] = q.k[j] + bias
        for (int j = lane; j < NT; j += 32) {
            const float* kr = sK + j * 65;
            float s = bp[i * NT + j];
#pragma unroll
            for (int d = 0; d < 64; d++) s += qreg[d] * kr[d];
            sP[w * 65 + j] = s;
        }
        __syncwarp();

        float v0 = sP[w * 65 + lane];
        float v1 = sP[w * 65 + 32 + lane];
        float v2 = (lane == 0) ? sP[w * 65 + 64] : -1e30f;
        float mx = fmaxf(v0, fmaxf(v1, v2));
#pragma unroll
        for (int o = 16; o; o >>= 1) mx = fmaxf(mx, __shfl_xor_sync(0xffffffffu, mx, o));
        float e0 = __expf(v0 - mx), e1 = __expf(v1 - mx);
        float e2 = (lane == 0) ? __expf(v2 - mx) : 0.f;
        float sum = e0 + e1 + e2;
#pragma unroll
        for (int o = 16; o; o >>= 1) sum += __shfl_xor_sync(0xffffffffu, sum, o);
        sP[w * 65 + lane]      = e0;
        sP[w * 65 + 32 + lane] = e1;
        if (lane == 0) sP[w * 65 + 64] = e2;
        __syncwarp();
        const float inv = 1.f / sum;

        // out[i, :] = P @ V
        float a0 = 0.f, a1 = 0.f;
        for (int m = 0; m < NT; m++) {
            const float p = sP[w * 65 + m];
            a0 += p * sV[m * DH + lane];
            a1 += p * sV[m * DH + lane + 32];
        }
        float* op = g_att + ((size_t)(b * NT + i)) * CH + h * DH;
        op[lane]      = a0 * inv;
        op[lane + 32] = a1 * inv;
        __syncwarp();
    }
}

// ---------------- host launcher ----------------
extern "C" void kernel_launch(void* const* d_in, const int* in_sizes, int n_in,
                              void* d_out, int out_size)
{
    const float* x       = (const float*)d_in[0];
    const float* qkv_w   = (const float*)d_in[1];
    const float* proj_w  = (const float*)d_in[2];
    const float* qn_g    = (const float*)d_in[3];
    const float* qn_b    = (const float*)d_in[4];
    const float* kn_g    = (const float*)d_in[5];
    const float* kn_b    = (const float*)d_in[6];
    const float* sg_w1   = (const float*)d_in[7];
    const float* sg_ln1g = (const float*)d_in[8];
    const float* sg_ln1b = (const float*)d_in[9];
    const float* sg_w2   = (const float*)d_in[10];
    const float* sg_ln2g = (const float*)d_in[11];
    const float* sg_ln2b = (const float*)d_in[12];
    const float* sg_bw   = (const float*)d_in[13];
    float* out = (float*)d_out;

    float *p_lat1, *p_lat2, *p_bias, *p_att;
    cudaGetSymbolAddress((void**)&p_lat1, g_lat1);
    cudaGetSymbolAddress((void**)&p_lat2, g_lat2);
    cudaGetSymbolAddress((void**)&p_bias, g_bias);
    cudaGetSymbolAddress((void**)&p_att,  g_att);

    const dim3 blk(256);

    // 1. qkv = x @ qkv_w^T  -> scatter into g_q/g_k/g_v  (M=66560, N=2304, K=768)
    gemm64<0><<<dim3(2304 / 64, 66560 / 64), blk>>>(x, CH, qkv_w, nullptr, 0, 66560, 2304, CH);

    // 2. per-head LN on q (x 1/8) and k : 2*798720 rows, 8 warps/block
    qk_ln_kernel<<<199680, 256>>>(qn_g, qn_b, kn_g, kn_b);

    // 3. lat1 = cls @ sg_w1^T  (cls rows stride N*C)
    gemm64<1><<<dim3(512 / 64, 1024 / 64), blk>>>(x, NT * CH, sg_w1, p_lat1, 512, 1024, 512, CH);
    // 4. LN + SiLU over 512
    ln_silu512<<<1024, 256>>>(p_lat1, sg_ln1g, sg_ln1b);
    // 5. lat2 = lat1 @ sg_w2^T
    gemm64<1><<<dim3(3072 / 64, 1024 / 64), blk>>>(p_lat1, 512, sg_w2, p_lat2, 3072, 1024, 3072, 512);
    // 6. LN over 3072
    ln3072<<<1024, 256>>>(p_lat2, sg_ln2g, sg_ln2b);
    // 7. bias = lat2(view 12288x256) @ sg_bias_w^T  (N=4225)
    gemm64<1><<<dim3((4225 + 63) / 64, 12288 / 64), blk>>>(p_lat2, 256, sg_bw, p_bias, 4225, 12288, 4225, 256);

    // 8. attention (one block per (b,h))
    attn_kernel<<<NBATCH * NH, 256>>>();

    // 9. out = att @ proj_w^T
    gemm64<1><<<dim3(768 / 64, 66560 / 64), blk>>>(p_att, CH, proj_w, out, CH, 66560, CH, CH);
}

// round 5
// speedup vs baseline: 1.9702x; 1.9702x over previous
#include <cuda_runtime.h>
#include <cuda_bf16.h>
#include <cstdint>

// ---------------- problem constants ----------------
#define NBATCH 1024
#define NT     65
#define CH     768
#define NH     12
#define DH     64

// ---------------- fp32 scratch ----------------
__device__ __align__(16) float g_q[51118080];     // [B,H,NT,DH]
__device__ __align__(16) float g_k[51118080];
__device__ __align__(16) float g_v[51118080];
__device__ __align__(16) float g_bias[51916800];  // [B*H,65*65]
__device__ __align__(16) float g_att[51118080];   // [B,NT,CH]
__device__ __align__(16) float g_lat1[524288];    // [1024,512]
__device__ __align__(16) float g_lat2[3145728];   // [1024,3072]

// ---------------- bf16 hi|lo split scratch (row = [hi(K) | lo(K)]) ----------------
__device__ __align__(16) __nv_bfloat16 g_xbf[102236160];   // 66560 x 1536
__device__ __align__(16) __nv_bfloat16 g_attbf[102236160]; // 66560 x 1536
__device__ __align__(16) __nv_bfloat16 g_wqkv[3538944];    // 2304 x 1536
__device__ __align__(16) __nv_bfloat16 g_wproj[1179648];   // 768 x 1536
__device__ __align__(16) __nv_bfloat16 g_clsbf[1572864];   // 1024 x 1536
__device__ __align__(16) __nv_bfloat16 g_w1bf[786432];     // 512 x 1536
__device__ __align__(16) __nv_bfloat16 g_l1bf[1048576];    // 1024 x 1024
__device__ __align__(16) __nv_bfloat16 g_w2bf[3145728];    // 3072 x 1024
__device__ __align__(16) __nv_bfloat16 g_l2bf[6291456];    // 12288 x 512
__device__ __align__(16) __nv_bfloat16 g_wbbf[2228224];    // 4352 x 512 (rows >= 4225 zero)

// ---------------- helpers ----------------
__device__ __forceinline__ uint32_t s2u(const void* p) {
    uint32_t a;
    asm("{ .reg .u64 t; cvta.to.shared.u64 t, %1; cvt.u32.u64 %0, t; }" : "=r"(a) : "l"(p));
    return a;
}
__device__ __forceinline__ void ldsm4(uint32_t* r, uint32_t addr) {
    asm volatile("ldmatrix.sync.aligned.m8n8.x4.shared.b16 {%0,%1,%2,%3}, [%4];"
        : "=r"(r[0]), "=r"(r[1]), "=r"(r[2]), "=r"(r[3]) : "r"(addr));
}
__device__ __forceinline__ void mma16816(float* d, const uint32_t* a, uint32_t b0, uint32_t b1) {
    asm volatile(
        "mma.sync.aligned.m16n8k16.row.col.f32.bf16.bf16.f32 "
        "{%0,%1,%2,%3}, {%4,%5,%6,%7}, {%8,%9}, {%0,%1,%2,%3};"
        : "+f"(d[0]), "+f"(d[1]), "+f"(d[2]), "+f"(d[3])
        : "r"(a[0]), "r"(a[1]), "r"(a[2]), "r"(a[3]), "r"(b0), "r"(b1));
}

// ---------------- fp32 -> bf16 hi|lo split (one block per row) ----------------
__global__ void conv_split(const float* __restrict__ src, int lds,
                           __nv_bfloat16* __restrict__ dst, int K, int rowsValid)
{
    const int r = blockIdx.x;
    const float* s = src + (size_t)r * lds;
    __nv_bfloat16* d = dst + (size_t)r * 2 * K;
    const bool valid = r < rowsValid;
    for (int c = threadIdx.x; c < K; c += blockDim.x) {
        float v = valid ? s[c] : 0.f;
        __nv_bfloat16 h = __float2bfloat16(v);
        float lo = v - __bfloat162float(h);
        d[c]     = h;
        d[K + c] = __float2bfloat16(lo);
    }
}

// ---------------- mma.sync bf16-split GEMM: C = A @ B^T ----------------
// A: M x 2K [hi|lo], B: N x 2K [hi|lo]. Three passes (Ah,Bh)(Ah,Bl)(Al,Bh)
// accumulated in fp32 register fragments. 128x128 CTA tile, 8 warps (2x4),
// each warp 64x32 via m16n8k16 atoms. K-chunk=32, double-buffered cp.async.
// MODE 0: qkv scatter epilogue; MODE 1: plain store with N guard.
#define KC   32
#define LDS_ 40   // padded bf16 row stride (80B, multiple of 16B)

template<int MODE>
__global__ __launch_bounds__(256, 2)
void gemm_mma(const __nv_bfloat16* __restrict__ A, int lda,
              const __nv_bfloat16* __restrict__ B, int ldb,
              float* __restrict__ C, int ldc, int M, int N, int K)
{
    __shared__ __align__(16) __nv_bfloat16 sA[2][128 * LDS_];
    __shared__ __align__(16) __nv_bfloat16 sB[2][128 * LDS_];

    const int tid = threadIdx.x, wid = tid >> 5, lane = tid & 31;
    const int wm = wid & 1, wn = wid >> 1;            // 2 x 4 warp grid
    const int bm = blockIdx.y * 128, bn = blockIdx.x * 128;
    const int nk = K / KC, total = 3 * nk;

    const uint32_t uA[2] = { s2u(sA[0]), s2u(sA[1]) };
    const uint32_t uB[2] = { s2u(sB[0]), s2u(sB[1]) };

    float acc[4][4][4];
#pragma unroll
    for (int i = 0; i < 4; i++)
#pragma unroll
        for (int j = 0; j < 4; j++)
#pragma unroll
            for (int e = 0; e < 4; e++) acc[i][j][e] = 0.f;

    // per-chunk loads: 1024 x 16B (A:512, B:512), 4 per thread
    auto loads = [&](int t, int st) {
        const int p = t / nk, c = t - p * nk;
        const int aOff = (p == 2 ? K : 0) + c * KC;
        const int bOff = (p == 1 ? K : 0) + c * KC;
#pragma unroll
        for (int i = 0; i < 4; i++) {
            const int idx = tid + i * 256;
            const int id2 = idx & 511;
            const int r = id2 >> 2, cc = id2 & 3;
            if (idx < 512) {
                const void* g = (const void*)(A + (size_t)(bm + r) * lda + aOff + cc * 8);
                asm volatile("cp.async.cg.shared.global [%0], [%1], 16;"
                             :: "r"(uA[st] + (uint32_t)(r * LDS_ + cc * 8) * 2), "l"(g));
            } else {
                const void* g = (const void*)(B + (size_t)(bn + r) * ldb + bOff + cc * 8);
                asm volatile("cp.async.cg.shared.global [%0], [%1], 16;"
                             :: "r"(uB[st] + (uint32_t)(r * LDS_ + cc * 8) * 2), "l"(g));
            }
        }
        asm volatile("cp.async.commit_group;");
    };

    loads(0, 0);
    for (int t = 0; t < total; ++t) {
        const int st = t & 1;
        if (t + 1 < total) {
            loads(t + 1, st ^ 1);
            asm volatile("cp.async.wait_group 1;");
        } else {
            asm volatile("cp.async.wait_group 0;");
        }
        __syncthreads();

        const uint32_t wAb = uA[st] + (uint32_t)(wm * 64 * LDS_) * 2;
        const uint32_t wBb = uB[st] + (uint32_t)(wn * 32 * LDS_) * 2;
#pragma unroll
        for (int ks = 0; ks < 2; ++ks) {
            uint32_t a[4][4], b[2][4];
#pragma unroll
            for (int mt = 0; mt < 4; ++mt) {
                const uint32_t addr = wAb +
                    (uint32_t)((mt * 16 + (lane & 15)) * LDS_ + ks * 16 + (lane >> 4) * 8) * 2;
                ldsm4(a[mt], addr);
            }
#pragma unroll
            for (int ng = 0; ng < 2; ++ng) {
                const uint32_t addr = wBb +
                    (uint32_t)((ng * 16 + ((lane >> 4) & 1) * 8 + (lane & 7)) * LDS_ +
                               ks * 16 + ((lane >> 3) & 1) * 8) * 2;
                ldsm4(b[ng], addr);
            }
#pragma unroll
            for (int mt = 0; mt < 4; ++mt)
#pragma unroll
                for (int nt = 0; nt < 4; ++nt)
                    mma16816(acc[mt][nt], a[mt], b[nt >> 1][(nt & 1) * 2], b[nt >> 1][(nt & 1) * 2 + 1]);
        }
        __syncthreads();
    }

    // epilogue
    const int gr = lane >> 2, gc = (lane & 3) * 2;
#pragma unroll
    for (int mt = 0; mt < 4; ++mt) {
#pragma unroll
        for (int nt = 0; nt < 4; ++nt) {
#pragma unroll
            for (int e = 0; e < 4; ++e) {
                const int m = bm + wm * 64 + mt * 16 + gr + (e >> 1) * 8;
                const int n = bn + wn * 32 + nt * 8 + gc + (e & 1);
                const float v = acc[mt][nt][e];
                if (MODE == 0) {
                    // n in [0,2304): s*768 + h*64 + d ; m = b*65 + t
                    const int s   = n / CH;
                    const int rem = n - s * CH;
                    const int h   = rem >> 6;
                    const int d   = rem & 63;
                    const int bb  = m / NT;
                    const int tt  = m - bb * NT;
                    const size_t idx = (((size_t)(bb * NH + h)) * NT + tt) * DH + d;
                    float* dst = (s == 0) ? g_q : (s == 1) ? g_k : g_v;
                    dst[idx] = v;
                } else {
                    if (n < N) C[(size_t)m * ldc + n] = v;
                }
            }
        }
    }
}

// ---------------- per-head-dim LayerNorm on q (x 1/8) and k ----------------
__global__ __launch_bounds__(256)
void qk_ln_kernel(const float* __restrict__ qn_g, const float* __restrict__ qn_b,
                  const float* __restrict__ kn_g, const float* __restrict__ kn_b)
{
    const long long R = (long long)NBATCH * NH * NT;
    long long wg = (((long long)blockIdx.x * blockDim.x) + threadIdx.x) >> 5;
    if (wg >= 2 * R) return;
    const int lane = threadIdx.x & 31;
    const bool isK = (wg >= R);
    const long long row = isK ? (wg - R) : wg;
    float* base = (isK ? g_k : g_q) + row * DH;

    float x0 = base[lane], x1 = base[lane + 32];
    float s = x0 + x1, ss = x0 * x0 + x1 * x1;
#pragma unroll
    for (int o = 16; o; o >>= 1) {
        s  += __shfl_xor_sync(0xffffffffu, s,  o);
        ss += __shfl_xor_sync(0xffffffffu, ss, o);
    }
    const float mean = s * (1.f / 64.f);
    const float var  = ss * (1.f / 64.f) - mean * mean;
    const float inv  = rsqrtf(var + 1e-5f);
    const float* g = isK ? kn_g : qn_g;
    const float* b = isK ? kn_b : qn_b;
    const float scale = isK ? 1.f : 0.125f;
    base[lane]      = ((x0 - mean) * inv * g[lane]      + b[lane])      * scale;
    base[lane + 32] = ((x1 - mean) * inv * g[lane + 32] + b[lane + 32]) * scale;
}

// ---------------- block reduce helper ----------------
__device__ __forceinline__ float2 block_reduce2(float s, float ss, float* shm)
{
#pragma unroll
    for (int o = 16; o; o >>= 1) {
        s  += __shfl_xor_sync(0xffffffffu, s,  o);
        ss += __shfl_xor_sync(0xffffffffu, ss, o);
    }
    const int w = threadIdx.x >> 5, lane = threadIdx.x & 31;
    if (lane == 0) { shm[w] = s; shm[8 + w] = ss; }
    __syncthreads();
    if (threadIdx.x < 32) {
        s  = (lane < 8) ? shm[lane]     : 0.f;
        ss = (lane < 8) ? shm[8 + lane] : 0.f;
#pragma unroll
        for (int o = 4; o; o >>= 1) {
            s  += __shfl_xor_sync(0xffffffffu, s,  o);
            ss += __shfl_xor_sync(0xffffffffu, ss, o);
        }
        if (lane == 0) { shm[0] = s; shm[1] = ss; }
    }
    __syncthreads();
    return make_float2(shm[0], shm[1]);
}

__global__ __launch_bounds__(256)
void ln_silu512(float* __restrict__ data, const float* __restrict__ g, const float* __restrict__ b)
{
    __shared__ float shm[16];
    const int row = blockIdx.x, tid = threadIdx.x;
    float* p = data + (size_t)row * 512;
    float x0 = p[tid], x1 = p[tid + 256];
    float2 r = block_reduce2(x0 + x1, x0 * x0 + x1 * x1, shm);
    const float mean = r.x * (1.f / 512.f);
    const float var  = r.y * (1.f / 512.f) - mean * mean;
    const float inv  = rsqrtf(var + 1e-5f);
    float y0 = (x0 - mean) * inv * g[tid]       + b[tid];
    float y1 = (x1 - mean) * inv * g[tid + 256] + b[tid + 256];
    p[tid]       = y0 / (1.f + __expf(-y0));
    p[tid + 256] = y1 / (1.f + __expf(-y1));
}

__global__ __launch_bounds__(256)
void ln3072(float* __restrict__ data, const float* __restrict__ g, const float* __restrict__ b)
{
    __shared__ float shm[16];
    const int row = blockIdx.x, tid = threadIdx.x;
    float* p = data + (size_t)row * 3072;
    float x[12];
    float s = 0.f, ss = 0.f;
#pragma unroll
    for (int i = 0; i < 12; i++) {
        x[i] = p[tid + i * 256];
        s += x[i]; ss += x[i] * x[i];
    }
    float2 r = block_reduce2(s, ss, shm);
    const float mean = r.x * (1.f / 3072.f);
    const float var  = r.y * (1.f / 3072.f) - mean * mean;
    const float inv  = rsqrtf(var + 1e-5f);
#pragma unroll
    for (int i = 0; i < 12; i++) {
        const int c = tid + i * 256;
        p[c] = (x[i] - mean) * inv * g[c] + b[c];
    }
}

// ---------------- fused attention: per (b,h) block (fp32) ----------------
__global__ __launch_bounds__(256)
void attn_kernel()
{
    __shared__ __align__(16) float sV[NT * DH];
    __shared__ __align__(16) float sK[NT * 65];
    __shared__ __align__(16) float sP[8 * 65];

    const int bh  = blockIdx.x;
    const int tid = threadIdx.x;
    const size_t base = (size_t)bh * (NT * DH);

    const float4* k4 = (const float4*)(g_k + base);
    const float4* v4 = (const float4*)(g_v + base);
    for (int i = tid; i < NT * (DH / 4); i += 256) {
        ((float4*)sV)[i] = v4[i];
        float4 kv = k4[i];
        const int r = i >> 4, c = (i & 15) << 2;
        float* d = sK + r * 65 + c;
        d[0] = kv.x; d[1] = kv.y; d[2] = kv.z; d[3] = kv.w;
    }
    __syncthreads();

    const int w = tid >> 5, lane = tid & 31;
    const float* bp = g_bias + (size_t)bh * (NT * NT);
    const float* gq = g_q + base;
    const int b = bh / NH, h = bh - b * NH;

    for (int i = w; i < NT; i += 8) {
        float q0 = gq[i * DH + lane];
        float q1 = gq[i * DH + lane + 32];
        float qreg[64];
#pragma unroll
        for (int d = 0; d < 32; d++) qreg[d]      = __shfl_sync(0xffffffffu, q0, d);
#pragma unroll
        for (int d = 0; d < 32; d++) qreg[32 + d] = __shfl_sync(0xffffffffu, q1, d);

        for (int j = lane; j < NT; j += 32) {
            const float* kr = sK + j * 65;
            float s = bp[i * NT + j];
#pragma unroll
            for (int d = 0; d < 64; d++) s += qreg[d] * kr[d];
            sP[w * 65 + j] = s;
        }
        __syncwarp();

        float v0 = sP[w * 65 + lane];
        float v1 = sP[w * 65 + 32 + lane];
        float v2 = (lane == 0) ? sP[w * 65 + 64] : -1e30f;
        float mx = fmaxf(v0, fmaxf(v1, v2));
#pragma unroll
        for (int o = 16; o; o >>= 1) mx = fmaxf(mx, __shfl_xor_sync(0xffffffffu, mx, o));
        float e0 = __expf(v0 - mx), e1 = __expf(v1 - mx);
        float e2 = (lane == 0) ? __expf(v2 - mx) : 0.f;
        float sum = e0 + e1 + e2;
#pragma unroll
        for (int o = 16; o; o >>= 1) sum += __shfl_xor_sync(0xffffffffu, sum, o);
        sP[w * 65 + lane]      = e0;
        sP[w * 65 + 32 + lane] = e1;
        if (lane == 0) sP[w * 65 + 64] = e2;
        __syncwarp();
        const float inv = 1.f / sum;

        float a0 = 0.f, a1 = 0.f;
        for (int m = 0; m < NT; m++) {
            const float p = sP[w * 65 + m];
            a0 += p * sV[m * DH + lane];
            a1 += p * sV[m * DH + lane + 32];
        }
        float* op = g_att + ((size_t)(b * NT + i)) * CH + h * DH;
        op[lane]      = a0 * inv;
        op[lane + 32] = a1 * inv;
        __syncwarp();
    }
}

// ---------------- host launcher ----------------
extern "C" void kernel_launch(void* const* d_in, const int* in_sizes, int n_in,
                              void* d_out, int out_size)
{
    const float* x       = (const float*)d_in[0];
    const float* qkv_w   = (const float*)d_in[1];
    const float* proj_w  = (const float*)d_in[2];
    const float* qn_g    = (const float*)d_in[3];
    const float* qn_b    = (const float*)d_in[4];
    const float* kn_g    = (const float*)d_in[5];
    const float* kn_b    = (const float*)d_in[6];
    const float* sg_w1   = (const float*)d_in[7];
    const float* sg_ln1g = (const float*)d_in[8];
    const float* sg_ln1b = (const float*)d_in[9];
    const float* sg_w2   = (const float*)d_in[10];
    const float* sg_ln2g = (const float*)d_in[11];
    const float* sg_ln2b = (const float*)d_in[12];
    const float* sg_bw   = (const float*)d_in[13];
    float* out = (float*)d_out;

    float *p_lat1, *p_lat2, *p_bias, *p_att;
    cudaGetSymbolAddress((void**)&p_lat1, g_lat1);
    cudaGetSymbolAddress((void**)&p_lat2, g_lat2);
    cudaGetSymbolAddress((void**)&p_bias, g_bias);
    cudaGetSymbolAddress((void**)&p_att,  g_att);
    __nv_bfloat16 *pxbf, *pattbf, *pwqkv, *pwproj, *pcls, *pw1, *pl1, *pw2, *pl2, *pwb;
    cudaGetSymbolAddress((void**)&pxbf,  g_xbf);
    cudaGetSymbolAddress((void**)&pattbf,g_attbf);
    cudaGetSymbolAddress((void**)&pwqkv, g_wqkv);
    cudaGetSymbolAddress((void**)&pwproj,g_wproj);
    cudaGetSymbolAddress((void**)&pcls,  g_clsbf);
    cudaGetSymbolAddress((void**)&pw1,   g_w1bf);
    cudaGetSymbolAddress((void**)&pl1,   g_l1bf);
    cudaGetSymbolAddress((void**)&pw2,   g_w2bf);
    cudaGetSymbolAddress((void**)&pl2,   g_l2bf);
    cudaGetSymbolAddress((void**)&pwb,   g_wbbf);

    // --- conversions for qkv GEMM ---
    conv_split<<<66560, 256>>>(x, CH, pxbf, CH, 66560);
    conv_split<<<2304, 256>>>(qkv_w, CH, pwqkv, CH, 2304);
    // 1. qkv (scatter into q/k/v)
    gemm_mma<0><<<dim3(18, 520), 256>>>(pxbf, 1536, pwqkv, 1536, nullptr, 0, 66560, 2304, 768);
    // 2. per-head LN on q/k
    qk_ln_kernel<<<199680, 256>>>(qn_g, qn_b, kn_g, kn_b);

    // --- bias-generator path ---
    conv_split<<<1024, 256>>>(x, NT * CH, pcls, CH, 1024);          // cls rows
    conv_split<<<512, 256>>>(sg_w1, CH, pw1, CH, 512);
    gemm_mma<1><<<dim3(4, 8), 256>>>(pcls, 1536, pw1, 1536, p_lat1, 512, 1024, 512, 768);
    ln_silu512<<<1024, 256>>>(p_lat1, sg_ln1g, sg_ln1b);
    conv_split<<<1024, 256>>>(p_lat1, 512, pl1, 512, 1024);
    conv_split<<<3072, 256>>>(sg_w2, 512, pw2, 512, 3072);
    gemm_mma<1><<<dim3(24, 8), 256>>>(pl1, 1024, pw2, 1024, p_lat2, 3072, 1024, 3072, 512);
    ln3072<<<1024, 256>>>(p_lat2, sg_ln2g, sg_ln2b);
    conv_split<<<12288, 256>>>(p_lat2, 256, pl2, 256, 12288);        // view (12288,256)
    conv_split<<<4352, 256>>>(sg_bw, 256, pwb, 256, 4225);           // pad rows >= 4225 with zeros
    gemm_mma<1><<<dim3(34, 96), 256>>>(pl2, 512, pwb, 512, p_bias, 4225, 12288, 4225, 256);

    // --- attention ---
    attn_kernel<<<NBATCH * NH, 256>>>();

    // --- output projection ---
    conv_split<<<66560, 256>>>(p_att, CH, pattbf, CH, 66560);
    conv_split<<<768, 256>>>(proj_w, CH, pwproj, CH, 768);
    gemm_mma<1><<<dim3(6, 520), 256>>>(pattbf, 1536, pwproj, 1536, out, 768, 66560, 768, 768);
}

// round 6
// speedup vs baseline: 2.7266x; 1.3839x over previous
#include <cuda_runtime.h>
#include <cuda_bf16.h>
#include <cstdint>

// ---------------- problem constants ----------------
#define NBATCH 1024
#define NT     65
#define CH     768
#define NH     12
#define DH     64

// ---------------- fp32 scratch ----------------
__device__ __align__(16) float g_q[51118080];     // [B,H,NT,DH]
__device__ __align__(16) float g_k[51118080];
__device__ __align__(16) float g_v[51118080];
__device__ __align__(16) float g_bias[51916800];  // [B*H,65*65]
__device__ __align__(16) float g_att[51118080];   // [B,NT,CH]
__device__ __align__(16) float g_lat1[524288];    // [1024,512]
__device__ __align__(16) float g_lat2[3145728];   // [1024,3072]

// ---------------- bf16 hi|lo split scratch (row = [hi(K) | lo(K)]) ----------------
__device__ __align__(16) __nv_bfloat16 g_xbf[102236160];   // 66560 x 1536
__device__ __align__(16) __nv_bfloat16 g_attbf[102236160]; // 66560 x 1536
__device__ __align__(16) __nv_bfloat16 g_wqkv[3538944];    // 2304 x 1536
__device__ __align__(16) __nv_bfloat16 g_wproj[1179648];   // 768 x 1536
__device__ __align__(16) __nv_bfloat16 g_clsbf[1572864];   // 1024 x 1536
__device__ __align__(16) __nv_bfloat16 g_w1bf[786432];     // 512 x 1536
__device__ __align__(16) __nv_bfloat16 g_l1bf[1048576];    // 1024 x 1024
__device__ __align__(16) __nv_bfloat16 g_w2bf[3145728];    // 3072 x 1024
__device__ __align__(16) __nv_bfloat16 g_l2bf[6291456];    // 12288 x 512
__device__ __align__(16) __nv_bfloat16 g_wbbf[2228224];    // 4352 x 512 (rows >= 4225 zero)

// ---------------- helpers ----------------
__device__ __forceinline__ uint32_t s2u(const void* p) {
    uint32_t a;
    asm("{ .reg .u64 t; cvta.to.shared.u64 t, %1; cvt.u32.u64 %0, t; }" : "=r"(a) : "l"(p));
    return a;
}
__device__ __forceinline__ void ldsm4(uint32_t* r, uint32_t addr) {
    asm volatile("ldmatrix.sync.aligned.m8n8.x4.shared.b16 {%0,%1,%2,%3}, [%4];"
        : "=r"(r[0]), "=r"(r[1]), "=r"(r[2]), "=r"(r[3]) : "r"(addr));
}
__device__ __forceinline__ void mma16816(float* d, const uint32_t* a, uint32_t b0, uint32_t b1) {
    asm volatile(
        "mma.sync.aligned.m16n8k16.row.col.f32.bf16.bf16.f32 "
        "{%0,%1,%2,%3}, {%4,%5,%6,%7}, {%8,%9}, {%0,%1,%2,%3};"
        : "+f"(d[0]), "+f"(d[1]), "+f"(d[2]), "+f"(d[3])
        : "r"(a[0]), "r"(a[1]), "r"(a[2]), "r"(a[3]), "r"(b0), "r"(b1));
}

// ---------------- fp32 -> bf16 hi|lo split (vectorized, one block per row) ----------------
__global__ void conv_split(const float* __restrict__ src, int lds,
                           __nv_bfloat16* __restrict__ dst, int K, int rowsValid)
{
    const int r = blockIdx.x;
    const float4* s = (const float4*)(src + (size_t)r * lds);
    __nv_bfloat162* dh = (__nv_bfloat162*)(dst + (size_t)r * 2 * K);
    __nv_bfloat162* dl = (__nv_bfloat162*)(dst + (size_t)r * 2 * K + K);
    const bool valid = r < rowsValid;
    for (int c = threadIdx.x; c < K / 4; c += blockDim.x) {
        float4 v = valid ? s[c] : make_float4(0.f, 0.f, 0.f, 0.f);
        __nv_bfloat16 hx = __float2bfloat16(v.x), hy = __float2bfloat16(v.y);
        __nv_bfloat16 hz = __float2bfloat16(v.z), hw = __float2bfloat16(v.w);
        dh[c * 2]     = __nv_bfloat162(hx, hy);
        dh[c * 2 + 1] = __nv_bfloat162(hz, hw);
        dl[c * 2]     = __nv_bfloat162(__float2bfloat16(v.x - __bfloat162float(hx)),
                                       __float2bfloat16(v.y - __bfloat162float(hy)));
        dl[c * 2 + 1] = __nv_bfloat162(__float2bfloat16(v.z - __bfloat162float(hz)),
                                       __float2bfloat16(v.w - __bfloat162float(hw)));
    }
}

// ---------------- mma.sync bf16-split GEMM: C = A @ B^T ----------------
// 4-stage cp.async pipeline, one __syncthreads per K-chunk. 128x128 CTA tile,
// 8 warps (2x4), each 64x32 via m16n8k16. 3 passes (Ah,Bh)(Ah,Bl)(Al,Bh).
#define KC    32
#define LDS_  40                       // padded bf16 row stride (80B)
#define STGB  20480                    // bytes per stage (A 10240 + B 10240)
#define GEMM_SMEM (4 * STGB)           // 81920

template<int MODE>
__global__ __launch_bounds__(256, 2)
void gemm_mma(const __nv_bfloat16* __restrict__ A, int lda,
              const __nv_bfloat16* __restrict__ B, int ldb,
              float* __restrict__ C, int ldc, int M, int N, int K)
{
    extern __shared__ char dynsm[];
    const uint32_t sbase = s2u(dynsm);

    const int tid = threadIdx.x, wid = tid >> 5, lane = tid & 31;
    const int wm = wid & 1, wn = wid >> 1;            // 2 x 4 warp grid
    const int bm = blockIdx.y * 128, bn = blockIdx.x * 128;
    const int nk = K / KC, total = 3 * nk;

    float acc[4][4][4];
#pragma unroll
    for (int i = 0; i < 4; i++)
#pragma unroll
        for (int j = 0; j < 4; j++)
#pragma unroll
            for (int e = 0; e < 4; e++) acc[i][j][e] = 0.f;

    // per-chunk loads: 1024 x 16B (A:512, B:512), 4 cp.async per thread
    auto loads = [&](int t, int st) {
        const uint32_t uA = sbase + (uint32_t)st * STGB;
        const uint32_t uB = uA + 10240u;
        const int p = t / nk, c = t - p * nk;
        const int aOff = (p == 2 ? K : 0) + c * KC;
        const int bOff = (p == 1 ? K : 0) + c * KC;
#pragma unroll
        for (int i = 0; i < 4; i++) {
            const int idx = tid + i * 256;
            const int id2 = idx & 511;
            const int r = id2 >> 2, cc = id2 & 3;
            if (idx < 512) {
                const void* g = (const void*)(A + (size_t)(bm + r) * lda + aOff + cc * 8);
                asm volatile("cp.async.cg.shared.global [%0], [%1], 16;"
                             :: "r"(uA + (uint32_t)(r * LDS_ + cc * 8) * 2), "l"(g));
            } else {
                const void* g = (const void*)(B + (size_t)(bn + r) * ldb + bOff + cc * 8);
                asm volatile("cp.async.cg.shared.global [%0], [%1], 16;"
                             :: "r"(uB + (uint32_t)(r * LDS_ + cc * 8) * 2), "l"(g));
            }
        }
        asm volatile("cp.async.commit_group;");
    };

    loads(0, 0); loads(1, 1); loads(2, 2);

    for (int t = 0; t < total; ++t) {
        const int st = t & 3;
        const int rem = total - 1 - t;
        if (rem >= 2)      asm volatile("cp.async.wait_group 2;");
        else if (rem == 1) asm volatile("cp.async.wait_group 1;");
        else               asm volatile("cp.async.wait_group 0;");
        __syncthreads();
        if (t + 3 < total) loads(t + 3, (t + 3) & 3);

        const uint32_t uA = sbase + (uint32_t)st * STGB;
        const uint32_t uB = uA + 10240u;
        const uint32_t wAb = uA + (uint32_t)(wm * 64 * LDS_) * 2;
        const uint32_t wBb = uB + (uint32_t)(wn * 32 * LDS_) * 2;
#pragma unroll
        for (int ks = 0; ks < 2; ++ks) {
            uint32_t a[4][4], b[2][4];
#pragma unroll
            for (int mt = 0; mt < 4; ++mt) {
                const uint32_t addr = wAb +
                    (uint32_t)((mt * 16 + (lane & 15)) * LDS_ + ks * 16 + (lane >> 4) * 8) * 2;
                ldsm4(a[mt], addr);
            }
#pragma unroll
            for (int ng = 0; ng < 2; ++ng) {
                const uint32_t addr = wBb +
                    (uint32_t)((ng * 16 + ((lane >> 4) & 1) * 8 + (lane & 7)) * LDS_ +
                               ks * 16 + ((lane >> 3) & 1) * 8) * 2;
                ldsm4(b[ng], addr);
            }
#pragma unroll
            for (int mt = 0; mt < 4; ++mt)
#pragma unroll
                for (int nt = 0; nt < 4; ++nt)
                    mma16816(acc[mt][nt], a[mt], b[nt >> 1][(nt & 1) * 2], b[nt >> 1][(nt & 1) * 2 + 1]);
        }
    }

    // epilogue
    const int gr = lane >> 2, gc = (lane & 3) * 2;
#pragma unroll
    for (int mt = 0; mt < 4; ++mt) {
#pragma unroll
        for (int nt = 0; nt < 4; ++nt) {
#pragma unroll
            for (int e = 0; e < 4; ++e) {
                const int m = bm + wm * 64 + mt * 16 + gr + (e >> 1) * 8;
                const int n = bn + wn * 32 + nt * 8 + gc + (e & 1);
                const float v = acc[mt][nt][e];
                if (MODE == 0) {
                    const int s   = n / CH;
                    const int rem = n - s * CH;
                    const int h   = rem >> 6;
                    const int d   = rem & 63;
                    const int bb  = m / NT;
                    const int tt  = m - bb * NT;
                    const size_t idx = (((size_t)(bb * NH + h)) * NT + tt) * DH + d;
                    float* dst = (s == 0) ? g_q : (s == 1) ? g_k : g_v;
                    dst[idx] = v;
                } else {
                    if (n < N) C[(size_t)m * ldc + n] = v;
                }
            }
        }
    }
}

// ---------------- per-head-dim LayerNorm: float4, 16 lanes per row ----------------
__global__ __launch_bounds__(256)
void qk_ln_kernel(const float* __restrict__ qn_g, const float* __restrict__ qn_b,
                  const float* __restrict__ kn_g, const float* __restrict__ kn_b)
{
    const long long R = (long long)NBATCH * NH * NT;          // 798720 rows per tensor
    const long long warp = (((long long)blockIdx.x * blockDim.x) + threadIdx.x) >> 5;
    if (warp >= R) return;                                     // 2 rows per warp, 2R rows
    const int half = (threadIdx.x >> 4) & 1;
    const int l16  = threadIdx.x & 15;
    const long long row = warp * 2 + half;
    const bool isK = (row >= R);
    const long long rr = isK ? row - R : row;
    float* base = (isK ? g_k : g_q) + rr * DH;

    float4 v = ((const float4*)base)[l16];
    float s  = v.x + v.y + v.z + v.w;
    float ss = v.x * v.x + v.y * v.y + v.z * v.z + v.w * v.w;
#pragma unroll
    for (int o = 8; o; o >>= 1) {
        s  += __shfl_xor_sync(0xffffffffu, s,  o);
        ss += __shfl_xor_sync(0xffffffffu, ss, o);
    }
    const float mean = s * (1.f / 64.f);
    const float var  = ss * (1.f / 64.f) - mean * mean;
    const float inv  = rsqrtf(var + 1e-5f);
    const float* gp = isK ? kn_g : qn_g;
    const float* bp = isK ? kn_b : qn_b;
    float4 gg = ((const float4*)gp)[l16];
    float4 bb = ((const float4*)bp)[l16];
    const float scale = isK ? 1.f : 0.125f;
    float4 o;
    o.x = ((v.x - mean) * inv * gg.x + bb.x) * scale;
    o.y = ((v.y - mean) * inv * gg.y + bb.y) * scale;
    o.z = ((v.z - mean) * inv * gg.z + bb.z) * scale;
    o.w = ((v.w - mean) * inv * gg.w + bb.w) * scale;
    ((float4*)base)[l16] = o;
}

// ---------------- block reduce helper ----------------
__device__ __forceinline__ float2 block_reduce2(float s, float ss, float* shm)
{
#pragma unroll
    for (int o = 16; o; o >>= 1) {
        s  += __shfl_xor_sync(0xffffffffu, s,  o);
        ss += __shfl_xor_sync(0xffffffffu, ss, o);
    }
    const int w = threadIdx.x >> 5, lane = threadIdx.x & 31;
    if (lane == 0) { shm[w] = s; shm[8 + w] = ss; }
    __syncthreads();
    if (threadIdx.x < 32) {
        s  = (lane < 8) ? shm[lane]     : 0.f;
        ss = (lane < 8) ? shm[8 + lane] : 0.f;
#pragma unroll
        for (int o = 4; o; o >>= 1) {
            s  += __shfl_xor_sync(0xffffffffu, s,  o);
            ss += __shfl_xor_sync(0xffffffffu, ss, o);
        }
        if (lane == 0) { shm[0] = s; shm[1] = ss; }
    }
    __syncthreads();
    return make_float2(shm[0], shm[1]);
}

__global__ __launch_bounds__(256)
void ln_silu512(float* __restrict__ data, const float* __restrict__ g, const float* __restrict__ b)
{
    __shared__ float shm[16];
    const int row = blockIdx.x, tid = threadIdx.x;
    float* p = data + (size_t)row * 512;
    float x0 = p[tid], x1 = p[tid + 256];
    float2 r = block_reduce2(x0 + x1, x0 * x0 + x1 * x1, shm);
    const float mean = r.x * (1.f / 512.f);
    const float var  = r.y * (1.f / 512.f) - mean * mean;
    const float inv  = rsqrtf(var + 1e-5f);
    float y0 = (x0 - mean) * inv * g[tid]       + b[tid];
    float y1 = (x1 - mean) * inv * g[tid + 256] + b[tid + 256];
    p[tid]       = y0 / (1.f + __expf(-y0));
    p[tid + 256] = y1 / (1.f + __expf(-y1));
}

__global__ __launch_bounds__(256)
void ln3072(float* __restrict__ data, const float* __restrict__ g, const float* __restrict__ b)
{
    __shared__ float shm[16];
    const int row = blockIdx.x, tid = threadIdx.x;
    float* p = data + (size_t)row * 3072;
    float x[12];
    float s = 0.f, ss = 0.f;
#pragma unroll
    for (int i = 0; i < 12; i++) {
        x[i] = p[tid + i * 256];
        s += x[i]; ss += x[i] * x[i];
    }
    float2 r = block_reduce2(s, ss, shm);
    const float mean = r.x * (1.f / 3072.f);
    const float var  = r.y * (1.f / 3072.f) - mean * mean;
    const float inv  = rsqrtf(var + 1e-5f);
#pragma unroll
    for (int i = 0; i < 12; i++) {
        const int c = tid + i * 256;
        p[c] = (x[i] - mean) * inv * g[c] + b[c];
    }
}

// ---------------- fused attention: per (b,h) block, 4-row register tiling ----------------
// dynamic smem: sV[4160] | sQ[4160] | sK[65*65=4225] | sS[8*4*66=2112]
#define ATTN_SMEM ((4160 + 4160 + 4225 + 2112) * 4)

__global__ __launch_bounds__(256)
void attn_kernel()
{
    extern __shared__ float asmem[];
    float* sV = asmem;
    float* sQ = asmem + 4160;
    float* sK = asmem + 8320;
    float* sS = asmem + 12545;

    const int bh  = blockIdx.x;
    const int tid = threadIdx.x;
    const size_t base = (size_t)bh * (NT * DH);

    const float4* k4 = (const float4*)(g_k + base);
    const float4* v4 = (const float4*)(g_v + base);
    const float4* q4 = (const float4*)(g_q + base);
    for (int i = tid; i < NT * (DH / 4); i += 256) {
        ((float4*)sV)[i] = v4[i];
        ((float4*)sQ)[i] = q4[i];
        float4 kv = k4[i];
        const int r = i >> 4, c = (i & 15) << 2;
        float* d = sK + r * 65 + c;
        d[0] = kv.x; d[1] = kv.y; d[2] = kv.z; d[3] = kv.w;
    }
    __syncthreads();

    const int w = tid >> 5, lane = tid & 31;
    const float* bp = g_bias + (size_t)bh * (NT * NT);
    const int b = bh / NH, h = bh - b * NH;
    float* sSw = sS + w * 4 * 66;

    for (int i0 = w * 4; i0 < NT; i0 += 32) {
        int irr[4];
#pragma unroll
        for (int r = 0; r < 4; ++r) irr[r] = (i0 + r < NT) ? (i0 + r) : (NT - 1);

        // j = 64 scores via lane-parallel dot + reduce
        float s64[4];
#pragma unroll
        for (int r = 0; r < 4; ++r) {
            float t = sQ[irr[r] * DH + lane]      * sK[64 * 65 + lane]
                    + sQ[irr[r] * DH + lane + 32] * sK[64 * 65 + lane + 32];
#pragma unroll
            for (int o = 16; o; o >>= 1) t += __shfl_xor_sync(0xffffffffu, t, o);
            s64[r] = t + bp[irr[r] * NT + 64];
        }

        // j = lane, lane+32 scores with 4-row k reuse
        float s0[4], s1[4];
#pragma unroll
        for (int r = 0; r < 4; ++r) {
            s0[r] = bp[irr[r] * NT + lane];
            s1[r] = bp[irr[r] * NT + lane + 32];
        }
#pragma unroll 4
        for (int d = 0; d < DH; ++d) {
            const float k0 = sK[lane * 65 + d];
            const float k1 = sK[(lane + 32) * 65 + d];
#pragma unroll
            for (int r = 0; r < 4; ++r) {
                const float qd = sQ[irr[r] * DH + d];
                s0[r] += qd * k0;
                s1[r] += qd * k1;
            }
        }

        // softmax per row
        float inv_[4];
#pragma unroll
        for (int r = 0; r < 4; ++r) {
            float mx = fmaxf(s0[r], s1[r]);
#pragma unroll
            for (int o = 16; o; o >>= 1) mx = fmaxf(mx, __shfl_xor_sync(0xffffffffu, mx, o));
            mx = fmaxf(mx, s64[r]);
            const float e0 = __expf(s0[r] - mx);
            const float e1 = __expf(s1[r] - mx);
            const float e2 = __expf(s64[r] - mx);
            float sum = e0 + e1;
#pragma unroll
            for (int o = 16; o; o >>= 1) sum += __shfl_xor_sync(0xffffffffu, sum, o);
            sum += e2;
            sSw[r * 66 + lane]      = e0;
            sSw[r * 66 + lane + 32] = e1;
            if (lane == 0) sSw[r * 66 + 64] = e2;
            inv_[r] = 1.f / sum;
        }
        __syncwarp();

        // out = P @ V with 4-row reuse
        float a0[4] = {0.f, 0.f, 0.f, 0.f}, a1[4] = {0.f, 0.f, 0.f, 0.f};
        for (int m = 0; m < NT; ++m) {
            const float v0 = sV[m * DH + lane];
            const float v1 = sV[m * DH + lane + 32];
#pragma unroll
            for (int r = 0; r < 4; ++r) {
                const float p = sSw[r * 66 + m];
                a0[r] += p * v0;
                a1[r] += p * v1;
            }
        }
#pragma unroll
        for (int r = 0; r < 4; ++r) {
            const int i = i0 + r;
            if (i < NT) {
                float* op = g_att + ((size_t)(b * NT + i)) * CH + h * DH;
                op[lane]      = a0[r] * inv_[r];
                op[lane + 32] = a1[r] * inv_[r];
            }
        }
        __syncwarp();
    }
}

// ---------------- host launcher ----------------
extern "C" void kernel_launch(void* const* d_in, const int* in_sizes, int n_in,
                              void* d_out, int out_size)
{
    const float* x       = (const float*)d_in[0];
    const float* qkv_w   = (const float*)d_in[1];
    const float* proj_w  = (const float*)d_in[2];
    const float* qn_g    = (const float*)d_in[3];
    const float* qn_b    = (const float*)d_in[4];
    const float* kn_g    = (const float*)d_in[5];
    const float* kn_b    = (const float*)d_in[6];
    const float* sg_w1   = (const float*)d_in[7];
    const float* sg_ln1g = (const float*)d_in[8];
    const float* sg_ln1b = (const float*)d_in[9];
    const float* sg_w2   = (const float*)d_in[10];
    const float* sg_ln2g = (const float*)d_in[11];
    const float* sg_ln2b = (const float*)d_in[12];
    const float* sg_bw   = (const float*)d_in[13];
    float* out = (float*)d_out;

    float *p_lat1, *p_lat2, *p_bias, *p_att;
    cudaGetSymbolAddress((void**)&p_lat1, g_lat1);
    cudaGetSymbolAddress((void**)&p_lat2, g_lat2);
    cudaGetSymbolAddress((void**)&p_bias, g_bias);
    cudaGetSymbolAddress((void**)&p_att,  g_att);
    __nv_bfloat16 *pxbf, *pattbf, *pwqkv, *pwproj, *pcls, *pw1, *pl1, *pw2, *pl2, *pwb;
    cudaGetSymbolAddress((void**)&pxbf,  g_xbf);
    cudaGetSymbolAddress((void**)&pattbf,g_attbf);
    cudaGetSymbolAddress((void**)&pwqkv, g_wqkv);
    cudaGetSymbolAddress((void**)&pwproj,g_wproj);
    cudaGetSymbolAddress((void**)&pcls,  g_clsbf);
    cudaGetSymbolAddress((void**)&pw1,   g_w1bf);
    cudaGetSymbolAddress((void**)&pl1,   g_l1bf);
    cudaGetSymbolAddress((void**)&pw2,   g_w2bf);
    cudaGetSymbolAddress((void**)&pl2,   g_l2bf);
    cudaGetSymbolAddress((void**)&pwb,   g_wbbf);

    cudaFuncSetAttribute(gemm_mma<0>, cudaFuncAttributeMaxDynamicSharedMemorySize, GEMM_SMEM);
    cudaFuncSetAttribute(gemm_mma<1>, cudaFuncAttributeMaxDynamicSharedMemorySize, GEMM_SMEM);
    cudaFuncSetAttribute(attn_kernel, cudaFuncAttributeMaxDynamicSharedMemorySize, ATTN_SMEM);

    // --- conversions for qkv GEMM ---
    conv_split<<<66560, 192>>>(x, CH, pxbf, CH, 66560);
    conv_split<<<2304, 192>>>(qkv_w, CH, pwqkv, CH, 2304);
    // 1. qkv (scatter into q/k/v)
    gemm_mma<0><<<dim3(18, 520), 256, GEMM_SMEM>>>(pxbf, 1536, pwqkv, 1536, nullptr, 0, 66560, 2304, 768);
    // 2. per-head LN on q/k : 1597440 rows, 2 per warp
    qk_ln_kernel<<<99840, 256>>>(qn_g, qn_b, kn_g, kn_b);

    // --- bias-generator path ---
    conv_split<<<1024, 192>>>(x, NT * CH, pcls, CH, 1024);
    conv_split<<<512, 192>>>(sg_w1, CH, pw1, CH, 512);
    gemm_mma<1><<<dim3(4, 8), 256, GEMM_SMEM>>>(pcls, 1536, pw1, 1536, p_lat1, 512, 1024, 512, 768);
    ln_silu512<<<1024, 256>>>(p_lat1, sg_ln1g, sg_ln1b);
    conv_split<<<1024, 128>>>(p_lat1, 512, pl1, 512, 1024);
    conv_split<<<3072, 128>>>(sg_w2, 512, pw2, 512, 3072);
    gemm_mma<1><<<dim3(24, 8), 256, GEMM_SMEM>>>(pl1, 1024, pw2, 1024, p_lat2, 3072, 1024, 3072, 512);
    ln3072<<<1024, 256>>>(p_lat2, sg_ln2g, sg_ln2b);
    conv_split<<<12288, 64>>>(p_lat2, 256, pl2, 256, 12288);
    conv_split<<<4352, 64>>>(sg_bw, 256, pwb, 256, 4225);
    gemm_mma<1><<<dim3(34, 96), 256, GEMM_SMEM>>>(pl2, 512, pwb, 512, p_bias, 4225, 12288, 4225, 256);

    // --- attention ---
    attn_kernel<<<NBATCH * NH, 256, ATTN_SMEM>>>();

    // --- output projection ---
    conv_split<<<66560, 192>>>(p_att, CH, pattbf, CH, 66560);
    conv_split<<<768, 192>>>(proj_w, CH, pwproj, CH, 768);
    gemm_mma<1><<<dim3(6, 520), 256, GEMM_SMEM>>>(pattbf, 1536, pwproj, 1536, out, 768, 66560, 768, 768);
}

// round 7
// speedup vs baseline: 3.7762x; 1.3849x over previous
#include <cuda_runtime.h>
#include <cuda_fp16.h>
#include <cstdint>

// ---------------- problem constants ----------------
#define NBATCH 1024
#define NT     65
#define CH     768
#define NH     12
#define DH     64

// ---------------- fp32 scratch ----------------
__device__ __align__(16) float g_q[51118080];     // [B,H,NT,DH]
__device__ __align__(16) float g_k[51118080];
__device__ __align__(16) float g_v[51118080];
__device__ __align__(16) float g_bias[51916800];  // [B*H,65*65]
__device__ __align__(16) float g_lat1[524288];    // [1024,512]
__device__ __align__(16) float g_lat2[3145728];   // [1024,3072]

// ---------------- fp16 scratch ----------------
// A-side operands: [hi(K) | lo(K)] per row. B-side weights: plain fp16.
__device__ __align__(16) __half g_xbf[102236160];   // 66560 x 1536
__device__ __align__(16) __half g_attbf[102236160]; // 66560 x 1536 (written by attn)
__device__ __align__(16) __half g_clsbf[1572864];   // 1024 x 1536
__device__ __align__(16) __half g_l1bf[1048576];    // 1024 x 1024
__device__ __align__(16) __half g_l2bf[6291456];    // 12288 x 512
__device__ __align__(16) __half g_wqkv[1769472];    // 2304 x 768
__device__ __align__(16) __half g_wproj[589824];    // 768 x 768
__device__ __align__(16) __half g_w1bf[393216];     // 512 x 768
__device__ __align__(16) __half g_w2bf[1572864];    // 3072 x 512
__device__ __align__(16) __half g_wbbf[1114112];    // 4352 x 256 (rows >= 4225 zero)

// ---------------- helpers ----------------
__device__ __forceinline__ uint32_t s2u(const void* p) {
    uint32_t a;
    asm("{ .reg .u64 t; cvta.to.shared.u64 t, %1; cvt.u32.u64 %0, t; }" : "=r"(a) : "l"(p));
    return a;
}
__device__ __forceinline__ void ldsm4(uint32_t* r, uint32_t addr) {
    asm volatile("ldmatrix.sync.aligned.m8n8.x4.shared.b16 {%0,%1,%2,%3}, [%4];"
        : "=r"(r[0]), "=r"(r[1]), "=r"(r[2]), "=r"(r[3]) : "r"(addr));
}
__device__ __forceinline__ void mma16816(float* d, const uint32_t* a, uint32_t b0, uint32_t b1) {
    asm volatile(
        "mma.sync.aligned.m16n8k16.row.col.f32.f16.f16.f32 "
        "{%0,%1,%2,%3}, {%4,%5,%6,%7}, {%8,%9}, {%0,%1,%2,%3};"
        : "+f"(d[0]), "+f"(d[1]), "+f"(d[2]), "+f"(d[3])
        : "r"(a[0]), "r"(a[1]), "r"(a[2]), "r"(a[3]), "r"(b0), "r"(b1));
}

// ---------------- fp32 -> fp16 hi|lo split (A-side) ----------------
__global__ void conv_split(const float* __restrict__ src, int lds,
                           __half* __restrict__ dst, int K, int rowsValid)
{
    const int r = blockIdx.x;
    const float4* s = (const float4*)(src + (size_t)r * lds);
    __half2* dh = (__half2*)(dst + (size_t)r * 2 * K);
    __half2* dl = (__half2*)(dst + (size_t)r * 2 * K + K);
    const bool valid = r < rowsValid;
    for (int c = threadIdx.x; c < K / 4; c += blockDim.x) {
        float4 v = valid ? s[c] : make_float4(0.f, 0.f, 0.f, 0.f);
        __half hx = __float2half(v.x), hy = __float2half(v.y);
        __half hz = __float2half(v.z), hw = __float2half(v.w);
        dh[c * 2]     = __half2(hx, hy);
        dh[c * 2 + 1] = __half2(hz, hw);
        dl[c * 2]     = __half2(__float2half(v.x - __half2float(hx)),
                                __float2half(v.y - __half2float(hy)));
        dl[c * 2 + 1] = __half2(__float2half(v.z - __half2float(hz)),
                                __float2half(v.w - __half2float(hw)));
    }
}

// ---------------- fp32 -> fp16 plain (B-side weights) ----------------
__global__ void conv16(const float* __restrict__ src, __half* __restrict__ dst,
                       int K, int rowsValid)
{
    const int r = blockIdx.x;
    const float4* s = (const float4*)(src + (size_t)r * K);
    __half2* d = (__half2*)(dst + (size_t)r * K);
    const bool valid = r < rowsValid;
    for (int c = threadIdx.x; c < K / 4; c += blockDim.x) {
        float4 v = valid ? s[c] : make_float4(0.f, 0.f, 0.f, 0.f);
        d[c * 2]     = __half2(__float2half(v.x), __float2half(v.y));
        d[c * 2 + 1] = __half2(__float2half(v.z), __float2half(v.w));
    }
}

// ---------------- fp16 2-pass split GEMM: C = (Ah+Al) @ Bh^T ----------------
// A: M x 2K [hi|lo] fp16, B: N x K fp16. 128x128 CTA tile, 4 warps (2x2),
// warp tile 64x64. KC=32, 3-stage cp.async pipeline; hi and lo MMAs share
// the B smem tile and accumulate into the same fragments.
#define KC    32
#define LDS_  40                       // padded fp16 row stride (80B)
#define APART 10240u                   // bytes per tile part per stage
#define STGB  30720u                   // Ah + Al + B
#define NSTG  3
#define GEMM_SMEM (NSTG * STGB)        // 92160

template<int MODE>
__global__ __launch_bounds__(128, 2)
void gemm_mma(const __half* __restrict__ A, int lda,
              const __half* __restrict__ B, int ldb,
              float* __restrict__ C, int ldc, int M, int N, int K)
{
    extern __shared__ char dynsm[];
    const uint32_t sbase = s2u(dynsm);

    const int tid = threadIdx.x, wid = tid >> 5, lane = tid & 31;
    const int wm = wid & 1, wn = wid >> 1;            // 2 x 2 warp grid
    const int bm = blockIdx.y * 128, bn = blockIdx.x * 128;
    const int nk = K / KC;

    float acc[4][8][4];
#pragma unroll
    for (int i = 0; i < 4; i++)
#pragma unroll
        for (int j = 0; j < 8; j++)
#pragma unroll
            for (int e = 0; e < 4; e++) acc[i][j][e] = 0.f;

    // per-chunk loads: 1536 x 16B (Ah 512 | Al 512 | B 512), 12 per thread
    auto loads = [&](int t) {
        const uint32_t ub = sbase + (uint32_t)(t % NSTG) * STGB;
        const int kOff = t * KC;
#pragma unroll
        for (int i = 0; i < 12; i++) {
            const int idx = tid + i * 128;
            const int part = idx >> 9;             // 0 Ah, 1 Al, 2 B
            const int id2 = idx & 511;
            const int r = id2 >> 2, cc = id2 & 3;
            const uint32_t dst = ub + (uint32_t)part * APART +
                                 (uint32_t)(r * LDS_ + cc * 8) * 2;
            const void* g = (part == 2)
                ? (const void*)(B + (size_t)(bn + r) * ldb + kOff + cc * 8)
                : (const void*)(A + (size_t)(bm + r) * lda + part * K + kOff + cc * 8);
            asm volatile("cp.async.cg.shared.global [%0], [%1], 16;" :: "r"(dst), "l"(g));
        }
        asm volatile("cp.async.commit_group;");
    };

    loads(0);
    if (nk > 1) loads(1);

    for (int t = 0; t < nk; ++t) {
        if (t + 1 < nk) asm volatile("cp.async.wait_group 1;");
        else            asm volatile("cp.async.wait_group 0;");
        __syncthreads();
        if (t + 2 < nk) loads(t + 2);

        const uint32_t ub  = sbase + (uint32_t)(t % NSTG) * STGB;
        const uint32_t uAh = ub + (uint32_t)(wm * 64 * LDS_) * 2;
        const uint32_t uAl = uAh + APART;
        const uint32_t uB  = ub + 2 * APART + (uint32_t)(wn * 64 * LDS_) * 2;
#pragma unroll
        for (int ks = 0; ks < 2; ++ks) {
            uint32_t ah[4][4], al[4][4], b[4][4];
#pragma unroll
            for (int mt = 0; mt < 4; ++mt) {
                const uint32_t ro = (uint32_t)((mt * 16 + (lane & 15)) * LDS_ +
                                               ks * 16 + (lane >> 4) * 8) * 2;
                ldsm4(ah[mt], uAh + ro);
                ldsm4(al[mt], uAl + ro);
            }
#pragma unroll
            for (int ng = 0; ng < 4; ++ng) {
                const uint32_t addr = uB +
                    (uint32_t)((ng * 16 + ((lane >> 4) & 1) * 8 + (lane & 7)) * LDS_ +
                               ks * 16 + ((lane >> 3) & 1) * 8) * 2;
                ldsm4(b[ng], addr);
            }
#pragma unroll
            for (int mt = 0; mt < 4; ++mt)
#pragma unroll
                for (int nt = 0; nt < 8; ++nt) {
                    const uint32_t b0 = b[nt >> 1][(nt & 1) * 2];
                    const uint32_t b1 = b[nt >> 1][(nt & 1) * 2 + 1];
                    mma16816(acc[mt][nt], ah[mt], b0, b1);
                    mma16816(acc[mt][nt], al[mt], b0, b1);
                }
        }
    }

    // epilogue
    const int gr = lane >> 2, gc = (lane & 3) * 2;
#pragma unroll
    for (int mt = 0; mt < 4; ++mt) {
#pragma unroll
        for (int nt = 0; nt < 8; ++nt) {
#pragma unroll
            for (int e = 0; e < 4; ++e) {
                const int m = bm + wm * 64 + mt * 16 + gr + (e >> 1) * 8;
                const int n = bn + wn * 64 + nt * 8 + gc + (e & 1);
                const float v = acc[mt][nt][e];
                if (MODE == 0) {
                    const int s   = n / CH;
                    const int rem = n - s * CH;
                    const int h   = rem >> 6;
                    const int d   = rem & 63;
                    const int bb  = m / NT;
                    const int tt  = m - bb * NT;
                    const size_t idx = (((size_t)(bb * NH + h)) * NT + tt) * DH + d;
                    float* dst = (s == 0) ? g_q : (s == 1) ? g_k : g_v;
                    dst[idx] = v;
                } else {
                    if (n < N) C[(size_t)m * ldc + n] = v;
                }
            }
        }
    }
}

// ---------------- per-head-dim LayerNorm: float4, 16 lanes per row ----------------
__global__ __launch_bounds__(256)
void qk_ln_kernel(const float* __restrict__ qn_g, const float* __restrict__ qn_b,
                  const float* __restrict__ kn_g, const float* __restrict__ kn_b)
{
    const long long R = (long long)NBATCH * NH * NT;
    const long long warp = (((long long)blockIdx.x * blockDim.x) + threadIdx.x) >> 5;
    if (warp >= R) return;
    const int half = (threadIdx.x >> 4) & 1;
    const int l16  = threadIdx.x & 15;
    const long long row = warp * 2 + half;
    const bool isK = (row >= R);
    const long long rr = isK ? row - R : row;
    float* base = (isK ? g_k : g_q) + rr * DH;

    float4 v = ((const float4*)base)[l16];
    float s  = v.x + v.y + v.z + v.w;
    float ss = v.x * v.x + v.y * v.y + v.z * v.z + v.w * v.w;
#pragma unroll
    for (int o = 8; o; o >>= 1) {
        s  += __shfl_xor_sync(0xffffffffu, s,  o);
        ss += __shfl_xor_sync(0xffffffffu, ss, o);
    }
    const float mean = s * (1.f / 64.f);
    const float var  = ss * (1.f / 64.f) - mean * mean;
    const float inv  = rsqrtf(var + 1e-5f);
    const float* gp = isK ? kn_g : qn_g;
    const float* bp = isK ? kn_b : qn_b;
    float4 gg = ((const float4*)gp)[l16];
    float4 bb = ((const float4*)bp)[l16];
    const float scale = isK ? 1.f : 0.125f;
    float4 o;
    o.x = ((v.x - mean) * inv * gg.x + bb.x) * scale;
    o.y = ((v.y - mean) * inv * gg.y + bb.y) * scale;
    o.z = ((v.z - mean) * inv * gg.z + bb.z) * scale;
    o.w = ((v.w - mean) * inv * gg.w + bb.w) * scale;
    ((float4*)base)[l16] = o;
}

// ---------------- block reduce helper ----------------
__device__ __forceinline__ float2 block_reduce2(float s, float ss, float* shm)
{
#pragma unroll
    for (int o = 16; o; o >>= 1) {
        s  += __shfl_xor_sync(0xffffffffu, s,  o);
        ss += __shfl_xor_sync(0xffffffffu, ss, o);
    }
    const int w = threadIdx.x >> 5, lane = threadIdx.x & 31;
    if (lane == 0) { shm[w] = s; shm[8 + w] = ss; }
    __syncthreads();
    if (threadIdx.x < 32) {
        s  = (lane < 8) ? shm[lane]     : 0.f;
        ss = (lane < 8) ? shm[8 + lane] : 0.f;
#pragma unroll
        for (int o = 4; o; o >>= 1) {
            s  += __shfl_xor_sync(0xffffffffu, s,  o);
            ss += __shfl_xor_sync(0xffffffffu, ss, o);
        }
        if (lane == 0) { shm[0] = s; shm[1] = ss; }
    }
    __syncthreads();
    return make_float2(shm[0], shm[1]);
}

__global__ __launch_bounds__(256)
void ln_silu512(float* __restrict__ data, const float* __restrict__ g, const float* __restrict__ b)
{
    __shared__ float shm[16];
    const int row = blockIdx.x, tid = threadIdx.x;
    float* p = data + (size_t)row * 512;
    float x0 = p[tid], x1 = p[tid + 256];
    float2 r = block_reduce2(x0 + x1, x0 * x0 + x1 * x1, shm);
    const float mean = r.x * (1.f / 512.f);
    const float var  = r.y * (1.f / 512.f) - mean * mean;
    const float inv  = rsqrtf(var + 1e-5f);
    float y0 = (x0 - mean) * inv * g[tid]       + b[tid];
    float y1 = (x1 - mean) * inv * g[tid + 256] + b[tid + 256];
    p[tid]       = y0 / (1.f + __expf(-y0));
    p[tid + 256] = y1 / (1.f + __expf(-y1));
}

__global__ __launch_bounds__(256)
void ln3072(float* __restrict__ data, const float* __restrict__ g, const float* __restrict__ b)
{
    __shared__ float shm[16];
    const int row = blockIdx.x, tid = threadIdx.x;
    float* p = data + (size_t)row * 3072;
    float x[12];
    float s = 0.f, ss = 0.f;
#pragma unroll
    for (int i = 0; i < 12; i++) {
        x[i] = p[tid + i * 256];
        s += x[i]; ss += x[i] * x[i];
    }
    float2 r = block_reduce2(s, ss, shm);
    const float mean = r.x * (1.f / 3072.f);
    const float var  = r.y * (1.f / 3072.f) - mean * mean;
    const float inv  = rsqrtf(var + 1e-5f);
#pragma unroll
    for (int i = 0; i < 12; i++) {
        const int c = tid + i * 256;
        p[c] = (x[i] - mean) * inv * g[c] + b[c];
    }
}

// ---------------- fused attention: per (b,h) block, writes fp16 hi|lo ----------------
#define ATTN_SMEM ((4160 + 4160 + 4225 + 2112) * 4)

__global__ __launch_bounds__(256)
void attn_kernel()
{
    extern __shared__ float asmem[];
    float* sV = asmem;
    float* sQ = asmem + 4160;
    float* sK = asmem + 8320;
    float* sS = asmem + 12545;

    const int bh  = blockIdx.x;
    const int tid = threadIdx.x;
    const size_t base = (size_t)bh * (NT * DH);

    const float4* k4 = (const float4*)(g_k + base);
    const float4* v4 = (const float4*)(g_v + base);
    const float4* q4 = (const float4*)(g_q + base);
    for (int i = tid; i < NT * (DH / 4); i += 256) {
        ((float4*)sV)[i] = v4[i];
        ((float4*)sQ)[i] = q4[i];
        float4 kv = k4[i];
        const int r = i >> 4, c = (i & 15) << 2;
        float* d = sK + r * 65 + c;
        d[0] = kv.x; d[1] = kv.y; d[2] = kv.z; d[3] = kv.w;
    }
    __syncthreads();

    const int w = tid >> 5, lane = tid & 31;
    const float* bp = g_bias + (size_t)bh * (NT * NT);
    const int b = bh / NH, h = bh - b * NH;
    float* sSw = sS + w * 4 * 66;

    for (int i0 = w * 4; i0 < NT; i0 += 32) {
        int irr[4];
#pragma unroll
        for (int r = 0; r < 4; ++r) irr[r] = (i0 + r < NT) ? (i0 + r) : (NT - 1);

        float s64[4];
#pragma unroll
        for (int r = 0; r < 4; ++r) {
            float t = sQ[irr[r] * DH + lane]      * sK[64 * 65 + lane]
                    + sQ[irr[r] * DH + lane + 32] * sK[64 * 65 + lane + 32];
#pragma unroll
            for (int o = 16; o; o >>= 1) t += __shfl_xor_sync(0xffffffffu, t, o);
            s64[r] = t + bp[irr[r] * NT + 64];
        }

        float s0[4], s1[4];
#pragma unroll
        for (int r = 0; r < 4; ++r) {
            s0[r] = bp[irr[r] * NT + lane];
            s1[r] = bp[irr[r] * NT + lane + 32];
        }
#pragma unroll 4
        for (int d = 0; d < DH; ++d) {
            const float k0 = sK[lane * 65 + d];
            const float k1 = sK[(lane + 32) * 65 + d];
#pragma unroll
            for (int r = 0; r < 4; ++r) {
                const float qd = sQ[irr[r] * DH + d];
                s0[r] += qd * k0;
                s1[r] += qd * k1;
            }
        }

        float inv_[4];
#pragma unroll
        for (int r = 0; r < 4; ++r) {
            float mx = fmaxf(s0[r], s1[r]);
#pragma unroll
            for (int o = 16; o; o >>= 1) mx = fmaxf(mx, __shfl_xor_sync(0xffffffffu, mx, o));
            mx = fmaxf(mx, s64[r]);
            const float e0 = __expf(s0[r] - mx);
            const float e1 = __expf(s1[r] - mx);
            const float e2 = __expf(s64[r] - mx);
            float sum = e0 + e1;
#pragma unroll
            for (int o = 16; o; o >>= 1) sum += __shfl_xor_sync(0xffffffffu, sum, o);
            sum += e2;
            sSw[r * 66 + lane]      = e0;
            sSw[r * 66 + lane + 32] = e1;
            if (lane == 0) sSw[r * 66 + 64] = e2;
            inv_[r] = 1.f / sum;
        }
        __syncwarp();

        float a0[4] = {0.f, 0.f, 0.f, 0.f}, a1[4] = {0.f, 0.f, 0.f, 0.f};
        for (int m = 0; m < NT; ++m) {
            const float v0 = sV[m * DH + lane];
            const float v1 = sV[m * DH + lane + 32];
#pragma unroll
            for (int r = 0; r < 4; ++r) {
                const float p = sSw[r * 66 + m];
                a0[r] += p * v0;
                a1[r] += p * v1;
            }
        }
#pragma unroll
        for (int r = 0; r < 4; ++r) {
            const int i = i0 + r;
            if (i < NT) {
                __half* oh = g_attbf + ((size_t)(b * NT + i)) * 1536 + h * DH;
                const float v0 = a0[r] * inv_[r];
                const float v1 = a1[r] * inv_[r];
                const __half h0 = __float2half(v0);
                const __half h1 = __float2half(v1);
                oh[lane]            = h0;
                oh[lane + 32]       = h1;
                oh[768 + lane]      = __float2half(v0 - __half2float(h0));
                oh[768 + lane + 32] = __float2half(v1 - __half2float(h1));
            }
        }
        __syncwarp();
    }
}

// ---------------- host launcher ----------------
extern "C" void kernel_launch(void* const* d_in, const int* in_sizes, int n_in,
                              void* d_out, int out_size)
{
    const float* x       = (const float*)d_in[0];
    const float* qkv_w   = (const float*)d_in[1];
    const float* proj_w  = (const float*)d_in[2];
    const float* qn_g    = (const float*)d_in[3];
    const float* qn_b    = (const float*)d_in[4];
    const float* kn_g    = (const float*)d_in[5];
    const float* kn_b    = (const float*)d_in[6];
    const float* sg_w1   = (const float*)d_in[7];
    const float* sg_ln1g = (const float*)d_in[8];
    const float* sg_ln1b = (const float*)d_in[9];
    const float* sg_w2   = (const float*)d_in[10];
    const float* sg_ln2g = (const float*)d_in[11];
    const float* sg_ln2b = (const float*)d_in[12];
    const float* sg_bw   = (const float*)d_in[13];
    float* out = (float*)d_out;

    float *p_lat1, *p_lat2, *p_bias;
    cudaGetSymbolAddress((void**)&p_lat1, g_lat1);
    cudaGetSymbolAddress((void**)&p_lat2, g_lat2);
    cudaGetSymbolAddress((void**)&p_bias, g_bias);
    __half *pxbf, *pattbf, *pwqkv, *pwproj, *pcls, *pw1, *pl1, *pw2, *pl2, *pwb;
    cudaGetSymbolAddress((void**)&pxbf,  g_xbf);
    cudaGetSymbolAddress((void**)&pattbf,g_attbf);
    cudaGetSymbolAddress((void**)&pwqkv, g_wqkv);
    cudaGetSymbolAddress((void**)&pwproj,g_wproj);
    cudaGetSymbolAddress((void**)&pcls,  g_clsbf);
    cudaGetSymbolAddress((void**)&pw1,   g_w1bf);
    cudaGetSymbolAddress((void**)&pl1,   g_l1bf);
    cudaGetSymbolAddress((void**)&pw2,   g_w2bf);
    cudaGetSymbolAddress((void**)&pl2,   g_l2bf);
    cudaGetSymbolAddress((void**)&pwb,   g_wbbf);

    cudaFuncSetAttribute(gemm_mma<0>, cudaFuncAttributeMaxDynamicSharedMemorySize, GEMM_SMEM);
    cudaFuncSetAttribute(gemm_mma<1>, cudaFuncAttributeMaxDynamicSharedMemorySize, GEMM_SMEM);
    cudaFuncSetAttribute(attn_kernel, cudaFuncAttributeMaxDynamicSharedMemorySize, ATTN_SMEM);

    // --- conversions for qkv GEMM ---
    conv_split<<<66560, 192>>>(x, CH, pxbf, CH, 66560);
    conv16<<<2304, 192>>>(qkv_w, pwqkv, CH, 2304);
    // 1. qkv (scatter into q/k/v)
    gemm_mma<0><<<dim3(18, 520), 128, GEMM_SMEM>>>(pxbf, 1536, pwqkv, 768, nullptr, 0, 66560, 2304, 768);
    // 2. per-head LN on q/k
    qk_ln_kernel<<<99840, 256>>>(qn_g, qn_b, kn_g, kn_b);

    // --- bias-generator path ---
    conv_split<<<1024, 192>>>(x, NT * CH, pcls, CH, 1024);
    conv16<<<512, 192>>>(sg_w1, pw1, CH, 512);
    gemm_mma<1><<<dim3(4, 8), 128, GEMM_SMEM>>>(pcls, 1536, pw1, 768, p_lat1, 512, 1024, 512, 768);
    ln_silu512<<<1024, 256>>>(p_lat1, sg_ln1g, sg_ln1b);
    conv_split<<<1024, 128>>>(p_lat1, 512, pl1, 512, 1024);
    conv16<<<3072, 128>>>(sg_w2, pw2, 512, 3072);
    gemm_mma<1><<<dim3(24, 8), 128, GEMM_SMEM>>>(pl1, 1024, pw2, 512, p_lat2, 3072, 1024, 3072, 512);
    ln3072<<<1024, 256>>>(p_lat2, sg_ln2g, sg_ln2b);
    conv_split<<<12288, 64>>>(p_lat2, 256, pl2, 256, 12288);
    conv16<<<4352, 64>>>(sg_bw, pwb, 256, 4225);
    gemm_mma<1><<<dim3(34, 96), 128, GEMM_SMEM>>>(pl2, 512, pwb, 256, p_bias, 4225, 12288, 4225, 256);

    // --- attention (writes fp16 hi|lo directly) ---
    attn_kernel<<<NBATCH * NH, 256, ATTN_SMEM>>>();

    // --- output projection ---
    conv16<<<768, 192>>>(proj_w, pwproj, CH, 768);
    gemm_mma<1><<<dim3(6, 520), 128, GEMM_SMEM>>>(pattbf, 1536, pwproj, 768, out, 768, 66560, 768, 768);
}

// round 8
// speedup vs baseline: 3.8407x; 1.0171x over previous
#include <cuda_runtime.h>
#include <cuda_fp16.h>
#include <cstdint>

// ---------------- problem constants ----------------
#define NBATCH 1024
#define NT     65
#define CH     768
#define NH     12
#define DH     64

// ---------------- fp32 scratch ----------------
__device__ __align__(16) float g_q[51118080];     // [B,H,NT,DH] (pre-LN)
__device__ __align__(16) float g_k[51118080];     // (pre-LN)
__device__ __align__(16) float g_v[51118080];
__device__ __align__(16) float g_bias[51916800];  // [B*H,65*65]
__device__ __align__(16) float g_lat1[524288];    // [1024,512]
__device__ __align__(16) float g_lat2[3145728];   // [1024,3072]

// ---------------- fp16 scratch ----------------
// A-side operands: [hi(K) | lo(K)] per row. B-side weights: plain fp16.
__device__ __align__(16) __half g_xbf[102236160];   // 66560 x 1536
__device__ __align__(16) __half g_attbf[102236160]; // 66560 x 1536 (written by attn)
__device__ __align__(16) __half g_clsbf[1572864];   // 1024 x 1536
__device__ __align__(16) __half g_l1bf[1048576];    // 1024 x 1024
__device__ __align__(16) __half g_l2bf[6291456];    // 12288 x 512
__device__ __align__(16) __half g_wqkv[1769472];    // 2304 x 768
__device__ __align__(16) __half g_wproj[589824];    // 768 x 768
__device__ __align__(16) __half g_w1bf[393216];     // 512 x 768
__device__ __align__(16) __half g_w2bf[1572864];    // 3072 x 512
__device__ __align__(16) __half g_wbbf[1114112];    // 4352 x 256 (rows >= 4225 zero)

// ---------------- helpers ----------------
__device__ __forceinline__ uint32_t s2u(const void* p) {
    uint32_t a;
    asm("{ .reg .u64 t; cvta.to.shared.u64 t, %1; cvt.u32.u64 %0, t; }" : "=r"(a) : "l"(p));
    return a;
}
__device__ __forceinline__ void ldsm4(uint32_t* r, uint32_t addr) {
    asm volatile("ldmatrix.sync.aligned.m8n8.x4.shared.b16 {%0,%1,%2,%3}, [%4];"
        : "=r"(r[0]), "=r"(r[1]), "=r"(r[2]), "=r"(r[3]) : "r"(addr));
}
__device__ __forceinline__ void mma16816(float* d, const uint32_t* a, uint32_t b0, uint32_t b1) {
    asm volatile(
        "mma.sync.aligned.m16n8k16.row.col.f32.f16.f16.f32 "
        "{%0,%1,%2,%3}, {%4,%5,%6,%7}, {%8,%9}, {%0,%1,%2,%3};"
        : "+f"(d[0]), "+f"(d[1]), "+f"(d[2]), "+f"(d[3])
        : "r"(a[0]), "r"(a[1]), "r"(a[2]), "r"(a[3]), "r"(b0), "r"(b1));
}

// ---------------- fp32 -> fp16 hi|lo split (A-side) ----------------
__global__ void conv_split(const float* __restrict__ src, int lds,
                           __half* __restrict__ dst, int K, int rowsValid)
{
    const int r = blockIdx.x;
    const float4* s = (const float4*)(src + (size_t)r * lds);
    __half2* dh = (__half2*)(dst + (size_t)r * 2 * K);
    __half2* dl = (__half2*)(dst + (size_t)r * 2 * K + K);
    const bool valid = r < rowsValid;
    for (int c = threadIdx.x; c < K / 4; c += blockDim.x) {
        float4 v = valid ? s[c] : make_float4(0.f, 0.f, 0.f, 0.f);
        __half hx = __float2half(v.x), hy = __float2half(v.y);
        __half hz = __float2half(v.z), hw = __float2half(v.w);
        dh[c * 2]     = __half2(hx, hy);
        dh[c * 2 + 1] = __half2(hz, hw);
        dl[c * 2]     = __half2(__float2half(v.x - __half2float(hx)),
                                __float2half(v.y - __half2float(hy)));
        dl[c * 2 + 1] = __half2(__float2half(v.z - __half2float(hz)),
                                __float2half(v.w - __half2float(hw)));
    }
}

// ---------------- fp32 -> fp16 plain (B-side weights) ----------------
__global__ void conv16(const float* __restrict__ src, __half* __restrict__ dst,
                       int K, int rowsValid)
{
    const int r = blockIdx.x;
    const float4* s = (const float4*)(src + (size_t)r * K);
    __half2* d = (__half2*)(dst + (size_t)r * K);
    const bool valid = r < rowsValid;
    for (int c = threadIdx.x; c < K / 4; c += blockDim.x) {
        float4 v = valid ? s[c] : make_float4(0.f, 0.f, 0.f, 0.f);
        d[c * 2]     = __half2(__float2half(v.x), __float2half(v.y));
        d[c * 2 + 1] = __half2(__float2half(v.z), __float2half(v.w));
    }
}

// ---------------- fp16 2-pass split GEMM: C = (Ah+Al) @ Bh^T ----------------
#define KC    32
#define LDS_  40                       // padded fp16 row stride (80B)
#define APART 10240u
#define STGB  30720u                   // Ah + Al + B
#define NSTG  3
#define GEMM_SMEM (NSTG * STGB)        // 92160

template<int MODE>
__global__ __launch_bounds__(128, 2)
void gemm_mma(const __half* __restrict__ A, int lda,
              const __half* __restrict__ B, int ldb,
              float* __restrict__ C, int ldc, int M, int N, int K)
{
    extern __shared__ char dynsm[];
    const uint32_t sbase = s2u(dynsm);

    const int tid = threadIdx.x, wid = tid >> 5, lane = tid & 31;
    const int wm = wid & 1, wn = wid >> 1;            // 2 x 2 warp grid
    const int bm = blockIdx.y * 128, bn = blockIdx.x * 128;
    const int nk = K / KC;

    float acc[4][8][4];
#pragma unroll
    for (int i = 0; i < 4; i++)
#pragma unroll
        for (int j = 0; j < 8; j++)
#pragma unroll
            for (int e = 0; e < 4; e++) acc[i][j][e] = 0.f;

    auto loads = [&](int t) {
        const uint32_t ub = sbase + (uint32_t)(t % NSTG) * STGB;
        const int kOff = t * KC;
#pragma unroll
        for (int i = 0; i < 12; i++) {
            const int idx = tid + i * 128;
            const int part = idx >> 9;             // 0 Ah, 1 Al, 2 B
            const int id2 = idx & 511;
            const int r = id2 >> 2, cc = id2 & 3;
            const uint32_t dst = ub + (uint32_t)part * APART +
                                 (uint32_t)(r * LDS_ + cc * 8) * 2;
            const void* g = (part == 2)
                ? (const void*)(B + (size_t)(bn + r) * ldb + kOff + cc * 8)
                : (const void*)(A + (size_t)(bm + r) * lda + part * K + kOff + cc * 8);
            asm volatile("cp.async.cg.shared.global [%0], [%1], 16;" :: "r"(dst), "l"(g));
        }
        asm volatile("cp.async.commit_group;");
    };

    loads(0);
    if (nk > 1) loads(1);

    for (int t = 0; t < nk; ++t) {
        if (t + 1 < nk) asm volatile("cp.async.wait_group 1;");
        else            asm volatile("cp.async.wait_group 0;");
        __syncthreads();
        if (t + 2 < nk) loads(t + 2);

        const uint32_t ub  = sbase + (uint32_t)(t % NSTG) * STGB;
        const uint32_t uAh = ub + (uint32_t)(wm * 64 * LDS_) * 2;
        const uint32_t uAl = uAh + APART;
        const uint32_t uB  = ub + 2 * APART + (uint32_t)(wn * 64 * LDS_) * 2;
#pragma unroll
        for (int ks = 0; ks < 2; ++ks) {
            uint32_t ah[4][4], al[4][4], b[4][4];
#pragma unroll
            for (int mt = 0; mt < 4; ++mt) {
                const uint32_t ro = (uint32_t)((mt * 16 + (lane & 15)) * LDS_ +
                                               ks * 16 + (lane >> 4) * 8) * 2;
                ldsm4(ah[mt], uAh + ro);
                ldsm4(al[mt], uAl + ro);
            }
#pragma unroll
            for (int ng = 0; ng < 4; ++ng) {
                const uint32_t addr = uB +
                    (uint32_t)((ng * 16 + ((lane >> 4) & 1) * 8 + (lane & 7)) * LDS_ +
                               ks * 16 + ((lane >> 3) & 1) * 8) * 2;
                ldsm4(b[ng], addr);
            }
#pragma unroll
            for (int mt = 0; mt < 4; ++mt)
#pragma unroll
                for (int nt = 0; nt < 8; ++nt) {
                    const uint32_t b0 = b[nt >> 1][(nt & 1) * 2];
                    const uint32_t b1 = b[nt >> 1][(nt & 1) * 2 + 1];
                    mma16816(acc[mt][nt], ah[mt], b0, b1);
                    mma16816(acc[mt][nt], al[mt], b0, b1);
                }
        }
    }

    const int gr = lane >> 2, gc = (lane & 3) * 2;
#pragma unroll
    for (int mt = 0; mt < 4; ++mt) {
#pragma unroll
        for (int nt = 0; nt < 8; ++nt) {
#pragma unroll
            for (int e = 0; e < 4; ++e) {
                const int m = bm + wm * 64 + mt * 16 + gr + (e >> 1) * 8;
                const int n = bn + wn * 64 + nt * 8 + gc + (e & 1);
                const float v = acc[mt][nt][e];
                if (MODE == 0) {
                    const int s   = n / CH;
                    const int rem = n - s * CH;
                    const int h   = rem >> 6;
                    const int d   = rem & 63;
                    const int bb  = m / NT;
                    const int tt  = m - bb * NT;
                    const size_t idx = (((size_t)(bb * NH + h)) * NT + tt) * DH + d;
                    float* dst = (s == 0) ? g_q : (s == 1) ? g_k : g_v;
                    dst[idx] = v;
                } else {
                    if (n < N) C[(size_t)m * ldc + n] = v;
                }
            }
        }
    }
}

// ---------------- block reduce helper ----------------
__device__ __forceinline__ float2 block_reduce2(float s, float ss, float* shm)
{
#pragma unroll
    for (int o = 16; o; o >>= 1) {
        s  += __shfl_xor_sync(0xffffffffu, s,  o);
        ss += __shfl_xor_sync(0xffffffffu, ss, o);
    }
    const int w = threadIdx.x >> 5, lane = threadIdx.x & 31;
    if (lane == 0) { shm[w] = s; shm[8 + w] = ss; }
    __syncthreads();
    if (threadIdx.x < 32) {
        s  = (lane < 8) ? shm[lane]     : 0.f;
        ss = (lane < 8) ? shm[8 + lane] : 0.f;
#pragma unroll
        for (int o = 4; o; o >>= 1) {
            s  += __shfl_xor_sync(0xffffffffu, s,  o);
            ss += __shfl_xor_sync(0xffffffffu, ss, o);
        }
        if (lane == 0) { shm[0] = s; shm[1] = ss; }
    }
    __syncthreads();
    return make_float2(shm[0], shm[1]);
}

__global__ __launch_bounds__(256)
void ln_silu512(float* __restrict__ data, const float* __restrict__ g, const float* __restrict__ b)
{
    __shared__ float shm[16];
    const int row = blockIdx.x, tid = threadIdx.x;
    float* p = data + (size_t)row * 512;
    float x0 = p[tid], x1 = p[tid + 256];
    float2 r = block_reduce2(x0 + x1, x0 * x0 + x1 * x1, shm);
    const float mean = r.x * (1.f / 512.f);
    const float var  = r.y * (1.f / 512.f) - mean * mean;
    const float inv  = rsqrtf(var + 1e-5f);
    float y0 = (x0 - mean) * inv * g[tid]       + b[tid];
    float y1 = (x1 - mean) * inv * g[tid + 256] + b[tid + 256];
    p[tid]       = y0 / (1.f + __expf(-y0));
    p[tid + 256] = y1 / (1.f + __expf(-y1));
}

__global__ __launch_bounds__(256)
void ln3072(float* __restrict__ data, const float* __restrict__ g, const float* __restrict__ b)
{
    __shared__ float shm[16];
    const int row = blockIdx.x, tid = threadIdx.x;
    float* p = data + (size_t)row * 3072;
    float x[12];
    float s = 0.f, ss = 0.f;
#pragma unroll
    for (int i = 0; i < 12; i++) {
        x[i] = p[tid + i * 256];
        s += x[i]; ss += x[i] * x[i];
    }
    float2 r = block_reduce2(s, ss, shm);
    const float mean = r.x * (1.f / 3072.f);
    const float var  = r.y * (1.f / 3072.f) - mean * mean;
    const float inv  = rsqrtf(var + 1e-5f);
#pragma unroll
    for (int i = 0; i < 12; i++) {
        const int c = tid + i * 256;
        p[c] = (x[i] - mean) * inv * g[c] + b[c];
    }
}

// ---------------- fused attention with in-smem Q/K LayerNorm ----------------
#define ATTN_SMEM ((4160 + 4160 + 4225 + 2112) * 4)

__global__ __launch_bounds__(256)
void attn_kernel(const float* __restrict__ qn_g, const float* __restrict__ qn_b,
                 const float* __restrict__ kn_g, const float* __restrict__ kn_b)
{
    extern __shared__ float asmem[];
    float* sV = asmem;
    float* sQ = asmem + 4160;
    float* sK = asmem + 8320;
    float* sS = asmem + 12545;

    const int bh  = blockIdx.x;
    const int tid = threadIdx.x;
    const size_t base = (size_t)bh * (NT * DH);
    const int w = tid >> 5, lane = tid & 31;

    const float4* k4 = (const float4*)(g_k + base);
    const float4* v4 = (const float4*)(g_v + base);
    const float4* q4 = (const float4*)(g_q + base);
    for (int i = tid; i < NT * (DH / 4); i += 256) {
        ((float4*)sV)[i] = v4[i];
        ((float4*)sQ)[i] = q4[i];
        float4 kv = k4[i];
        const int r = i >> 4, c = (i & 15) << 2;
        float* d = sK + r * 65 + c;
        d[0] = kv.x; d[1] = kv.y; d[2] = kv.z; d[3] = kv.w;
    }
    __syncthreads();

    // ---- fused per-row LayerNorm on sQ (x 1/8) and sK ----
    {
        const float qg0 = qn_g[lane], qg1 = qn_g[lane + 32];
        const float qb0 = qn_b[lane], qb1 = qn_b[lane + 32];
        const float kg0 = kn_g[lane], kg1 = kn_g[lane + 32];
        const float kb0 = kn_b[lane], kb1 = kn_b[lane + 32];
        for (int r = w; r < 2 * NT; r += 8) {
            const bool isQ = (r < NT);
            float* row = isQ ? (sQ + r * DH) : (sK + (r - NT) * 65);
            float x0 = row[lane], x1 = row[lane + 32];
            float s = x0 + x1, ss = x0 * x0 + x1 * x1;
#pragma unroll
            for (int o = 16; o; o >>= 1) {
                s  += __shfl_xor_sync(0xffffffffu, s,  o);
                ss += __shfl_xor_sync(0xffffffffu, ss, o);
            }
            const float mean = s * (1.f / 64.f);
            const float var  = ss * (1.f / 64.f) - mean * mean;
            const float inv  = rsqrtf(var + 1e-5f);
            const float g0 = isQ ? qg0 : kg0, g1 = isQ ? qg1 : kg1;
            const float b0 = isQ ? qb0 : kb0, b1 = isQ ? qb1 : kb1;
            const float sc = isQ ? 0.125f : 1.f;
            row[lane]      = ((x0 - mean) * inv * g0 + b0) * sc;
            row[lane + 32] = ((x1 - mean) * inv * g1 + b1) * sc;
        }
    }
    __syncthreads();

    const float* bp = g_bias + (size_t)bh * (NT * NT);
    const int b = bh / NH, h = bh - b * NH;
    float* sSw = sS + w * 4 * 66;

    for (int i0 = w * 4; i0 < NT; i0 += 32) {
        int irr[4];
#pragma unroll
        for (int r = 0; r < 4; ++r) irr[r] = (i0 + r < NT) ? (i0 + r) : (NT - 1);

        float s64[4];
#pragma unroll
        for (int r = 0; r < 4; ++r) {
            float t = sQ[irr[r] * DH + lane]      * sK[64 * 65 + lane]
                    + sQ[irr[r] * DH + lane + 32] * sK[64 * 65 + lane + 32];
#pragma unroll
            for (int o = 16; o; o >>= 1) t += __shfl_xor_sync(0xffffffffu, t, o);
            s64[r] = t + bp[irr[r] * NT + 64];
        }

        float s0[4], s1[4];
#pragma unroll
        for (int r = 0; r < 4; ++r) {
            s0[r] = bp[irr[r] * NT + lane];
            s1[r] = bp[irr[r] * NT + lane + 32];
        }
#pragma unroll 4
        for (int d = 0; d < DH; ++d) {
            const float k0 = sK[lane * 65 + d];
            const float k1 = sK[(lane + 32) * 65 + d];
#pragma unroll
            for (int r = 0; r < 4; ++r) {
                const float qd = sQ[irr[r] * DH + d];
                s0[r] += qd * k0;
                s1[r] += qd * k1;
            }
        }

        float inv_[4];
#pragma unroll
        for (int r = 0; r < 4; ++r) {
            float mx = fmaxf(s0[r], s1[r]);
#pragma unroll
            for (int o = 16; o; o >>= 1) mx = fmaxf(mx, __shfl_xor_sync(0xffffffffu, mx, o));
            mx = fmaxf(mx, s64[r]);
            const float e0 = __expf(s0[r] - mx);
            const float e1 = __expf(s1[r] - mx);
            const float e2 = __expf(s64[r] - mx);
            float sum = e0 + e1;
#pragma unroll
            for (int o = 16; o; o >>= 1) sum += __shfl_xor_sync(0xffffffffu, sum, o);
            sum += e2;
            sSw[r * 66 + lane]      = e0;
            sSw[r * 66 + lane + 32] = e1;
            if (lane == 0) sSw[r * 66 + 64] = e2;
            inv_[r] = 1.f / sum;
        }
        __syncwarp();

        float a0[4] = {0.f, 0.f, 0.f, 0.f}, a1[4] = {0.f, 0.f, 0.f, 0.f};
        for (int m = 0; m < NT; ++m) {
            const float v0 = sV[m * DH + lane];
            const float v1 = sV[m * DH + lane + 32];
#pragma unroll
            for (int r = 0; r < 4; ++r) {
                const float p = sSw[r * 66 + m];
                a0[r] += p * v0;
                a1[r] += p * v1;
            }
        }
#pragma unroll
        for (int r = 0; r < 4; ++r) {
            const int i = i0 + r;
            if (i < NT) {
                __half* oh = g_attbf + ((size_t)(b * NT + i)) * 1536 + h * DH;
                const float v0 = a0[r] * inv_[r];
                const float v1 = a1[r] * inv_[r];
                const __half h0 = __float2half(v0);
                const __half h1 = __float2half(v1);
                oh[lane]            = h0;
                oh[lane + 32]       = h1;
                oh[768 + lane]      = __float2half(v0 - __half2float(h0));
                oh[768 + lane + 32] = __float2half(v1 - __half2float(h1));
            }
        }
        __syncwarp();
    }
}

// ---------------- host launcher ----------------
extern "C" void kernel_launch(void* const* d_in, const int* in_sizes, int n_in,
                              void* d_out, int out_size)
{
    const float* x       = (const float*)d_in[0];
    const float* qkv_w   = (const float*)d_in[1];
    const float* proj_w  = (const float*)d_in[2];
    const float* qn_g    = (const float*)d_in[3];
    const float* qn_b    = (const float*)d_in[4];
    const float* kn_g    = (const float*)d_in[5];
    const float* kn_b    = (const float*)d_in[6];
    const float* sg_w1   = (const float*)d_in[7];
    const float* sg_ln1g = (const float*)d_in[8];
    const float* sg_ln1b = (const float*)d_in[9];
    const float* sg_w2   = (const float*)d_in[10];
    const float* sg_ln2g = (const float*)d_in[11];
    const float* sg_ln2b = (const float*)d_in[12];
    const float* sg_bw   = (const float*)d_in[13];
    float* out = (float*)d_out;

    float *p_lat1, *p_lat2, *p_bias;
    cudaGetSymbolAddress((void**)&p_lat1, g_lat1);
    cudaGetSymbolAddress((void**)&p_lat2, g_lat2);
    cudaGetSymbolAddress((void**)&p_bias, g_bias);
    __half *pxbf, *pattbf, *pwqkv, *pwproj, *pcls, *pw1, *pl1, *pw2, *pl2, *pwb;
    cudaGetSymbolAddress((void**)&pxbf,  g_xbf);
    cudaGetSymbolAddress((void**)&pattbf,g_attbf);
    cudaGetSymbolAddress((void**)&pwqkv, g_wqkv);
    cudaGetSymbolAddress((void**)&pwproj,g_wproj);
    cudaGetSymbolAddress((void**)&pcls,  g_clsbf);
    cudaGetSymbolAddress((void**)&pw1,   g_w1bf);
    cudaGetSymbolAddress((void**)&pl1,   g_l1bf);
    cudaGetSymbolAddress((void**)&pw2,   g_w2bf);
    cudaGetSymbolAddress((void**)&pl2,   g_l2bf);
    cudaGetSymbolAddress((void**)&pwb,   g_wbbf);

    cudaFuncSetAttribute(gemm_mma<0>, cudaFuncAttributeMaxDynamicSharedMemorySize, GEMM_SMEM);
    cudaFuncSetAttribute(gemm_mma<1>, cudaFuncAttributeMaxDynamicSharedMemorySize, GEMM_SMEM);
    cudaFuncSetAttribute(attn_kernel, cudaFuncAttributeMaxDynamicSharedMemorySize, ATTN_SMEM);

    // side stream + events (created once, on the first — uncaptured — call)
    static cudaStream_t sB = nullptr;
    static cudaEvent_t evFork = nullptr, evJoin = nullptr;
    if (sB == nullptr) {
        cudaStreamCreateWithFlags(&sB, cudaStreamNonBlocking);
        cudaEventCreateWithFlags(&evFork, cudaEventDisableTiming);
        cudaEventCreateWithFlags(&evJoin, cudaEventDisableTiming);
    }

    // fork: bias-generator path runs concurrently on sB
    cudaEventRecord(evFork, 0);
    cudaStreamWaitEvent(sB, evFork, 0);

    // --- side stream: bias path + proj weight conversion ---
    conv_split<<<1024, 192, 0, sB>>>(x, NT * CH, pcls, CH, 1024);
    conv16<<<512, 192, 0, sB>>>(sg_w1, pw1, CH, 512);
    conv16<<<768, 192, 0, sB>>>(proj_w, pwproj, CH, 768);
    gemm_mma<1><<<dim3(4, 8), 128, GEMM_SMEM, sB>>>(pcls, 1536, pw1, 768, p_lat1, 512, 1024, 512, 768);
    ln_silu512<<<1024, 256, 0, sB>>>(p_lat1, sg_ln1g, sg_ln1b);
    conv_split<<<1024, 128, 0, sB>>>(p_lat1, 512, pl1, 512, 1024);
    conv16<<<3072, 128, 0, sB>>>(sg_w2, pw2, 512, 3072);
    gemm_mma<1><<<dim3(24, 8), 128, GEMM_SMEM, sB>>>(pl1, 1024, pw2, 512, p_lat2, 3072, 1024, 3072, 512);
    ln3072<<<1024, 256, 0, sB>>>(p_lat2, sg_ln2g, sg_ln2b);
    conv_split<<<12288, 64, 0, sB>>>(p_lat2, 256, pl2, 256, 12288);
    conv16<<<4352, 64, 0, sB>>>(sg_bw, pwb, 256, 4225);
    gemm_mma<1><<<dim3(34, 96), 128, GEMM_SMEM, sB>>>(pl2, 512, pwb, 256, p_bias, 4225, 12288, 4225, 256);
    cudaEventRecord(evJoin, sB);

    // --- main stream: qkv path ---
    conv_split<<<66560, 192>>>(x, CH, pxbf, CH, 66560);
    conv16<<<2304, 192>>>(qkv_w, pwqkv, CH, 2304);
    gemm_mma<0><<<dim3(18, 520), 128, GEMM_SMEM>>>(pxbf, 1536, pwqkv, 768, nullptr, 0, 66560, 2304, 768);

    // join: attention needs q/k/v AND bias
    cudaStreamWaitEvent(0, evJoin, 0);
    attn_kernel<<<NBATCH * NH, 256, ATTN_SMEM>>>(qn_g, qn_b, kn_g, kn_b);

    // --- output projection ---
    gemm_mma<1><<<dim3(6, 520), 128, GEMM_SMEM>>>(pattbf, 1536, pwproj, 768, out, 768, 66560, 768, 768);
}

// round 9
// speedup vs baseline: 4.1431x; 1.0787x over previous
#include <cuda_runtime.h>
#include <cuda_fp16.h>
#include <cstdint>

// ---------------- problem constants ----------------
#define NBATCH 1024
#define NT     65
#define CH     768
#define NH     12
#define DH     64

// ---------------- fp32 scratch ----------------
__device__ __align__(16) float g_q[51118080];     // [B,H,NT,DH] (pre-LN)
__device__ __align__(16) float g_k[51118080];     // (pre-LN)
__device__ __align__(16) float g_v[51118080];
__device__ __align__(16) float g_bias[51916800];  // [B*H,65*65]
__device__ __align__(16) float g_lat1[524288];    // [1024,512]
__device__ __align__(16) float g_lat2[3145728];   // [1024,3072]

// ---------------- fp16 scratch ----------------
__device__ __align__(16) __half g_xbf[102236160];   // 66560 x 1536 [hi|lo]
__device__ __align__(16) __half g_attbf[51118080];  // 66560 x 768 (plain fp16, by attn)
__device__ __align__(16) __half g_clsbf[1572864];   // 1024 x 1536 [hi|lo]
__device__ __align__(16) __half g_l1bf[1048576];    // 1024 x 1024 [hi|lo]
__device__ __align__(16) __half g_l2bf[6291456];    // 12288 x 512 [hi|lo]
__device__ __align__(16) __half g_wqkv[1769472];    // 2304 x 768
__device__ __align__(16) __half g_wproj[589824];    // 768 x 768
__device__ __align__(16) __half g_w1bf[393216];     // 512 x 768
__device__ __align__(16) __half g_w2bf[1572864];    // 3072 x 512
__device__ __align__(16) __half g_wbbf[1114112];    // 4352 x 256 (rows >= 4225 zero)

// ---------------- helpers ----------------
__device__ __forceinline__ uint32_t s2u(const void* p) {
    uint32_t a;
    asm("{ .reg .u64 t; cvta.to.shared.u64 t, %1; cvt.u32.u64 %0, t; }" : "=r"(a) : "l"(p));
    return a;
}
__device__ __forceinline__ void ldsm4(uint32_t* r, uint32_t addr) {
    asm volatile("ldmatrix.sync.aligned.m8n8.x4.shared.b16 {%0,%1,%2,%3}, [%4];"
        : "=r"(r[0]), "=r"(r[1]), "=r"(r[2]), "=r"(r[3]) : "r"(addr));
}
__device__ __forceinline__ void mma16816(float* d, const uint32_t* a, uint32_t b0, uint32_t b1) {
    asm volatile(
        "mma.sync.aligned.m16n8k16.row.col.f32.f16.f16.f32 "
        "{%0,%1,%2,%3}, {%4,%5,%6,%7}, {%8,%9}, {%0,%1,%2,%3};"
        : "+f"(d[0]), "+f"(d[1]), "+f"(d[2]), "+f"(d[3])
        : "r"(a[0]), "r"(a[1]), "r"(a[2]), "r"(a[3]), "r"(b0), "r"(b1));
}

// ---------------- fp32 -> fp16 hi|lo split (A-side) ----------------
__global__ void conv_split(const float* __restrict__ src, int lds,
                           __half* __restrict__ dst, int K, int rowsValid)
{
    const int r = blockIdx.x;
    const float4* s = (const float4*)(src + (size_t)r * lds);
    __half2* dh = (__half2*)(dst + (size_t)r * 2 * K);
    __half2* dl = (__half2*)(dst + (size_t)r * 2 * K + K);
    const bool valid = r < rowsValid;
    for (int c = threadIdx.x; c < K / 4; c += blockDim.x) {
        float4 v = valid ? s[c] : make_float4(0.f, 0.f, 0.f, 0.f);
        __half hx = __float2half(v.x), hy = __float2half(v.y);
        __half hz = __float2half(v.z), hw = __float2half(v.w);
        dh[c * 2]     = __half2(hx, hy);
        dh[c * 2 + 1] = __half2(hz, hw);
        dl[c * 2]     = __half2(__float2half(v.x - __half2float(hx)),
                                __float2half(v.y - __half2float(hy)));
        dl[c * 2 + 1] = __half2(__float2half(v.z - __half2float(hz)),
                                __float2half(v.w - __half2float(hw)));
    }
}

// ---------------- fp32 -> fp16 plain (B-side weights) ----------------
__global__ void conv16(const float* __restrict__ src, __half* __restrict__ dst,
                       int K, int rowsValid)
{
    const int r = blockIdx.x;
    const float4* s = (const float4*)(src + (size_t)r * K);
    __half2* d = (__half2*)(dst + (size_t)r * K);
    const bool valid = r < rowsValid;
    for (int c = threadIdx.x; c < K / 4; c += blockDim.x) {
        float4 v = valid ? s[c] : make_float4(0.f, 0.f, 0.f, 0.f);
        d[c * 2]     = __half2(__float2half(v.x), __float2half(v.y));
        d[c * 2 + 1] = __half2(__float2half(v.z), __float2half(v.w));
    }
}

// ---------------- fp16 split GEMM: C = A @ B^T ----------------
// PASSES=2: A is M x 2K [hi|lo], C=(Ah+Al)@B.  PASSES=1: A is M x K plain fp16.
#define KC    32
#define LDS_  40                       // padded fp16 row stride (80B)
#define APART 10240u
#define NSTG  3

template<int MODE, int PASSES>
__global__ __launch_bounds__(128, 2)
void gemm_mma(const __half* __restrict__ A, int lda,
              const __half* __restrict__ B, int ldb,
              float* __restrict__ C, int ldc, int M, int N, int K)
{
    constexpr int NPARTS = PASSES + 1;              // A parts + B
    constexpr uint32_t STGB = NPARTS * APART;

    extern __shared__ char dynsm[];
    const uint32_t sbase = s2u(dynsm);

    const int tid = threadIdx.x, wid = tid >> 5, lane = tid & 31;
    const int wm = wid & 1, wn = wid >> 1;            // 2 x 2 warp grid
    const int bm = blockIdx.y * 128, bn = blockIdx.x * 128;
    const int nk = K / KC;

    float acc[4][8][4];
#pragma unroll
    for (int i = 0; i < 4; i++)
#pragma unroll
        for (int j = 0; j < 8; j++)
#pragma unroll
            for (int e = 0; e < 4; e++) acc[i][j][e] = 0.f;

    auto loads = [&](int t) {
        const uint32_t ub = sbase + (uint32_t)(t % NSTG) * STGB;
        const int kOff = t * KC;
#pragma unroll
        for (int i = 0; i < 4 * NPARTS; i++) {
            const int idx = tid + i * 128;
            const int part = idx >> 9;             // 0..PASSES-1: A parts, last: B
            const int id2 = idx & 511;
            const int r = id2 >> 2, cc = id2 & 3;
            const uint32_t dst = ub + (uint32_t)part * APART +
                                 (uint32_t)(r * LDS_ + cc * 8) * 2;
            const void* g = (part == NPARTS - 1)
                ? (const void*)(B + (size_t)(bn + r) * ldb + kOff + cc * 8)
                : (const void*)(A + (size_t)(bm + r) * lda + part * K + kOff + cc * 8);
            asm volatile("cp.async.cg.shared.global [%0], [%1], 16;" :: "r"(dst), "l"(g));
        }
        asm volatile("cp.async.commit_group;");
    };

    loads(0);
    if (nk > 1) loads(1);

    for (int t = 0; t < nk; ++t) {
        if (t + 1 < nk) asm volatile("cp.async.wait_group 1;");
        else            asm volatile("cp.async.wait_group 0;");
        __syncthreads();
        if (t + 2 < nk) loads(t + 2);

        const uint32_t ub  = sbase + (uint32_t)(t % NSTG) * STGB;
        const uint32_t uAh = ub + (uint32_t)(wm * 64 * LDS_) * 2;
        const uint32_t uAl = uAh + APART;
        const uint32_t uB  = ub + (NPARTS - 1) * APART + (uint32_t)(wn * 64 * LDS_) * 2;
#pragma unroll
        for (int ks = 0; ks < 2; ++ks) {
            uint32_t ah[4][4], al[4][4], b[4][4];
#pragma unroll
            for (int mt = 0; mt < 4; ++mt) {
                const uint32_t ro = (uint32_t)((mt * 16 + (lane & 15)) * LDS_ +
                                               ks * 16 + (lane >> 4) * 8) * 2;
                ldsm4(ah[mt], uAh + ro);
                if (PASSES == 2) ldsm4(al[mt], uAl + ro);
            }
#pragma unroll
            for (int ng = 0; ng < 4; ++ng) {
                const uint32_t addr = uB +
                    (uint32_t)((ng * 16 + ((lane >> 4) & 1) * 8 + (lane & 7)) * LDS_ +
                               ks * 16 + ((lane >> 3) & 1) * 8) * 2;
                ldsm4(b[ng], addr);
            }
#pragma unroll
            for (int mt = 0; mt < 4; ++mt)
#pragma unroll
                for (int nt = 0; nt < 8; ++nt) {
                    const uint32_t b0 = b[nt >> 1][(nt & 1) * 2];
                    const uint32_t b1 = b[nt >> 1][(nt & 1) * 2 + 1];
                    mma16816(acc[mt][nt], ah[mt], b0, b1);
                    if (PASSES == 2) mma16816(acc[mt][nt], al[mt], b0, b1);
                }
        }
    }

    const int gr = lane >> 2, gc = (lane & 3) * 2;
#pragma unroll
    for (int mt = 0; mt < 4; ++mt) {
#pragma unroll
        for (int nt = 0; nt < 8; ++nt) {
#pragma unroll
            for (int e = 0; e < 4; ++e) {
                const int m = bm + wm * 64 + mt * 16 + gr + (e >> 1) * 8;
                const int n = bn + wn * 64 + nt * 8 + gc + (e & 1);
                const float v = acc[mt][nt][e];
                if (MODE == 0) {
                    const int s   = n / CH;
                    const int rem = n - s * CH;
                    const int h   = rem >> 6;
                    const int d   = rem & 63;
                    const int bb  = m / NT;
                    const int tt  = m - bb * NT;
                    const size_t idx = (((size_t)(bb * NH + h)) * NT + tt) * DH + d;
                    float* dst = (s == 0) ? g_q : (s == 1) ? g_k : g_v;
                    dst[idx] = v;
                } else {
                    if (n < N) C[(size_t)m * ldc + n] = v;
                }
            }
        }
    }
}

// ---------------- block reduce helper ----------------
__device__ __forceinline__ float2 block_reduce2(float s, float ss, float* shm)
{
#pragma unroll
    for (int o = 16; o; o >>= 1) {
        s  += __shfl_xor_sync(0xffffffffu, s,  o);
        ss += __shfl_xor_sync(0xffffffffu, ss, o);
    }
    const int w = threadIdx.x >> 5, lane = threadIdx.x & 31;
    if (lane == 0) { shm[w] = s; shm[8 + w] = ss; }
    __syncthreads();
    if (threadIdx.x < 32) {
        s  = (lane < 8) ? shm[lane]     : 0.f;
        ss = (lane < 8) ? shm[8 + lane] : 0.f;
#pragma unroll
        for (int o = 4; o; o >>= 1) {
            s  += __shfl_xor_sync(0xffffffffu, s,  o);
            ss += __shfl_xor_sync(0xffffffffu, ss, o);
        }
        if (lane == 0) { shm[0] = s; shm[1] = ss; }
    }
    __syncthreads();
    return make_float2(shm[0], shm[1]);
}

__global__ __launch_bounds__(256)
void ln_silu512(float* __restrict__ data, const float* __restrict__ g, const float* __restrict__ b)
{
    __shared__ float shm[16];
    const int row = blockIdx.x, tid = threadIdx.x;
    float* p = data + (size_t)row * 512;
    float x0 = p[tid], x1 = p[tid + 256];
    float2 r = block_reduce2(x0 + x1, x0 * x0 + x1 * x1, shm);
    const float mean = r.x * (1.f / 512.f);
    const float var  = r.y * (1.f / 512.f) - mean * mean;
    const float inv  = rsqrtf(var + 1e-5f);
    float y0 = (x0 - mean) * inv * g[tid]       + b[tid];
    float y1 = (x1 - mean) * inv * g[tid + 256] + b[tid + 256];
    p[tid]       = y0 / (1.f + __expf(-y0));
    p[tid + 256] = y1 / (1.f + __expf(-y1));
}

__global__ __launch_bounds__(256)
void ln3072(float* __restrict__ data, const float* __restrict__ g, const float* __restrict__ b)
{
    __shared__ float shm[16];
    const int row = blockIdx.x, tid = threadIdx.x;
    float* p = data + (size_t)row * 3072;
    float x[12];
    float s = 0.f, ss = 0.f;
#pragma unroll
    for (int i = 0; i < 12; i++) {
        x[i] = p[tid + i * 256];
        s += x[i]; ss += x[i] * x[i];
    }
    float2 r = block_reduce2(s, ss, shm);
    const float mean = r.x * (1.f / 3072.f);
    const float var  = r.y * (1.f / 3072.f) - mean * mean;
    const float inv  = rsqrtf(var + 1e-5f);
#pragma unroll
    for (int i = 0; i < 12; i++) {
        const int c = tid + i * 256;
        p[c] = (x[i] - mean) * inv * g[c] + b[c];
    }
}

// ---------------- fused attention with in-smem Q/K LayerNorm ----------------
#define ATTN_SMEM ((4160 + 4160 + 4225 + 2112) * 4)

__global__ __launch_bounds__(256)
void attn_kernel(const float* __restrict__ qn_g, const float* __restrict__ qn_b,
                 const float* __restrict__ kn_g, const float* __restrict__ kn_b)
{
    extern __shared__ float asmem[];
    float* sV = asmem;
    float* sQ = asmem + 4160;
    float* sK = asmem + 8320;
    float* sS = asmem + 12545;

    const int bh  = blockIdx.x;
    const int tid = threadIdx.x;
    const size_t base = (size_t)bh * (NT * DH);
    const int w = tid >> 5, lane = tid & 31;

    const float4* k4 = (const float4*)(g_k + base);
    const float4* v4 = (const float4*)(g_v + base);
    const float4* q4 = (const float4*)(g_q + base);
    for (int i = tid; i < NT * (DH / 4); i += 256) {
        ((float4*)sV)[i] = v4[i];
        ((float4*)sQ)[i] = q4[i];
        float4 kv = k4[i];
        const int r = i >> 4, c = (i & 15) << 2;
        float* d = sK + r * 65 + c;
        d[0] = kv.x; d[1] = kv.y; d[2] = kv.z; d[3] = kv.w;
    }
    __syncthreads();

    // ---- fused per-row LayerNorm on sQ (x 1/8) and sK ----
    {
        const float qg0 = qn_g[lane], qg1 = qn_g[lane + 32];
        const float qb0 = qn_b[lane], qb1 = qn_b[lane + 32];
        const float kg0 = kn_g[lane], kg1 = kn_g[lane + 32];
        const float kb0 = kn_b[lane], kb1 = kn_b[lane + 32];
        for (int r = w; r < 2 * NT; r += 8) {
            const bool isQ = (r < NT);
            float* row = isQ ? (sQ + r * DH) : (sK + (r - NT) * 65);
            float x0 = row[lane], x1 = row[lane + 32];
            float s = x0 + x1, ss = x0 * x0 + x1 * x1;
#pragma unroll
            for (int o = 16; o; o >>= 1) {
                s  += __shfl_xor_sync(0xffffffffu, s,  o);
                ss += __shfl_xor_sync(0xffffffffu, ss, o);
            }
            const float mean = s * (1.f / 64.f);
            const float var  = ss * (1.f / 64.f) - mean * mean;
            const float inv  = rsqrtf(var + 1e-5f);
            const float g0 = isQ ? qg0 : kg0, g1 = isQ ? qg1 : kg1;
            const float b0 = isQ ? qb0 : kb0, b1 = isQ ? qb1 : kb1;
            const float sc = isQ ? 0.125f : 1.f;
            row[lane]      = ((x0 - mean) * inv * g0 + b0) * sc;
            row[lane + 32] = ((x1 - mean) * inv * g1 + b1) * sc;
        }
    }
    __syncthreads();

    const float* bp = g_bias + (size_t)bh * (NT * NT);
    const int b = bh / NH, h = bh - b * NH;
    float* sSw = sS + w * 4 * 66;

    for (int i0 = w * 4; i0 < NT; i0 += 32) {
        int irr[4];
#pragma unroll
        for (int r = 0; r < 4; ++r) irr[r] = (i0 + r < NT) ? (i0 + r) : (NT - 1);

        float s64[4];
#pragma unroll
        for (int r = 0; r < 4; ++r) {
            float t = sQ[irr[r] * DH + lane]      * sK[64 * 65 + lane]
                    + sQ[irr[r] * DH + lane + 32] * sK[64 * 65 + lane + 32];
#pragma unroll
            for (int o = 16; o; o >>= 1) t += __shfl_xor_sync(0xffffffffu, t, o);
            s64[r] = t + bp[irr[r] * NT + 64];
        }

        float s0[4], s1[4];
#pragma unroll
        for (int r = 0; r < 4; ++r) {
            s0[r] = bp[irr[r] * NT + lane];
            s1[r] = bp[irr[r] * NT + lane + 32];
        }
#pragma unroll 4
        for (int d = 0; d < DH; ++d) {
            const float k0 = sK[lane * 65 + d];
            const float k1 = sK[(lane + 32) * 65 + d];
#pragma unroll
            for (int r = 0; r < 4; ++r) {
                const float qd = sQ[irr[r] * DH + d];
                s0[r] += qd * k0;
                s1[r] += qd * k1;
            }
        }

        float inv_[4];
#pragma unroll
        for (int r = 0; r < 4; ++r) {
            float mx = fmaxf(s0[r], s1[r]);
#pragma unroll
            for (int o = 16; o; o >>= 1) mx = fmaxf(mx, __shfl_xor_sync(0xffffffffu, mx, o));
            mx = fmaxf(mx, s64[r]);
            const float e0 = __expf(s0[r] - mx);
            const float e1 = __expf(s1[r] - mx);
            const float e2 = __expf(s64[r] - mx);
            float sum = e0 + e1;
#pragma unroll
            for (int o = 16; o; o >>= 1) sum += __shfl_xor_sync(0xffffffffu, sum, o);
            sum += e2;
            sSw[r * 66 + lane]      = e0;
            sSw[r * 66 + lane + 32] = e1;
            if (lane == 0) sSw[r * 66 + 64] = e2;
            inv_[r] = 1.f / sum;
        }
        __syncwarp();

        float a0[4] = {0.f, 0.f, 0.f, 0.f}, a1[4] = {0.f, 0.f, 0.f, 0.f};
        for (int m = 0; m < NT; ++m) {
            const float v0 = sV[m * DH + lane];
            const float v1 = sV[m * DH + lane + 32];
#pragma unroll
            for (int r = 0; r < 4; ++r) {
                const float p = sSw[r * 66 + m];
                a0[r] += p * v0;
                a1[r] += p * v1;
            }
        }
#pragma unroll
        for (int r = 0; r < 4; ++r) {
            const int i = i0 + r;
            if (i < NT) {
                __half* oh = g_attbf + ((size_t)(b * NT + i)) * CH + h * DH;
                oh[lane]      = __float2half(a0[r] * inv_[r]);
                oh[lane + 32] = __float2half(a1[r] * inv_[r]);
            }
        }
        __syncwarp();
    }
}

// ---------------- host launcher ----------------
extern "C" void kernel_launch(void* const* d_in, const int* in_sizes, int n_in,
                              void* d_out, int out_size)
{
    const float* x       = (const float*)d_in[0];
    const float* qkv_w   = (const float*)d_in[1];
    const float* proj_w  = (const float*)d_in[2];
    const float* qn_g    = (const float*)d_in[3];
    const float* qn_b    = (const float*)d_in[4];
    const float* kn_g    = (const float*)d_in[5];
    const float* kn_b    = (const float*)d_in[6];
    const float* sg_w1   = (const float*)d_in[7];
    const float* sg_ln1g = (const float*)d_in[8];
    const float* sg_ln1b = (const float*)d_in[9];
    const float* sg_w2   = (const float*)d_in[10];
    const float* sg_ln2g = (const float*)d_in[11];
    const float* sg_ln2b = (const float*)d_in[12];
    const float* sg_bw   = (const float*)d_in[13];
    float* out = (float*)d_out;

    float *p_lat1, *p_lat2, *p_bias;
    cudaGetSymbolAddress((void**)&p_lat1, g_lat1);
    cudaGetSymbolAddress((void**)&p_lat2, g_lat2);
    cudaGetSymbolAddress((void**)&p_bias, g_bias);
    __half *pxbf, *pattbf, *pwqkv, *pwproj, *pcls, *pw1, *pl1, *pw2, *pl2, *pwb;
    cudaGetSymbolAddress((void**)&pxbf,  g_xbf);
    cudaGetSymbolAddress((void**)&pattbf,g_attbf);
    cudaGetSymbolAddress((void**)&pwqkv, g_wqkv);
    cudaGetSymbolAddress((void**)&pwproj,g_wproj);
    cudaGetSymbolAddress((void**)&pcls,  g_clsbf);
    cudaGetSymbolAddress((void**)&pw1,   g_w1bf);
    cudaGetSymbolAddress((void**)&pl1,   g_l1bf);
    cudaGetSymbolAddress((void**)&pw2,   g_w2bf);
    cudaGetSymbolAddress((void**)&pl2,   g_l2bf);
    cudaGetSymbolAddress((void**)&pwb,   g_wbbf);

    const int SM2 = NSTG * 3 * (int)APART;   // 92160 (2-pass)
    const int SM1 = NSTG * 2 * (int)APART;   // 61440 (1-pass)
    cudaFuncSetAttribute(gemm_mma<0,2>, cudaFuncAttributeMaxDynamicSharedMemorySize, SM2);
    cudaFuncSetAttribute(gemm_mma<1,2>, cudaFuncAttributeMaxDynamicSharedMemorySize, SM2);
    cudaFuncSetAttribute(gemm_mma<1,1>, cudaFuncAttributeMaxDynamicSharedMemorySize, SM1);
    cudaFuncSetAttribute(attn_kernel, cudaFuncAttributeMaxDynamicSharedMemorySize, ATTN_SMEM);

    // side stream + events (created once, on the first — uncaptured — call)
    static cudaStream_t sB = nullptr;
    static cudaEvent_t evFork = nullptr, evJoin = nullptr;
    if (sB == nullptr) {
        cudaStreamCreateWithFlags(&sB, cudaStreamNonBlocking);
        cudaEventCreateWithFlags(&evFork, cudaEventDisableTiming);
        cudaEventCreateWithFlags(&evJoin, cudaEventDisableTiming);
    }

    // fork: bias-generator path runs concurrently on sB
    cudaEventRecord(evFork, 0);
    cudaStreamWaitEvent(sB, evFork, 0);

    // --- side stream: bias path + proj weight conversion ---
    conv_split<<<1024, 192, 0, sB>>>(x, NT * CH, pcls, CH, 1024);
    conv16<<<512, 192, 0, sB>>>(sg_w1, pw1, CH, 512);
    conv16<<<768, 192, 0, sB>>>(proj_w, pwproj, CH, 768);
    gemm_mma<1,2><<<dim3(4, 8), 128, SM2, sB>>>(pcls, 1536, pw1, 768, p_lat1, 512, 1024, 512, 768);
    ln_silu512<<<1024, 256, 0, sB>>>(p_lat1, sg_ln1g, sg_ln1b);
    conv_split<<<1024, 128, 0, sB>>>(p_lat1, 512, pl1, 512, 1024);
    conv16<<<3072, 128, 0, sB>>>(sg_w2, pw2, 512, 3072);
    gemm_mma<1,2><<<dim3(24, 8), 128, SM2, sB>>>(pl1, 1024, pw2, 512, p_lat2, 3072, 1024, 3072, 512);
    ln3072<<<1024, 256, 0, sB>>>(p_lat2, sg_ln2g, sg_ln2b);
    conv_split<<<12288, 64, 0, sB>>>(p_lat2, 256, pl2, 256, 12288);
    conv16<<<4352, 64, 0, sB>>>(sg_bw, pwb, 256, 4225);
    gemm_mma<1,2><<<dim3(34, 96), 128, SM2, sB>>>(pl2, 512, pwb, 256, p_bias, 4225, 12288, 4225, 256);
    cudaEventRecord(evJoin, sB);

    // --- main stream: qkv path ---
    conv_split<<<66560, 192>>>(x, CH, pxbf, CH, 66560);
    conv16<<<2304, 192>>>(qkv_w, pwqkv, CH, 2304);
    gemm_mma<0,2><<<dim3(18, 520), 128, SM2>>>(pxbf, 1536, pwqkv, 768, nullptr, 0, 66560, 2304, 768);

    // join: attention needs q/k/v AND bias
    cudaStreamWaitEvent(0, evJoin, 0);
    attn_kernel<<<NBATCH * NH, 256, ATTN_SMEM>>>(qn_g, qn_b, kn_g, kn_b);

    // --- output projection: single-pass fp16 A ---
    gemm_mma<1,1><<<dim3(6, 520), 128, SM1>>>(pattbf, 768, pwproj, 768, out, 768, 66560, 768, 768);
}

// round 10
// speedup vs baseline: 5.0730x; 1.2244x over previous
#include <cuda_runtime.h>
#include <cuda_fp16.h>
#include <cstdint>

// ---------------- problem constants ----------------
#define NBATCH 1024
#define NT     65
#define CH     768
#define NH     12
#define DH     64

// ---------------- fp32 scratch ----------------
__device__ __align__(16) float g_q[51118080];     // [B,H,NT,DH] (pre-LN)
__device__ __align__(16) float g_k[51118080];     // (pre-LN)
__device__ __align__(16) float g_v[51118080];
__device__ __align__(16) float g_bias[51916800];  // [B*H,65*65]
__device__ __align__(16) float g_lat1[524288];    // [1024,512]
__device__ __align__(16) float g_lat2[3145728];   // [1024,3072]

// ---------------- fp16 scratch ----------------
__device__ __align__(16) __half g_xbf[51118080];    // 66560 x 768 (plain fp16)
__device__ __align__(16) __half g_attbf[51118080];  // 66560 x 768 (plain fp16, by attn)
__device__ __align__(16) __half g_clsbf[1572864];   // 1024 x 1536 [hi|lo]
__device__ __align__(16) __half g_l1bf[1048576];    // 1024 x 1024 [hi|lo]
__device__ __align__(16) __half g_l2bf[6291456];    // 12288 x 512 [hi|lo]
__device__ __align__(16) __half g_wqkv[1769472];    // 2304 x 768
__device__ __align__(16) __half g_wproj[589824];    // 768 x 768
__device__ __align__(16) __half g_w1bf[393216];     // 512 x 768
__device__ __align__(16) __half g_w2bf[1572864];    // 3072 x 512
__device__ __align__(16) __half g_wbbf[1114112];    // 4352 x 256 (rows >= 4225 zero)

// ---------------- helpers ----------------
__device__ __forceinline__ uint32_t s2u(const void* p) {
    uint32_t a;
    asm("{ .reg .u64 t; cvta.to.shared.u64 t, %1; cvt.u32.u64 %0, t; }" : "=r"(a) : "l"(p));
    return a;
}
__device__ __forceinline__ void ldsm4(uint32_t* r, uint32_t addr) {
    asm volatile("ldmatrix.sync.aligned.m8n8.x4.shared.b16 {%0,%1,%2,%3}, [%4];"
        : "=r"(r[0]), "=r"(r[1]), "=r"(r[2]), "=r"(r[3]) : "r"(addr));
}
__device__ __forceinline__ void mma16816(float* d, const uint32_t* a, uint32_t b0, uint32_t b1) {
    asm volatile(
        "mma.sync.aligned.m16n8k16.row.col.f32.f16.f16.f32 "
        "{%0,%1,%2,%3}, {%4,%5,%6,%7}, {%8,%9}, {%0,%1,%2,%3};"
        : "+f"(d[0]), "+f"(d[1]), "+f"(d[2]), "+f"(d[3])
        : "r"(a[0]), "r"(a[1]), "r"(a[2]), "r"(a[3]), "r"(b0), "r"(b1));
}

// ---------------- fp32 -> fp16 hi|lo split (A-side, 2-pass GEMMs) ----------------
__global__ void conv_split(const float* __restrict__ src, int lds,
                           __half* __restrict__ dst, int K, int rowsValid)
{
    const int r = blockIdx.x;
    const float4* s = (const float4*)(src + (size_t)r * lds);
    __half2* dh = (__half2*)(dst + (size_t)r * 2 * K);
    __half2* dl = (__half2*)(dst + (size_t)r * 2 * K + K);
    const bool valid = r < rowsValid;
    for (int c = threadIdx.x; c < K / 4; c += blockDim.x) {
        float4 v = valid ? s[c] : make_float4(0.f, 0.f, 0.f, 0.f);
        __half hx = __float2half(v.x), hy = __float2half(v.y);
        __half hz = __float2half(v.z), hw = __float2half(v.w);
        dh[c * 2]     = __half2(hx, hy);
        dh[c * 2 + 1] = __half2(hz, hw);
        dl[c * 2]     = __half2(__float2half(v.x - __half2float(hx)),
                                __float2half(v.y - __half2float(hy)));
        dl[c * 2 + 1] = __half2(__float2half(v.z - __half2float(hz)),
                                __float2half(v.w - __half2float(hw)));
    }
}

// ---------------- fp32 -> fp16 plain (with row stride for gathers) ----------------
__global__ void conv16(const float* __restrict__ src, int lds,
                       __half* __restrict__ dst, int K, int rowsValid)
{
    const int r = blockIdx.x;
    const float4* s = (const float4*)(src + (size_t)r * lds);
    __half2* d = (__half2*)(dst + (size_t)r * K);
    const bool valid = r < rowsValid;
    for (int c = threadIdx.x; c < K / 4; c += blockDim.x) {
        float4 v = valid ? s[c] : make_float4(0.f, 0.f, 0.f, 0.f);
        d[c * 2]     = __half2(__float2half(v.x), __float2half(v.y));
        d[c * 2 + 1] = __half2(__float2half(v.z), __float2half(v.w));
    }
}

// ---------------- fp16 split GEMM: C = A @ B^T ----------------
// PASSES=2: A is M x 2K [hi|lo], C=(Ah+Al)@B.  PASSES=1: A is M x K plain fp16.
#define KC    32
#define LDS_  40                       // padded fp16 row stride (80B)
#define APART 10240u
#define NSTG  3

template<int MODE, int PASSES>
__global__ __launch_bounds__(128, 2)
void gemm_mma(const __half* __restrict__ A, int lda,
              const __half* __restrict__ B, int ldb,
              float* __restrict__ C, int ldc, int M, int N, int K)
{
    constexpr int NPARTS = PASSES + 1;              // A parts + B
    constexpr uint32_t STGB = NPARTS * APART;

    extern __shared__ char dynsm[];
    const uint32_t sbase = s2u(dynsm);

    const int tid = threadIdx.x, wid = tid >> 5, lane = tid & 31;
    const int wm = wid & 1, wn = wid >> 1;            // 2 x 2 warp grid
    const int bm = blockIdx.y * 128, bn = blockIdx.x * 128;
    const int nk = K / KC;

    float acc[4][8][4];
#pragma unroll
    for (int i = 0; i < 4; i++)
#pragma unroll
        for (int j = 0; j < 8; j++)
#pragma unroll
            for (int e = 0; e < 4; e++) acc[i][j][e] = 0.f;

    auto loads = [&](int t) {
        const uint32_t ub = sbase + (uint32_t)(t % NSTG) * STGB;
        const int kOff = t * KC;
#pragma unroll
        for (int i = 0; i < 4 * NPARTS; i++) {
            const int idx = tid + i * 128;
            const int part = idx >> 9;             // 0..PASSES-1: A parts, last: B
            const int id2 = idx & 511;
            const int r = id2 >> 2, cc = id2 & 3;
            const uint32_t dst = ub + (uint32_t)part * APART +
                                 (uint32_t)(r * LDS_ + cc * 8) * 2;
            const void* g = (part == NPARTS - 1)
                ? (const void*)(B + (size_t)(bn + r) * ldb + kOff + cc * 8)
                : (const void*)(A + (size_t)(bm + r) * lda + part * K + kOff + cc * 8);
            asm volatile("cp.async.cg.shared.global [%0], [%1], 16;" :: "r"(dst), "l"(g));
        }
        asm volatile("cp.async.commit_group;");
    };

    loads(0);
    if (nk > 1) loads(1);

    for (int t = 0; t < nk; ++t) {
        if (t + 1 < nk) asm volatile("cp.async.wait_group 1;");
        else            asm volatile("cp.async.wait_group 0;");
        __syncthreads();
        if (t + 2 < nk) loads(t + 2);

        const uint32_t ub  = sbase + (uint32_t)(t % NSTG) * STGB;
        const uint32_t uAh = ub + (uint32_t)(wm * 64 * LDS_) * 2;
        const uint32_t uAl = uAh + APART;
        const uint32_t uB  = ub + (NPARTS - 1) * APART + (uint32_t)(wn * 64 * LDS_) * 2;
#pragma unroll
        for (int ks = 0; ks < 2; ++ks) {
            uint32_t ah[4][4], al[4][4], b[4][4];
#pragma unroll
            for (int mt = 0; mt < 4; ++mt) {
                const uint32_t ro = (uint32_t)((mt * 16 + (lane & 15)) * LDS_ +
                                               ks * 16 + (lane >> 4) * 8) * 2;
                ldsm4(ah[mt], uAh + ro);
                if (PASSES == 2) ldsm4(al[mt], uAl + ro);
            }
#pragma unroll
            for (int ng = 0; ng < 4; ++ng) {
                const uint32_t addr = uB +
                    (uint32_t)((ng * 16 + ((lane >> 4) & 1) * 8 + (lane & 7)) * LDS_ +
                               ks * 16 + ((lane >> 3) & 1) * 8) * 2;
                ldsm4(b[ng], addr);
            }
#pragma unroll
            for (int mt = 0; mt < 4; ++mt)
#pragma unroll
                for (int nt = 0; nt < 8; ++nt) {
                    const uint32_t b0 = b[nt >> 1][(nt & 1) * 2];
                    const uint32_t b1 = b[nt >> 1][(nt & 1) * 2 + 1];
                    mma16816(acc[mt][nt], ah[mt], b0, b1);
                    if (PASSES == 2) mma16816(acc[mt][nt], al[mt], b0, b1);
                }
        }
    }

    const int gr = lane >> 2, gc = (lane & 3) * 2;
#pragma unroll
    for (int mt = 0; mt < 4; ++mt) {
#pragma unroll
        for (int nt = 0; nt < 8; ++nt) {
#pragma unroll
            for (int e = 0; e < 4; ++e) {
                const int m = bm + wm * 64 + mt * 16 + gr + (e >> 1) * 8;
                const int n = bn + wn * 64 + nt * 8 + gc + (e & 1);
                const float v = acc[mt][nt][e];
                if (MODE == 0) {
                    const int s   = n / CH;
                    const int rem = n - s * CH;
                    const int h   = rem >> 6;
                    const int d   = rem & 63;
                    const int bb  = m / NT;
                    const int tt  = m - bb * NT;
                    const size_t idx = (((size_t)(bb * NH + h)) * NT + tt) * DH + d;
                    float* dst = (s == 0) ? g_q : (s == 1) ? g_k : g_v;
                    dst[idx] = v;
                } else {
                    if (n < N) C[(size_t)m * ldc + n] = v;
                }
            }
        }
    }
}

// ---------------- block reduce helper ----------------
__device__ __forceinline__ float2 block_reduce2(float s, float ss, float* shm)
{
#pragma unroll
    for (int o = 16; o; o >>= 1) {
        s  += __shfl_xor_sync(0xffffffffu, s,  o);
        ss += __shfl_xor_sync(0xffffffffu, ss, o);
    }
    const int w = threadIdx.x >> 5, lane = threadIdx.x & 31;
    if (lane == 0) { shm[w] = s; shm[8 + w] = ss; }
    __syncthreads();
    if (threadIdx.x < 32) {
        s  = (lane < 8) ? shm[lane]     : 0.f;
        ss = (lane < 8) ? shm[8 + lane] : 0.f;
#pragma unroll
        for (int o = 4; o; o >>= 1) {
            s  += __shfl_xor_sync(0xffffffffu, s,  o);
            ss += __shfl_xor_sync(0xffffffffu, ss, o);
        }
        if (lane == 0) { shm[0] = s; shm[1] = ss; }
    }
    __syncthreads();
    return make_float2(shm[0], shm[1]);
}

__global__ __launch_bounds__(256)
void ln_silu512(float* __restrict__ data, const float* __restrict__ g, const float* __restrict__ b)
{
    __shared__ float shm[16];
    const int row = blockIdx.x, tid = threadIdx.x;
    float* p = data + (size_t)row * 512;
    float x0 = p[tid], x1 = p[tid + 256];
    float2 r = block_reduce2(x0 + x1, x0 * x0 + x1 * x1, shm);
    const float mean = r.x * (1.f / 512.f);
    const float var  = r.y * (1.f / 512.f) - mean * mean;
    const float inv  = rsqrtf(var + 1e-5f);
    float y0 = (x0 - mean) * inv * g[tid]       + b[tid];
    float y1 = (x1 - mean) * inv * g[tid + 256] + b[tid + 256];
    p[tid]       = y0 / (1.f + __expf(-y0));
    p[tid + 256] = y1 / (1.f + __expf(-y1));
}

__global__ __launch_bounds__(256)
void ln3072(float* __restrict__ data, const float* __restrict__ g, const float* __restrict__ b)
{
    __shared__ float shm[16];
    const int row = blockIdx.x, tid = threadIdx.x;
    float* p = data + (size_t)row * 3072;
    float x[12];
    float s = 0.f, ss = 0.f;
#pragma unroll
    for (int i = 0; i < 12; i++) {
        x[i] = p[tid + i * 256];
        s += x[i]; ss += x[i] * x[i];
    }
    float2 r = block_reduce2(s, ss, shm);
    const float mean = r.x * (1.f / 3072.f);
    const float var  = r.y * (1.f / 3072.f) - mean * mean;
    const float inv  = rsqrtf(var + 1e-5f);
#pragma unroll
    for (int i = 0; i < 12; i++) {
        const int c = tid + i * 256;
        p[c] = (x[i] - mean) * inv * g[c] + b[c];
    }
}

// ---------------- fused attention with in-smem Q/K LayerNorm ----------------
#define ATTN_SMEM ((4160 + 4160 + 4225 + 2112) * 4)

__global__ __launch_bounds__(256)
void attn_kernel(const float* __restrict__ qn_g, const float* __restrict__ qn_b,
                 const float* __restrict__ kn_g, const float* __restrict__ kn_b)
{
    extern __shared__ float asmem[];
    float* sV = asmem;
    float* sQ = asmem + 4160;
    float* sK = asmem + 8320;
    float* sS = asmem + 12545;

    const int bh  = blockIdx.x;
    const int tid = threadIdx.x;
    const size_t base = (size_t)bh * (NT * DH);
    const int w = tid >> 5, lane = tid & 31;

    const float4* k4 = (const float4*)(g_k + base);
    const float4* v4 = (const float4*)(g_v + base);
    const float4* q4 = (const float4*)(g_q + base);
    for (int i = tid; i < NT * (DH / 4); i += 256) {
        ((float4*)sV)[i] = v4[i];
        ((float4*)sQ)[i] = q4[i];
        float4 kv = k4[i];
        const int r = i >> 4, c = (i & 15) << 2;
        float* d = sK + r * 65 + c;
        d[0] = kv.x; d[1] = kv.y; d[2] = kv.z; d[3] = kv.w;
    }
    __syncthreads();

    // ---- fused per-row LayerNorm on sQ (x 1/8) and sK ----
    {
        const float qg0 = qn_g[lane], qg1 = qn_g[lane + 32];
        const float qb0 = qn_b[lane], qb1 = qn_b[lane + 32];
        const float kg0 = kn_g[lane], kg1 = kn_g[lane + 32];
        const float kb0 = kn_b[lane], kb1 = kn_b[lane + 32];
        for (int r = w; r < 2 * NT; r += 8) {
            const bool isQ = (r < NT);
            float* row = isQ ? (sQ + r * DH) : (sK + (r - NT) * 65);
            float x0 = row[lane], x1 = row[lane + 32];
            float s = x0 + x1, ss = x0 * x0 + x1 * x1;
#pragma unroll
            for (int o = 16; o; o >>= 1) {
                s  += __shfl_xor_sync(0xffffffffu, s,  o);
                ss += __shfl_xor_sync(0xffffffffu, ss, o);
            }
            const float mean = s * (1.f / 64.f);
            const float var  = ss * (1.f / 64.f) - mean * mean;
            const float inv  = rsqrtf(var + 1e-5f);
            const float g0 = isQ ? qg0 : kg0, g1 = isQ ? qg1 : kg1;
            const float b0 = isQ ? qb0 : kb0, b1 = isQ ? qb1 : kb1;
            const float sc = isQ ? 0.125f : 1.f;
            row[lane]      = ((x0 - mean) * inv * g0 + b0) * sc;
            row[lane + 32] = ((x1 - mean) * inv * g1 + b1) * sc;
        }
    }
    __syncthreads();

    const float* bp = g_bias + (size_t)bh * (NT * NT);
    const int b = bh / NH, h = bh - b * NH;
    float* sSw = sS + w * 4 * 66;

    for (int i0 = w * 4; i0 < NT; i0 += 32) {
        int irr[4];
#pragma unroll
        for (int r = 0; r < 4; ++r) irr[r] = (i0 + r < NT) ? (i0 + r) : (NT - 1);

        float s64[4];
#pragma unroll
        for (int r = 0; r < 4; ++r) {
            float t = sQ[irr[r] * DH + lane]      * sK[64 * 65 + lane]
                    + sQ[irr[r] * DH + lane + 32] * sK[64 * 65 + lane + 32];
#pragma unroll
            for (int o = 16; o; o >>= 1) t += __shfl_xor_sync(0xffffffffu, t, o);
            s64[r] = t + bp[irr[r] * NT + 64];
        }

        float s0[4], s1[4];
#pragma unroll
        for (int r = 0; r < 4; ++r) {
            s0[r] = bp[irr[r] * NT + lane];
            s1[r] = bp[irr[r] * NT + lane + 32];
        }
#pragma unroll 4
        for (int d = 0; d < DH; ++d) {
            const float k0 = sK[lane * 65 + d];
            const float k1 = sK[(lane + 32) * 65 + d];
#pragma unroll
            for (int r = 0; r < 4; ++r) {
                const float qd = sQ[irr[r] * DH + d];
                s0[r] += qd * k0;
                s1[r] += qd * k1;
            }
        }

        float inv_[4];
#pragma unroll
        for (int r = 0; r < 4; ++r) {
            float mx = fmaxf(s0[r], s1[r]);
#pragma unroll
            for (int o = 16; o; o >>= 1) mx = fmaxf(mx, __shfl_xor_sync(0xffffffffu, mx, o));
            mx = fmaxf(mx, s64[r]);
            const float e0 = __expf(s0[r] - mx);
            const float e1 = __expf(s1[r] - mx);
            const float e2 = __expf(s64[r] - mx);
            float sum = e0 + e1;
#pragma unroll
            for (int o = 16; o; o >>= 1) sum += __shfl_xor_sync(0xffffffffu, sum, o);
            sum += e2;
            sSw[r * 66 + lane]      = e0;
            sSw[r * 66 + lane + 32] = e1;
            if (lane == 0) sSw[r * 66 + 64] = e2;
            inv_[r] = 1.f / sum;
        }
        __syncwarp();

        float a0[4] = {0.f, 0.f, 0.f, 0.f}, a1[4] = {0.f, 0.f, 0.f, 0.f};
        for (int m = 0; m < NT; ++m) {
            const float v0 = sV[m * DH + lane];
            const float v1 = sV[m * DH + lane + 32];
#pragma unroll
            for (int r = 0; r < 4; ++r) {
                const float p = sSw[r * 66 + m];
                a0[r] += p * v0;
                a1[r] += p * v1;
            }
        }
#pragma unroll
        for (int r = 0; r < 4; ++r) {
            const int i = i0 + r;
            if (i < NT) {
                __half* oh = g_attbf + ((size_t)(b * NT + i)) * CH + h * DH;
                oh[lane]      = __float2half(a0[r] * inv_[r]);
                oh[lane + 32] = __float2half(a1[r] * inv_[r]);
            }
        }
        __syncwarp();
    }
}

// ---------------- host launcher ----------------
extern "C" void kernel_launch(void* const* d_in, const int* in_sizes, int n_in,
                              void* d_out, int out_size)
{
    const float* x       = (const float*)d_in[0];
    const float* qkv_w   = (const float*)d_in[1];
    const float* proj_w  = (const float*)d_in[2];
    const float* qn_g    = (const float*)d_in[3];
    const float* qn_b    = (const float*)d_in[4];
    const float* kn_g    = (const float*)d_in[5];
    const float* kn_b    = (const float*)d_in[6];
    const float* sg_w1   = (const float*)d_in[7];
    const float* sg_ln1g = (const float*)d_in[8];
    const float* sg_ln1b = (const float*)d_in[9];
    const float* sg_w2   = (const float*)d_in[10];
    const float* sg_ln2g = (const float*)d_in[11];
    const float* sg_ln2b = (const float*)d_in[12];
    const float* sg_bw   = (const float*)d_in[13];
    float* out = (float*)d_out;

    float *p_lat1, *p_lat2, *p_bias;
    cudaGetSymbolAddress((void**)&p_lat1, g_lat1);
    cudaGetSymbolAddress((void**)&p_lat2, g_lat2);
    cudaGetSymbolAddress((void**)&p_bias, g_bias);
    __half *pxbf, *pattbf, *pwqkv, *pwproj, *pcls, *pw1, *pl1, *pw2, *pl2, *pwb;
    cudaGetSymbolAddress((void**)&pxbf,  g_xbf);
    cudaGetSymbolAddress((void**)&pattbf,g_attbf);
    cudaGetSymbolAddress((void**)&pwqkv, g_wqkv);
    cudaGetSymbolAddress((void**)&pwproj,g_wproj);
    cudaGetSymbolAddress((void**)&pcls,  g_clsbf);
    cudaGetSymbolAddress((void**)&pw1,   g_w1bf);
    cudaGetSymbolAddress((void**)&pl1,   g_l1bf);
    cudaGetSymbolAddress((void**)&pw2,   g_w2bf);
    cudaGetSymbolAddress((void**)&pl2,   g_l2bf);
    cudaGetSymbolAddress((void**)&pwb,   g_wbbf);

    const int SM2 = NSTG * 3 * (int)APART;   // 92160 (2-pass)
    const int SM1 = NSTG * 2 * (int)APART;   // 61440 (1-pass)
    cudaFuncSetAttribute(gemm_mma<0,1>, cudaFuncAttributeMaxDynamicSharedMemorySize, SM1);
    cudaFuncSetAttribute(gemm_mma<1,2>, cudaFuncAttributeMaxDynamicSharedMemorySize, SM2);
    cudaFuncSetAttribute(gemm_mma<1,1>, cudaFuncAttributeMaxDynamicSharedMemorySize, SM1);
    cudaFuncSetAttribute(attn_kernel, cudaFuncAttributeMaxDynamicSharedMemorySize, ATTN_SMEM);

    // side stream + events (created once, on the first — uncaptured — call)
    static cudaStream_t sB = nullptr;
    static cudaEvent_t evFork = nullptr, evJoin = nullptr;
    if (sB == nullptr) {
        cudaStreamCreateWithFlags(&sB, cudaStreamNonBlocking);
        cudaEventCreateWithFlags(&evFork, cudaEventDisableTiming);
        cudaEventCreateWithFlags(&evJoin, cudaEventDisableTiming);
    }

    // fork: bias-generator path runs concurrently on sB
    cudaEventRecord(evFork, 0);
    cudaStreamWaitEvent(sB, evFork, 0);

    // --- side stream: bias path + proj weight conversion ---
    conv_split<<<1024, 192, 0, sB>>>(x, NT * CH, pcls, CH, 1024);
    conv16<<<512, 192, 0, sB>>>(sg_w1, CH, pw1, CH, 512);
    conv16<<<768, 192, 0, sB>>>(proj_w, CH, pwproj, CH, 768);
    gemm_mma<1,2><<<dim3(4, 8), 128, SM2, sB>>>(pcls, 1536, pw1, 768, p_lat1, 512, 1024, 512, 768);
    ln_silu512<<<1024, 256, 0, sB>>>(p_lat1, sg_ln1g, sg_ln1b);
    conv_split<<<1024, 128, 0, sB>>>(p_lat1, 512, pl1, 512, 1024);
    conv16<<<3072, 128, 0, sB>>>(sg_w2, 512, pw2, 512, 3072);
    gemm_mma<1,2><<<dim3(24, 8), 128, SM2, sB>>>(pl1, 1024, pw2, 512, p_lat2, 3072, 1024, 3072, 512);
    ln3072<<<1024, 256, 0, sB>>>(p_lat2, sg_ln2g, sg_ln2b);
    conv_split<<<12288, 64, 0, sB>>>(p_lat2, 256, pl2, 256, 12288);
    conv16<<<4352, 64, 0, sB>>>(sg_bw, 256, pwb, 256, 4225);
    gemm_mma<1,2><<<dim3(34, 96), 128, SM2, sB>>>(pl2, 512, pwb, 256, p_bias, 4225, 12288, 4225, 256);
    cudaEventRecord(evJoin, sB);

    // --- main stream: qkv path (single-pass fp16) ---
    conv16<<<66560, 192>>>(x, CH, pxbf, CH, 66560);
    conv16<<<2304, 192>>>(qkv_w, CH, pwqkv, CH, 2304);
    gemm_mma<0,1><<<dim3(18, 520), 128, SM1>>>(pxbf, 768, pwqkv, 768, nullptr, 0, 66560, 2304, 768);

    // join: attention needs q/k/v AND bias
    cudaStreamWaitEvent(0, evJoin, 0);
    attn_kernel<<<NBATCH * NH, 256, ATTN_SMEM>>>(qn_g, qn_b, kn_g, kn_b);

    // --- output projection: single-pass fp16 A ---
    gemm_mma<1,1><<<dim3(6, 520), 128, SM1>>>(pattbf, 768, pwproj, 768, out, 768, 66560, 768, 768);
}

// round 11
// speedup vs baseline: 5.2074x; 1.0265x over previous
#include <cuda_runtime.h>
#include <cuda_fp16.h>
#include <cstdint>

// ---------------- problem constants ----------------
#define NBATCH 1024
#define NT     65
#define CH     768
#define NH     12
#define DH     64

// ---------------- fp32 scratch ----------------
__device__ __align__(16) float g_q[51118080];     // [B,H,NT,DH] (pre-LN)
__device__ __align__(16) float g_k[51118080];     // (pre-LN)
__device__ __align__(16) float g_v[51118080];
__device__ __align__(16) float g_bias[51916800];  // [B*H,65*65]
__device__ __align__(16) float g_lat1[524288];    // [1024,512]
__device__ __align__(16) float g_lat2[3145728];   // [1024,3072]

// ---------------- fp16 scratch ----------------
__device__ __align__(16) __half g_xbf[51118080];    // 66560 x 768 (plain fp16)
__device__ __align__(16) __half g_attbf[51118080];  // 66560 x 768 (plain fp16, by attn)
__device__ __align__(16) __half g_clsbf[1572864];   // 1024 x 1536 [hi|lo]
__device__ __align__(16) __half g_l1bf[1048576];    // 1024 x 1024 [hi|lo]
__device__ __align__(16) __half g_l2bf[6291456];    // 12288 x 512 [hi|lo]
__device__ __align__(16) __half g_wqkv[1769472];    // 2304 x 768
__device__ __align__(16) __half g_wproj[589824];    // 768 x 768
__device__ __align__(16) __half g_w1bf[393216];     // 512 x 768
__device__ __align__(16) __half g_w2bf[1572864];    // 3072 x 512
__device__ __align__(16) __half g_wbbf[1114112];    // 4352 x 256 (rows >= 4225 zero)

// ---------------- helpers ----------------
__device__ __forceinline__ uint32_t s2u(const void* p) {
    uint32_t a;
    asm("{ .reg .u64 t; cvta.to.shared.u64 t, %1; cvt.u32.u64 %0, t; }" : "=r"(a) : "l"(p));
    return a;
}
__device__ __forceinline__ void ldsm4(uint32_t* r, uint32_t addr) {
    asm volatile("ldmatrix.sync.aligned.m8n8.x4.shared.b16 {%0,%1,%2,%3}, [%4];"
        : "=r"(r[0]), "=r"(r[1]), "=r"(r[2]), "=r"(r[3]) : "r"(addr));
}
__device__ __forceinline__ void mma16816(float* d, const uint32_t* a, uint32_t b0, uint32_t b1) {
    asm volatile(
        "mma.sync.aligned.m16n8k16.row.col.f32.f16.f16.f32 "
        "{%0,%1,%2,%3}, {%4,%5,%6,%7}, {%8,%9}, {%0,%1,%2,%3};"
        : "+f"(d[0]), "+f"(d[1]), "+f"(d[2]), "+f"(d[3])
        : "r"(a[0]), "r"(a[1]), "r"(a[2]), "r"(a[3]), "r"(b0), "r"(b1));
}

// ---------------- fp32 -> fp16 hi|lo split (A-side, 2-pass GEMMs) ----------------
__global__ void conv_split(const float* __restrict__ src, int lds,
                           __half* __restrict__ dst, int K, int rowsValid)
{
    const int r = blockIdx.x;
    const float4* s = (const float4*)(src + (size_t)r * lds);
    __half2* dh = (__half2*)(dst + (size_t)r * 2 * K);
    __half2* dl = (__half2*)(dst + (size_t)r * 2 * K + K);
    const bool valid = r < rowsValid;
    for (int c = threadIdx.x; c < K / 4; c += blockDim.x) {
        float4 v = valid ? s[c] : make_float4(0.f, 0.f, 0.f, 0.f);
        __half hx = __float2half(v.x), hy = __float2half(v.y);
        __half hz = __float2half(v.z), hw = __float2half(v.w);
        dh[c * 2]     = __half2(hx, hy);
        dh[c * 2 + 1] = __half2(hz, hw);
        dl[c * 2]     = __half2(__float2half(v.x - __half2float(hx)),
                                __float2half(v.y - __half2float(hy)));
        dl[c * 2 + 1] = __half2(__float2half(v.z - __half2float(hz)),
                                __float2half(v.w - __half2float(hw)));
    }
}

// ---------------- fp32 -> fp16 plain ----------------
__global__ void conv16(const float* __restrict__ src, int lds,
                       __half* __restrict__ dst, int K, int rowsValid)
{
    const int r = blockIdx.x;
    const float4* s = (const float4*)(src + (size_t)r * lds);
    __half2* d = (__half2*)(dst + (size_t)r * K);
    const bool valid = r < rowsValid;
    for (int c = threadIdx.x; c < K / 4; c += blockDim.x) {
        float4 v = valid ? s[c] : make_float4(0.f, 0.f, 0.f, 0.f);
        d[c * 2]     = __half2(__float2half(v.x), __float2half(v.y));
        d[c * 2 + 1] = __half2(__float2half(v.z), __float2half(v.w));
    }
}

// ---------------- fp16 split GEMM: C = A @ B^T ----------------
#define KC    32
#define LDS_  40
#define APART 10240u
#define NSTG  3

template<int MODE, int PASSES>
__global__ __launch_bounds__(128, 2)
void gemm_mma(const __half* __restrict__ A, int lda,
              const __half* __restrict__ B, int ldb,
              float* __restrict__ C, int ldc, int M, int N, int K)
{
    constexpr int NPARTS = PASSES + 1;
    constexpr uint32_t STGB = NPARTS * APART;

    extern __shared__ char dynsm[];
    const uint32_t sbase = s2u(dynsm);

    const int tid = threadIdx.x, wid = tid >> 5, lane = tid & 31;
    const int wm = wid & 1, wn = wid >> 1;
    const int bm = blockIdx.y * 128, bn = blockIdx.x * 128;
    const int nk = K / KC;

    float acc[4][8][4];
#pragma unroll
    for (int i = 0; i < 4; i++)
#pragma unroll
        for (int j = 0; j < 8; j++)
#pragma unroll
            for (int e = 0; e < 4; e++) acc[i][j][e] = 0.f;

    auto loads = [&](int t) {
        const uint32_t ub = sbase + (uint32_t)(t % NSTG) * STGB;
        const int kOff = t * KC;
#pragma unroll
        for (int i = 0; i < 4 * NPARTS; i++) {
            const int idx = tid + i * 128;
            const int part = idx >> 9;
            const int id2 = idx & 511;
            const int r = id2 >> 2, cc = id2 & 3;
            const uint32_t dst = ub + (uint32_t)part * APART +
                                 (uint32_t)(r * LDS_ + cc * 8) * 2;
            const void* g = (part == NPARTS - 1)
                ? (const void*)(B + (size_t)(bn + r) * ldb + kOff + cc * 8)
                : (const void*)(A + (size_t)(bm + r) * lda + part * K + kOff + cc * 8);
            asm volatile("cp.async.cg.shared.global [%0], [%1], 16;" :: "r"(dst), "l"(g));
        }
        asm volatile("cp.async.commit_group;");
    };

    loads(0);
    if (nk > 1) loads(1);

    for (int t = 0; t < nk; ++t) {
        if (t + 1 < nk) asm volatile("cp.async.wait_group 1;");
        else            asm volatile("cp.async.wait_group 0;");
        __syncthreads();
        if (t + 2 < nk) loads(t + 2);

        const uint32_t ub  = sbase + (uint32_t)(t % NSTG) * STGB;
        const uint32_t uAh = ub + (uint32_t)(wm * 64 * LDS_) * 2;
        const uint32_t uAl = uAh + APART;
        const uint32_t uB  = ub + (NPARTS - 1) * APART + (uint32_t)(wn * 64 * LDS_) * 2;
#pragma unroll
        for (int ks = 0; ks < 2; ++ks) {
            uint32_t ah[4][4], al[4][4], b[4][4];
#pragma unroll
            for (int mt = 0; mt < 4; ++mt) {
                const uint32_t ro = (uint32_t)((mt * 16 + (lane & 15)) * LDS_ +
                                               ks * 16 + (lane >> 4) * 8) * 2;
                ldsm4(ah[mt], uAh + ro);
                if (PASSES == 2) ldsm4(al[mt], uAl + ro);
            }
#pragma unroll
            for (int ng = 0; ng < 4; ++ng) {
                const uint32_t addr = uB +
                    (uint32_t)((ng * 16 + ((lane >> 4) & 1) * 8 + (lane & 7)) * LDS_ +
                               ks * 16 + ((lane >> 3) & 1) * 8) * 2;
                ldsm4(b[ng], addr);
            }
#pragma unroll
            for (int mt = 0; mt < 4; ++mt)
#pragma unroll
                for (int nt = 0; nt < 8; ++nt) {
                    const uint32_t b0 = b[nt >> 1][(nt & 1) * 2];
                    const uint32_t b1 = b[nt >> 1][(nt & 1) * 2 + 1];
                    mma16816(acc[mt][nt], ah[mt], b0, b1);
                    if (PASSES == 2) mma16816(acc[mt][nt], al[mt], b0, b1);
                }
        }
    }

    const int gr = lane >> 2, gc = (lane & 3) * 2;
#pragma unroll
    for (int mt = 0; mt < 4; ++mt) {
#pragma unroll
        for (int nt = 0; nt < 8; ++nt) {
#pragma unroll
            for (int e = 0; e < 4; ++e) {
                const int m = bm + wm * 64 + mt * 16 + gr + (e >> 1) * 8;
                const int n = bn + wn * 64 + nt * 8 + gc + (e & 1);
                const float v = acc[mt][nt][e];
                if (MODE == 0) {
                    const int s   = n / CH;
                    const int rem = n - s * CH;
                    const int h   = rem >> 6;
                    const int d   = rem & 63;
                    const int bb  = m / NT;
                    const int tt  = m - bb * NT;
                    const size_t idx = (((size_t)(bb * NH + h)) * NT + tt) * DH + d;
                    float* dst = (s == 0) ? g_q : (s == 1) ? g_k : g_v;
                    dst[idx] = v;
                } else {
                    if (n < N) C[(size_t)m * ldc + n] = v;
                }
            }
        }
    }
}

// ---------------- block reduce helper ----------------
__device__ __forceinline__ float2 block_reduce2(float s, float ss, float* shm)
{
#pragma unroll
    for (int o = 16; o; o >>= 1) {
        s  += __shfl_xor_sync(0xffffffffu, s,  o);
        ss += __shfl_xor_sync(0xffffffffu, ss, o);
    }
    const int w = threadIdx.x >> 5, lane = threadIdx.x & 31;
    if (lane == 0) { shm[w] = s; shm[8 + w] = ss; }
    __syncthreads();
    if (threadIdx.x < 32) {
        s  = (lane < 8) ? shm[lane]     : 0.f;
        ss = (lane < 8) ? shm[8 + lane] : 0.f;
#pragma unroll
        for (int o = 4; o; o >>= 1) {
            s  += __shfl_xor_sync(0xffffffffu, s,  o);
            ss += __shfl_xor_sync(0xffffffffu, ss, o);
        }
        if (lane == 0) { shm[0] = s; shm[1] = ss; }
    }
    __syncthreads();
    return make_float2(shm[0], shm[1]);
}

__global__ __launch_bounds__(256)
void ln_silu512(float* __restrict__ data, const float* __restrict__ g, const float* __restrict__ b)
{
    __shared__ float shm[16];
    const int row = blockIdx.x, tid = threadIdx.x;
    float* p = data + (size_t)row * 512;
    float x0 = p[tid], x1 = p[tid + 256];
    float2 r = block_reduce2(x0 + x1, x0 * x0 + x1 * x1, shm);
    const float mean = r.x * (1.f / 512.f);
    const float var  = r.y * (1.f / 512.f) - mean * mean;
    const float inv  = rsqrtf(var + 1e-5f);
    float y0 = (x0 - mean) * inv * g[tid]       + b[tid];
    float y1 = (x1 - mean) * inv * g[tid + 256] + b[tid + 256];
    p[tid]       = y0 / (1.f + __expf(-y0));
    p[tid + 256] = y1 / (1.f + __expf(-y1));
}

__global__ __launch_bounds__(256)
void ln3072(float* __restrict__ data, const float* __restrict__ g, const float* __restrict__ b)
{
    __shared__ float shm[16];
    const int row = blockIdx.x, tid = threadIdx.x;
    float* p = data + (size_t)row * 3072;
    float x[12];
    float s = 0.f, ss = 0.f;
#pragma unroll
    for (int i = 0; i < 12; i++) {
        x[i] = p[tid + i * 256];
        s += x[i]; ss += x[i] * x[i];
    }
    float2 r = block_reduce2(s, ss, shm);
    const float mean = r.x * (1.f / 3072.f);
    const float var  = r.y * (1.f / 3072.f) - mean * mean;
    const float inv  = rsqrtf(var + 1e-5f);
#pragma unroll
    for (int i = 0; i < 12; i++) {
        const int c = tid + i * 256;
        p[c] = (x[i] - mean) * inv * g[c] + b[c];
    }
}

// ---------------- tensor-core fused attention (LN + QK^T + bias + softmax + PV) ----------------
// smem (fp16): Q[80][72] | K[80][72] | Vt[64][88] | P[80][88]
#define ATT_SQ 72
#define ATT_SP 88
#define ATT_OQ 0
#define ATT_OK 11520
#define ATT_OV 23040
#define ATT_OP 34304
#define ATT_SMEM 48384

__global__ __launch_bounds__(128)
void attn_kernel(const float* __restrict__ qn_g, const float* __restrict__ qn_b,
                 const float* __restrict__ kn_g, const float* __restrict__ kn_b)
{
    extern __shared__ __align__(16) char asm_[];
    __half* hQ = (__half*)(asm_ + ATT_OQ);
    __half* hK = (__half*)(asm_ + ATT_OK);
    __half* hV = (__half*)(asm_ + ATT_OV);
    __half* hP = (__half*)(asm_ + ATT_OP);
    const uint32_t uQ = s2u(hQ), uK = s2u(hK), uV = s2u(hV), uP = s2u(hP);

    const int bh  = blockIdx.x;
    const int tid = threadIdx.x;
    const int w = tid >> 5, lane = tid & 31;
    const size_t base = (size_t)bh * (NT * DH);
    const float* gq = g_q + base;
    const float* gk = g_k + base;
    const float* gv = g_v + base;

    // zero pads: all of Vt, Q rows 65..79, K rows 65..79
    {
        const uint4 z = make_uint4(0, 0, 0, 0);
        uint4* pV = (uint4*)(asm_ + ATT_OV);
        for (int i = tid; i < 704; i += 128) pV[i] = z;          // 11264 B
        uint4* pQ = (uint4*)(asm_ + ATT_OQ + 65 * ATT_SQ * 2);   // 9360
        uint4* pK = (uint4*)(asm_ + ATT_OK + 65 * ATT_SQ * 2);
        for (int i = tid; i < 135; i += 128) { pQ[i] = z; pK[i] = z; }
    }
    __syncthreads();

    // LN q (x1/8), k -> fp16 smem; V -> transposed fp16 smem
    {
        const float qg0 = qn_g[lane], qg1 = qn_g[lane + 32];
        const float qb0 = qn_b[lane], qb1 = qn_b[lane + 32];
        const float kg0 = kn_g[lane], kg1 = kn_g[lane + 32];
        const float kb0 = kn_b[lane], kb1 = kn_b[lane + 32];
        for (int r = w; r < NT; r += 4) {
            float x0 = gq[r * DH + lane], x1 = gq[r * DH + lane + 32];
            float s = x0 + x1, ss = x0 * x0 + x1 * x1;
#pragma unroll
            for (int o = 16; o; o >>= 1) {
                s  += __shfl_xor_sync(0xffffffffu, s,  o);
                ss += __shfl_xor_sync(0xffffffffu, ss, o);
            }
            float mean = s * (1.f / 64.f);
            float inv  = rsqrtf(ss * (1.f / 64.f) - mean * mean + 1e-5f);
            hQ[r * ATT_SQ + lane]      = __float2half(((x0 - mean) * inv * qg0 + qb0) * 0.125f);
            hQ[r * ATT_SQ + lane + 32] = __float2half(((x1 - mean) * inv * qg1 + qb1) * 0.125f);

            x0 = gk[r * DH + lane]; x1 = gk[r * DH + lane + 32];
            s = x0 + x1; ss = x0 * x0 + x1 * x1;
#pragma unroll
            for (int o = 16; o; o >>= 1) {
                s  += __shfl_xor_sync(0xffffffffu, s,  o);
                ss += __shfl_xor_sync(0xffffffffu, ss, o);
            }
            mean = s * (1.f / 64.f);
            inv  = rsqrtf(ss * (1.f / 64.f) - mean * mean + 1e-5f);
            hK[r * ATT_SQ + lane]      = __float2half((x0 - mean) * inv * kg0 + kb0);
            hK[r * ATT_SQ + lane + 32] = __float2half((x1 - mean) * inv * kg1 + kb1);

            hV[lane * ATT_SP + r]        = __float2half(gv[r * DH + lane]);
            hV[(lane + 32) * ATT_SP + r] = __float2half(gv[r * DH + lane + 32]);
        }
    }
    __syncthreads();

    const float* bp = g_bias + (size_t)bh * (NT * NT);
    const int b = bh / NH, h = bh - b * NH;
    const int gr = lane >> 2, gc = (lane & 3) * 2;

    for (int mt = w; mt < 5; mt += 4) {     // warp0: mt 0 and 4; others one tile
        // ---- S = Q @ K^T ----
        float acc[9][4];
#pragma unroll
        for (int nt = 0; nt < 9; ++nt)
#pragma unroll
            for (int e = 0; e < 4; ++e) acc[nt][e] = 0.f;
#pragma unroll
        for (int kt = 0; kt < 4; ++kt) {
            uint32_t a[4];
            ldsm4(a, uQ + (uint32_t)((mt * 16 + (lane & 15)) * ATT_SQ + kt * 16 + (lane >> 4) * 8) * 2);
            uint32_t bf[5][4];
#pragma unroll
            for (int ng = 0; ng < 5; ++ng)
                ldsm4(bf[ng], uK + (uint32_t)((ng * 16 + ((lane >> 4) & 1) * 8 + (lane & 7)) * ATT_SQ +
                                              kt * 16 + ((lane >> 3) & 1) * 8) * 2);
#pragma unroll
            for (int nt = 0; nt < 9; ++nt)
                mma16816(acc[nt], a, bf[nt >> 1][(nt & 1) * 2], bf[nt >> 1][(nt & 1) * 2 + 1]);
        }
        // ---- bias + column mask ----
#pragma unroll
        for (int nt = 0; nt < 9; ++nt)
#pragma unroll
            for (int e = 0; e < 4; ++e) {
                const int i = mt * 16 + gr + (e >> 1) * 8;
                const int j = nt * 8 + gc + (e & 1);
                if (j >= NT)      acc[nt][e] = -1e30f;
                else if (i < NT)  acc[nt][e] += bp[i * NT + j];
            }
        // ---- softmax (two sub-rows per lane) + write P fp16 ----
#pragma unroll
        for (int hp = 0; hp < 2; ++hp) {
            const int e0 = hp * 2;
            float mx = -1e30f;
#pragma unroll
            for (int nt = 0; nt < 9; ++nt)
                mx = fmaxf(mx, fmaxf(acc[nt][e0], acc[nt][e0 + 1]));
            mx = fmaxf(mx, __shfl_xor_sync(0xffffffffu, mx, 1));
            mx = fmaxf(mx, __shfl_xor_sync(0xffffffffu, mx, 2));
            float sum = 0.f;
#pragma unroll
            for (int nt = 0; nt < 9; ++nt) {
                acc[nt][e0]     = __expf(acc[nt][e0]     - mx);
                acc[nt][e0 + 1] = __expf(acc[nt][e0 + 1] - mx);
                sum += acc[nt][e0] + acc[nt][e0 + 1];
            }
            sum += __shfl_xor_sync(0xffffffffu, sum, 1);
            sum += __shfl_xor_sync(0xffffffffu, sum, 2);
            const float inv = 1.f / sum;
            const int row = mt * 16 + gr + hp * 8;
#pragma unroll
            for (int nt = 0; nt < 9; ++nt)
                *(__half2*)&hP[row * ATT_SP + nt * 8 + gc] =
                    __floats2half2_rn(acc[nt][e0] * inv, acc[nt][e0 + 1] * inv);
            *(__half2*)&hP[row * ATT_SP + 72 + gc] = __floats2half2_rn(0.f, 0.f);
        }
        __syncwarp();

        // ---- O = P @ Vt ----
        float oc[8][4];
#pragma unroll
        for (int nt = 0; nt < 8; ++nt)
#pragma unroll
            for (int e = 0; e < 4; ++e) oc[nt][e] = 0.f;
#pragma unroll
        for (int kt = 0; kt < 5; ++kt) {
            uint32_t a[4];
            ldsm4(a, uP + (uint32_t)((mt * 16 + (lane & 15)) * ATT_SP + kt * 16 + (lane >> 4) * 8) * 2);
            uint32_t bf[4][4];
#pragma unroll
            for (int ng = 0; ng < 4; ++ng)
                ldsm4(bf[ng], uV + (uint32_t)((ng * 16 + ((lane >> 4) & 1) * 8 + (lane & 7)) * ATT_SP +
                                              kt * 16 + ((lane >> 3) & 1) * 8) * 2);
#pragma unroll
            for (int nt = 0; nt < 8; ++nt)
                mma16816(oc[nt], a, bf[nt >> 1][(nt & 1) * 2], bf[nt >> 1][(nt & 1) * 2 + 1]);
        }
        // ---- store O fp16 ----
#pragma unroll
        for (int hp = 0; hp < 2; ++hp) {
            const int i = mt * 16 + gr + hp * 8;
            if (i < NT) {
                __half* oh = g_attbf + ((size_t)(b * NT + i)) * CH + h * DH;
#pragma unroll
                for (int nt = 0; nt < 8; ++nt)
                    *(__half2*)&oh[nt * 8 + gc] =
                        __floats2half2_rn(oc[nt][hp * 2], oc[nt][hp * 2 + 1]);
            }
        }
    }
}

// ---------------- host launcher ----------------
extern "C" void kernel_launch(void* const* d_in, const int* in_sizes, int n_in,
                              void* d_out, int out_size)
{
    const float* x       = (const float*)d_in[0];
    const float* qkv_w   = (const float*)d_in[1];
    const float* proj_w  = (const float*)d_in[2];
    const float* qn_g    = (const float*)d_in[3];
    const float* qn_b    = (const float*)d_in[4];
    const float* kn_g    = (const float*)d_in[5];
    const float* kn_b    = (const float*)d_in[6];
    const float* sg_w1   = (const float*)d_in[7];
    const float* sg_ln1g = (const float*)d_in[8];
    const float* sg_ln1b = (const float*)d_in[9];
    const float* sg_w2   = (const float*)d_in[10];
    const float* sg_ln2g = (const float*)d_in[11];
    const float* sg_ln2b = (const float*)d_in[12];
    const float* sg_bw   = (const float*)d_in[13];
    float* out = (float*)d_out;

    float *p_lat1, *p_lat2, *p_bias;
    cudaGetSymbolAddress((void**)&p_lat1, g_lat1);
    cudaGetSymbolAddress((void**)&p_lat2, g_lat2);
    cudaGetSymbolAddress((void**)&p_bias, g_bias);
    __half *pxbf, *pattbf, *pwqkv, *pwproj, *pcls, *pw1, *pl1, *pw2, *pl2, *pwb;
    cudaGetSymbolAddress((void**)&pxbf,  g_xbf);
    cudaGetSymbolAddress((void**)&pattbf,g_attbf);
    cudaGetSymbolAddress((void**)&pwqkv, g_wqkv);
    cudaGetSymbolAddress((void**)&pwproj,g_wproj);
    cudaGetSymbolAddress((void**)&pcls,  g_clsbf);
    cudaGetSymbolAddress((void**)&pw1,   g_w1bf);
    cudaGetSymbolAddress((void**)&pl1,   g_l1bf);
    cudaGetSymbolAddress((void**)&pw2,   g_w2bf);
    cudaGetSymbolAddress((void**)&pl2,   g_l2bf);
    cudaGetSymbolAddress((void**)&pwb,   g_wbbf);

    const int SM2 = NSTG * 3 * (int)APART;   // 92160 (2-pass)
    const int SM1 = NSTG * 2 * (int)APART;   // 61440 (1-pass)
    cudaFuncSetAttribute(gemm_mma<0,1>, cudaFuncAttributeMaxDynamicSharedMemorySize, SM1);
    cudaFuncSetAttribute(gemm_mma<1,2>, cudaFuncAttributeMaxDynamicSharedMemorySize, SM2);
    cudaFuncSetAttribute(gemm_mma<1,1>, cudaFuncAttributeMaxDynamicSharedMemorySize, SM1);
    cudaFuncSetAttribute(attn_kernel, cudaFuncAttributeMaxDynamicSharedMemorySize, ATT_SMEM);

    // side stream + events (created once, on the first — uncaptured — call)
    static cudaStream_t sB = nullptr;
    static cudaEvent_t evFork = nullptr, evJoin = nullptr;
    if (sB == nullptr) {
        cudaStreamCreateWithFlags(&sB, cudaStreamNonBlocking);
        cudaEventCreateWithFlags(&evFork, cudaEventDisableTiming);
        cudaEventCreateWithFlags(&evJoin, cudaEventDisableTiming);
    }

    // fork: bias-generator path runs concurrently on sB
    cudaEventRecord(evFork, 0);
    cudaStreamWaitEvent(sB, evFork, 0);

    // --- side stream: bias path + proj weight conversion ---
    conv_split<<<1024, 192, 0, sB>>>(x, NT * CH, pcls, CH, 1024);
    conv16<<<512, 192, 0, sB>>>(sg_w1, CH, pw1, CH, 512);
    conv16<<<768, 192, 0, sB>>>(proj_w, CH, pwproj, CH, 768);
    gemm_mma<1,2><<<dim3(4, 8), 128, SM2, sB>>>(pcls, 1536, pw1, 768, p_lat1, 512, 1024, 512, 768);
    ln_silu512<<<1024, 256, 0, sB>>>(p_lat1, sg_ln1g, sg_ln1b);
    conv_split<<<1024, 128, 0, sB>>>(p_lat1, 512, pl1, 512, 1024);
    conv16<<<3072, 128, 0, sB>>>(sg_w2, 512, pw2, 512, 3072);
    gemm_mma<1,2><<<dim3(24, 8), 128, SM2, sB>>>(pl1, 1024, pw2, 512, p_lat2, 3072, 1024, 3072, 512);
    ln3072<<<1024, 256, 0, sB>>>(p_lat2, sg_ln2g, sg_ln2b);
    conv_split<<<12288, 64, 0, sB>>>(p_lat2, 256, pl2, 256, 12288);
    conv16<<<4352, 64, 0, sB>>>(sg_bw, 256, pwb, 256, 4225);
    gemm_mma<1,2><<<dim3(34, 96), 128, SM2, sB>>>(pl2, 512, pwb, 256, p_bias, 4225, 12288, 4225, 256);
    cudaEventRecord(evJoin, sB);

    // --- main stream: qkv path (single-pass fp16) ---
    conv16<<<66560, 192>>>(x, CH, pxbf, CH, 66560);
    conv16<<<2304, 192>>>(qkv_w, CH, pwqkv, CH, 2304);
    gemm_mma<0,1><<<dim3(18, 520), 128, SM1>>>(pxbf, 768, pwqkv, 768, nullptr, 0, 66560, 2304, 768);

    // join: attention needs q/k/v AND bias
    cudaStreamWaitEvent(0, evJoin, 0);
    attn_kernel<<<NBATCH * NH, 128, ATT_SMEM>>>(qn_g, qn_b, kn_g, kn_b);

    // --- output projection: single-pass fp16 A ---
    gemm_mma<1,1><<<dim3(6, 520), 128, SM1>>>(pattbf, 768, pwproj, 768, out, 768, 66560, 768, 768);
}

// round 12
// speedup vs baseline: 5.3503x; 1.0275x over previous
#include <cuda_runtime.h>
#include <cuda_fp16.h>
#include <cstdint>

// ---------------- problem constants ----------------
#define NBATCH 1024
#define NT     65
#define CH     768
#define NH     12
#define DH     64

// ---------------- fp32 scratch ----------------
__device__ __align__(16) float g_bias[51916800];  // [B*H,65*65]
__device__ __align__(16) float g_lat1[524288];    // [1024,512]
__device__ __align__(16) float g_lat2[3145728];   // [1024,3072]

// ---------------- fp16 scratch ----------------
__device__ __align__(16) __half g_qh[51118080];     // [B,H,NT,DH] fp16 (pre-LN)
__device__ __align__(16) __half g_kh[51118080];
__device__ __align__(16) __half g_vh[51118080];
__device__ __align__(16) __half g_xbf[51118080];    // 66560 x 768
__device__ __align__(16) __half g_attbf[51118080];  // 66560 x 768 (by attn)
__device__ __align__(16) __half g_clsbf[1572864];   // 1024 x 1536 [hi|lo]
__device__ __align__(16) __half g_l1bf[1048576];    // 1024 x 1024 [hi|lo]
__device__ __align__(16) __half g_l2bf[6291456];    // 12288 x 512 [hi|lo]
__device__ __align__(16) __half g_wqkv[1769472];    // 2304 x 768
__device__ __align__(16) __half g_wproj[589824];    // 768 x 768
__device__ __align__(16) __half g_w1bf[393216];     // 512 x 768
__device__ __align__(16) __half g_w2bf[1572864];    // 3072 x 512
__device__ __align__(16) __half g_wbbf[1114112];    // 4352 x 256 (rows >= 4225 zero)

// ---------------- helpers ----------------
__device__ __forceinline__ uint32_t s2u(const void* p) {
    uint32_t a;
    asm("{ .reg .u64 t; cvta.to.shared.u64 t, %1; cvt.u32.u64 %0, t; }" : "=r"(a) : "l"(p));
    return a;
}
__device__ __forceinline__ void ldsm4(uint32_t* r, uint32_t addr) {
    asm volatile("ldmatrix.sync.aligned.m8n8.x4.shared.b16 {%0,%1,%2,%3}, [%4];"
        : "=r"(r[0]), "=r"(r[1]), "=r"(r[2]), "=r"(r[3]) : "r"(addr));
}
__device__ __forceinline__ void mma16816(float* d, const uint32_t* a, uint32_t b0, uint32_t b1) {
    asm volatile(
        "mma.sync.aligned.m16n8k16.row.col.f32.f16.f16.f32 "
        "{%0,%1,%2,%3}, {%4,%5,%6,%7}, {%8,%9}, {%0,%1,%2,%3};"
        : "+f"(d[0]), "+f"(d[1]), "+f"(d[2]), "+f"(d[3])
        : "r"(a[0]), "r"(a[1]), "r"(a[2]), "r"(a[3]), "r"(b0), "r"(b1));
}

// ---------------- fp32 -> fp16 hi|lo split ----------------
__global__ void conv_split(const float* __restrict__ src, int lds,
                           __half* __restrict__ dst, int K, int rowsValid)
{
    const int r = blockIdx.x;
    const float4* s = (const float4*)(src + (size_t)r * lds);
    __half2* dh = (__half2*)(dst + (size_t)r * 2 * K);
    __half2* dl = (__half2*)(dst + (size_t)r * 2 * K + K);
    const bool valid = r < rowsValid;
    for (int c = threadIdx.x; c < K / 4; c += blockDim.x) {
        float4 v = valid ? s[c] : make_float4(0.f, 0.f, 0.f, 0.f);
        __half hx = __float2half(v.x), hy = __float2half(v.y);
        __half hz = __float2half(v.z), hw = __float2half(v.w);
        dh[c * 2]     = __half2(hx, hy);
        dh[c * 2 + 1] = __half2(hz, hw);
        dl[c * 2]     = __half2(__float2half(v.x - __half2float(hx)),
                                __float2half(v.y - __half2float(hy)));
        dl[c * 2 + 1] = __half2(__float2half(v.z - __half2float(hz)),
                                __float2half(v.w - __half2float(hw)));
    }
}

// ---------------- fp32 -> fp16 plain ----------------
__global__ void conv16(const float* __restrict__ src, int lds,
                       __half* __restrict__ dst, int K, int rowsValid)
{
    const int r = blockIdx.x;
    const float4* s = (const float4*)(src + (size_t)r * lds);
    __half2* d = (__half2*)(dst + (size_t)r * K);
    const bool valid = r < rowsValid;
    for (int c = threadIdx.x; c < K / 4; c += blockDim.x) {
        float4 v = valid ? s[c] : make_float4(0.f, 0.f, 0.f, 0.f);
        d[c * 2]     = __half2(__float2half(v.x), __float2half(v.y));
        d[c * 2 + 1] = __half2(__float2half(v.z), __float2half(v.w));
    }
}

// ---------------- fp16 split GEMM: C = A @ B^T ----------------
// MODE 0: qkv scatter epilogue -> fp16 q/k/v (half2 stores).
// MODE 1: fp32 store with N guard.
#define KC    32
#define LDS_  40
#define APART 10240u
#define NSTG  3

template<int MODE, int PASSES>
__global__ __launch_bounds__(128, 2)
void gemm_mma(const __half* __restrict__ A, int lda,
              const __half* __restrict__ B, int ldb,
              float* __restrict__ C, int ldc, int M, int N, int K)
{
    constexpr int NPARTS = PASSES + 1;
    constexpr uint32_t STGB = NPARTS * APART;

    extern __shared__ char dynsm[];
    const uint32_t sbase = s2u(dynsm);

    const int tid = threadIdx.x, wid = tid >> 5, lane = tid & 31;
    const int wm = wid & 1, wn = wid >> 1;
    const int bm = blockIdx.y * 128, bn = blockIdx.x * 128;
    const int nk = K / KC;

    float acc[4][8][4];
#pragma unroll
    for (int i = 0; i < 4; i++)
#pragma unroll
        for (int j = 0; j < 8; j++)
#pragma unroll
            for (int e = 0; e < 4; e++) acc[i][j][e] = 0.f;

    auto loads = [&](int t) {
        const uint32_t ub = sbase + (uint32_t)(t % NSTG) * STGB;
        const int kOff = t * KC;
#pragma unroll
        for (int i = 0; i < 4 * NPARTS; i++) {
            const int idx = tid + i * 128;
            const int part = idx >> 9;
            const int id2 = idx & 511;
            const int r = id2 >> 2, cc = id2 & 3;
            const uint32_t dst = ub + (uint32_t)part * APART +
                                 (uint32_t)(r * LDS_ + cc * 8) * 2;
            const void* g = (part == NPARTS - 1)
                ? (const void*)(B + (size_t)(bn + r) * ldb + kOff + cc * 8)
                : (const void*)(A + (size_t)(bm + r) * lda + part * K + kOff + cc * 8);
            asm volatile("cp.async.cg.shared.global [%0], [%1], 16;" :: "r"(dst), "l"(g));
        }
        asm volatile("cp.async.commit_group;");
    };

    loads(0);
    if (nk > 1) loads(1);

    for (int t = 0; t < nk; ++t) {
        if (t + 1 < nk) asm volatile("cp.async.wait_group 1;");
        else            asm volatile("cp.async.wait_group 0;");
        __syncthreads();
        if (t + 2 < nk) loads(t + 2);

        const uint32_t ub  = sbase + (uint32_t)(t % NSTG) * STGB;
        const uint32_t uAh = ub + (uint32_t)(wm * 64 * LDS_) * 2;
        const uint32_t uAl = uAh + APART;
        const uint32_t uB  = ub + (NPARTS - 1) * APART + (uint32_t)(wn * 64 * LDS_) * 2;
#pragma unroll
        for (int ks = 0; ks < 2; ++ks) {
            uint32_t ah[4][4], al[4][4], b[4][4];
#pragma unroll
            for (int mt = 0; mt < 4; ++mt) {
                const uint32_t ro = (uint32_t)((mt * 16 + (lane & 15)) * LDS_ +
                                               ks * 16 + (lane >> 4) * 8) * 2;
                ldsm4(ah[mt], uAh + ro);
                if (PASSES == 2) ldsm4(al[mt], uAl + ro);
            }
#pragma unroll
            for (int ng = 0; ng < 4; ++ng) {
                const uint32_t addr = uB +
                    (uint32_t)((ng * 16 + ((lane >> 4) & 1) * 8 + (lane & 7)) * LDS_ +
                               ks * 16 + ((lane >> 3) & 1) * 8) * 2;
                ldsm4(b[ng], addr);
            }
#pragma unroll
            for (int mt = 0; mt < 4; ++mt)
#pragma unroll
                for (int nt = 0; nt < 8; ++nt) {
                    const uint32_t b0 = b[nt >> 1][(nt & 1) * 2];
                    const uint32_t b1 = b[nt >> 1][(nt & 1) * 2 + 1];
                    mma16816(acc[mt][nt], ah[mt], b0, b1);
                    if (PASSES == 2) mma16816(acc[mt][nt], al[mt], b0, b1);
                }
        }
    }

    const int gr = lane >> 2, gc = (lane & 3) * 2;
#pragma unroll
    for (int mt = 0; mt < 4; ++mt) {
#pragma unroll
        for (int nt = 0; nt < 8; ++nt) {
            if (MODE == 0) {
                // n and n+1 are consecutive d within one head: half2 store
#pragma unroll
                for (int hp = 0; hp < 2; ++hp) {
                    const int m = bm + wm * 64 + mt * 16 + gr + hp * 8;
                    const int n = bn + wn * 64 + nt * 8 + gc;
                    const int s   = n / CH;
                    const int rem = n - s * CH;
                    const int h   = rem >> 6;
                    const int d   = rem & 63;
                    const int bb  = m / NT;
                    const int tt  = m - bb * NT;
                    const size_t idx = (((size_t)(bb * NH + h)) * NT + tt) * DH + d;
                    __half* dst = (s == 0) ? g_qh : (s == 1) ? g_kh : g_vh;
                    *(__half2*)&dst[idx] =
                        __floats2half2_rn(acc[mt][nt][hp * 2], acc[mt][nt][hp * 2 + 1]);
                }
            } else {
#pragma unroll
                for (int e = 0; e < 4; ++e) {
                    const int m = bm + wm * 64 + mt * 16 + gr + (e >> 1) * 8;
                    const int n = bn + wn * 64 + nt * 8 + gc + (e & 1);
                    if (n < N) C[(size_t)m * ldc + n] = acc[mt][nt][e];
                }
            }
        }
    }
}

// ---------------- block reduce helper ----------------
__device__ __forceinline__ float2 block_reduce2(float s, float ss, float* shm)
{
#pragma unroll
    for (int o = 16; o; o >>= 1) {
        s  += __shfl_xor_sync(0xffffffffu, s,  o);
        ss += __shfl_xor_sync(0xffffffffu, ss, o);
    }
    const int w = threadIdx.x >> 5, lane = threadIdx.x & 31;
    if (lane == 0) { shm[w] = s; shm[8 + w] = ss; }
    __syncthreads();
    if (threadIdx.x < 32) {
        s  = (lane < 8) ? shm[lane]     : 0.f;
        ss = (lane < 8) ? shm[8 + lane] : 0.f;
#pragma unroll
        for (int o = 4; o; o >>= 1) {
            s  += __shfl_xor_sync(0xffffffffu, s,  o);
            ss += __shfl_xor_sync(0xffffffffu, ss, o);
        }
        if (lane == 0) { shm[0] = s; shm[1] = ss; }
    }
    __syncthreads();
    return make_float2(shm[0], shm[1]);
}

__global__ __launch_bounds__(256)
void ln_silu512(float* __restrict__ data, const float* __restrict__ g, const float* __restrict__ b)
{
    __shared__ float shm[16];
    const int row = blockIdx.x, tid = threadIdx.x;
    float* p = data + (size_t)row * 512;
    float x0 = p[tid], x1 = p[tid + 256];
    float2 r = block_reduce2(x0 + x1, x0 * x0 + x1 * x1, shm);
    const float mean = r.x * (1.f / 512.f);
    const float var  = r.y * (1.f / 512.f) - mean * mean;
    const float inv  = rsqrtf(var + 1e-5f);
    float y0 = (x0 - mean) * inv * g[tid]       + b[tid];
    float y1 = (x1 - mean) * inv * g[tid + 256] + b[tid + 256];
    p[tid]       = y0 / (1.f + __expf(-y0));
    p[tid + 256] = y1 / (1.f + __expf(-y1));
}

__global__ __launch_bounds__(256)
void ln3072(float* __restrict__ data, const float* __restrict__ g, const float* __restrict__ b)
{
    __shared__ float shm[16];
    const int row = blockIdx.x, tid = threadIdx.x;
    float* p = data + (size_t)row * 3072;
    float x[12];
    float s = 0.f, ss = 0.f;
#pragma unroll
    for (int i = 0; i < 12; i++) {
        x[i] = p[tid + i * 256];
        s += x[i]; ss += x[i] * x[i];
    }
    float2 r = block_reduce2(s, ss, shm);
    const float mean = r.x * (1.f / 3072.f);
    const float var  = r.y * (1.f / 3072.f) - mean * mean;
    const float inv  = rsqrtf(var + 1e-5f);
#pragma unroll
    for (int i = 0; i < 12; i++) {
        const int c = tid + i * 256;
        p[c] = (x[i] - mean) * inv * g[c] + b[c];
    }
}

// ---------------- tensor-core fused attention (fp16 q/k/v inputs) ----------------
// smem (fp16): Q[80][72] | K[80][72] | Vt[64][88] | P[80][88]
#define ATT_SQ 72
#define ATT_SP 88
#define ATT_OQ 0
#define ATT_OK 11520
#define ATT_OV 23040
#define ATT_OP 34304
#define ATT_SMEM 48384

__global__ __launch_bounds__(128)
void attn_kernel(const float* __restrict__ qn_g, const float* __restrict__ qn_b,
                 const float* __restrict__ kn_g, const float* __restrict__ kn_b)
{
    extern __shared__ __align__(16) char asm_[];
    __half* hQ = (__half*)(asm_ + ATT_OQ);
    __half* hK = (__half*)(asm_ + ATT_OK);
    __half* hV = (__half*)(asm_ + ATT_OV);
    __half* hP = (__half*)(asm_ + ATT_OP);
    const uint32_t uQ = s2u(hQ), uK = s2u(hK), uV = s2u(hV), uP = s2u(hP);

    const int bh  = blockIdx.x;
    const int tid = threadIdx.x;
    const int w = tid >> 5, lane = tid & 31;
    const size_t base = (size_t)bh * (NT * DH);
    const __half* gq = g_qh + base;
    const __half* gk = g_kh + base;
    const __half* gv = g_vh + base;

    // zero pads: all of Vt, Q rows 65..79, K rows 65..79
    {
        const uint4 z = make_uint4(0, 0, 0, 0);
        uint4* pV = (uint4*)(asm_ + ATT_OV);
        for (int i = tid; i < 704; i += 128) pV[i] = z;
        uint4* pQ = (uint4*)(asm_ + ATT_OQ + 65 * ATT_SQ * 2);
        uint4* pK = (uint4*)(asm_ + ATT_OK + 65 * ATT_SQ * 2);
        for (int i = tid; i < 135; i += 128) { pQ[i] = z; pK[i] = z; }
    }
    __syncthreads();

    // LN q (x1/8), k -> fp16 smem; V -> transposed fp16 smem
    {
        const float qg0 = qn_g[lane], qg1 = qn_g[lane + 32];
        const float qb0 = qn_b[lane], qb1 = qn_b[lane + 32];
        const float kg0 = kn_g[lane], kg1 = kn_g[lane + 32];
        const float kb0 = kn_b[lane], kb1 = kn_b[lane + 32];
        for (int r = w; r < NT; r += 4) {
            float x0 = __half2float(gq[r * DH + lane]);
            float x1 = __half2float(gq[r * DH + lane + 32]);
            float s = x0 + x1, ss = x0 * x0 + x1 * x1;
#pragma unroll
            for (int o = 16; o; o >>= 1) {
                s  += __shfl_xor_sync(0xffffffffu, s,  o);
                ss += __shfl_xor_sync(0xffffffffu, ss, o);
            }
            float mean = s * (1.f / 64.f);
            float inv  = rsqrtf(ss * (1.f / 64.f) - mean * mean + 1e-5f);
            hQ[r * ATT_SQ + lane]      = __float2half(((x0 - mean) * inv * qg0 + qb0) * 0.125f);
            hQ[r * ATT_SQ + lane + 32] = __float2half(((x1 - mean) * inv * qg1 + qb1) * 0.125f);

            x0 = __half2float(gk[r * DH + lane]);
            x1 = __half2float(gk[r * DH + lane + 32]);
            s = x0 + x1; ss = x0 * x0 + x1 * x1;
#pragma unroll
            for (int o = 16; o; o >>= 1) {
                s  += __shfl_xor_sync(0xffffffffu, s,  o);
                ss += __shfl_xor_sync(0xffffffffu, ss, o);
            }
            mean = s * (1.f / 64.f);
            inv  = rsqrtf(ss * (1.f / 64.f) - mean * mean + 1e-5f);
            hK[r * ATT_SQ + lane]      = __float2half((x0 - mean) * inv * kg0 + kb0);
            hK[r * ATT_SQ + lane + 32] = __float2half((x1 - mean) * inv * kg1 + kb1);

            hV[lane * ATT_SP + r]        = gv[r * DH + lane];
            hV[(lane + 32) * ATT_SP + r] = gv[r * DH + lane + 32];
        }
    }
    __syncthreads();

    const float* bp = g_bias + (size_t)bh * (NT * NT);
    const int b = bh / NH, h = bh - b * NH;
    const int gr = lane >> 2, gc = (lane & 3) * 2;

    for (int mt = w; mt < 5; mt += 4) {
        // ---- S = Q @ K^T ----
        float acc[9][4];
#pragma unroll
        for (int nt = 0; nt < 9; ++nt)
#pragma unroll
            for (int e = 0; e < 4; ++e) acc[nt][e] = 0.f;
#pragma unroll
        for (int kt = 0; kt < 4; ++kt) {
            uint32_t a[4];
            ldsm4(a, uQ + (uint32_t)((mt * 16 + (lane & 15)) * ATT_SQ + kt * 16 + (lane >> 4) * 8) * 2);
            uint32_t bf[5][4];
#pragma unroll
            for (int ng = 0; ng < 5; ++ng)
                ldsm4(bf[ng], uK + (uint32_t)((ng * 16 + ((lane >> 4) & 1) * 8 + (lane & 7)) * ATT_SQ +
                                              kt * 16 + ((lane >> 3) & 1) * 8) * 2);
#pragma unroll
            for (int nt = 0; nt < 9; ++nt)
                mma16816(acc[nt], a, bf[nt >> 1][(nt & 1) * 2], bf[nt >> 1][(nt & 1) * 2 + 1]);
        }
        // ---- bias + column mask ----
#pragma unroll
        for (int nt = 0; nt < 9; ++nt)
#pragma unroll
            for (int e = 0; e < 4; ++e) {
                const int i = mt * 16 + gr + (e >> 1) * 8;
                const int j = nt * 8 + gc + (e & 1);
                if (j >= NT)      acc[nt][e] = -1e30f;
                else if (i < NT)  acc[nt][e] += bp[i * NT + j];
            }
        // ---- softmax ----
#pragma unroll
        for (int hp = 0; hp < 2; ++hp) {
            const int e0 = hp * 2;
            float mx = -1e30f;
#pragma unroll
            for (int nt = 0; nt < 9; ++nt)
                mx = fmaxf(mx, fmaxf(acc[nt][e0], acc[nt][e0 + 1]));
            mx = fmaxf(mx, __shfl_xor_sync(0xffffffffu, mx, 1));
            mx = fmaxf(mx, __shfl_xor_sync(0xffffffffu, mx, 2));
            float sum = 0.f;
#pragma unroll
            for (int nt = 0; nt < 9; ++nt) {
                acc[nt][e0]     = __expf(acc[nt][e0]     - mx);
                acc[nt][e0 + 1] = __expf(acc[nt][e0 + 1] - mx);
                sum += acc[nt][e0] + acc[nt][e0 + 1];
            }
            sum += __shfl_xor_sync(0xffffffffu, sum, 1);
            sum += __shfl_xor_sync(0xffffffffu, sum, 2);
            const float inv = 1.f / sum;
            const int row = mt * 16 + gr + hp * 8;
#pragma unroll
            for (int nt = 0; nt < 9; ++nt)
                *(__half2*)&hP[row * ATT_SP + nt * 8 + gc] =
                    __floats2half2_rn(acc[nt][e0] * inv, acc[nt][e0 + 1] * inv);
            *(__half2*)&hP[row * ATT_SP + 72 + gc] = __floats2half2_rn(0.f, 0.f);
        }
        __syncwarp();

        // ---- O = P @ Vt ----
        float oc[8][4];
#pragma unroll
        for (int nt = 0; nt < 8; ++nt)
#pragma unroll
            for (int e = 0; e < 4; ++e) oc[nt][e] = 0.f;
#pragma unroll
        for (int kt = 0; kt < 5; ++kt) {
            uint32_t a[4];
            ldsm4(a, uP + (uint32_t)((mt * 16 + (lane & 15)) * ATT_SP + kt * 16 + (lane >> 4) * 8) * 2);
            uint32_t bf[4][4];
#pragma unroll
            for (int ng = 0; ng < 4; ++ng)
                ldsm4(bf[ng], uV + (uint32_t)((ng * 16 + ((lane >> 4) & 1) * 8 + (lane & 7)) * ATT_SP +
                                              kt * 16 + ((lane >> 3) & 1) * 8) * 2);
#pragma unroll
            for (int nt = 0; nt < 8; ++nt)
                mma16816(oc[nt], a, bf[nt >> 1][(nt & 1) * 2], bf[nt >> 1][(nt & 1) * 2 + 1]);
        }
        // ---- store O fp16 ----
#pragma unroll
        for (int hp = 0; hp < 2; ++hp) {
            const int i = mt * 16 + gr + hp * 8;
            if (i < NT) {
                __half* oh = g_attbf + ((size_t)(b * NT + i)) * CH + h * DH;
#pragma unroll
                for (int nt = 0; nt < 8; ++nt)
                    *(__half2*)&oh[nt * 8 + gc] =
                        __floats2half2_rn(oc[nt][hp * 2], oc[nt][hp * 2 + 1]);
            }
        }
    }
}

// ---------------- host launcher ----------------
extern "C" void kernel_launch(void* const* d_in, const int* in_sizes, int n_in,
                              void* d_out, int out_size)
{
    const float* x       = (const float*)d_in[0];
    const float* qkv_w   = (const float*)d_in[1];
    const float* proj_w  = (const float*)d_in[2];
    const float* qn_g    = (const float*)d_in[3];
    const float* qn_b    = (const float*)d_in[4];
    const float* kn_g    = (const float*)d_in[5];
    const float* kn_b    = (const float*)d_in[6];
    const float* sg_w1   = (const float*)d_in[7];
    const float* sg_ln1g = (const float*)d_in[8];
    const float* sg_ln1b = (const float*)d_in[9];
    const float* sg_w2   = (const float*)d_in[10];
    const float* sg_ln2g = (const float*)d_in[11];
    const float* sg_ln2b = (const float*)d_in[12];
    const float* sg_bw   = (const float*)d_in[13];
    float* out = (float*)d_out;

    float *p_lat1, *p_lat2, *p_bias;
    cudaGetSymbolAddress((void**)&p_lat1, g_lat1);
    cudaGetSymbolAddress((void**)&p_lat2, g_lat2);
    cudaGetSymbolAddress((void**)&p_bias, g_bias);
    __half *pxbf, *pattbf, *pwqkv, *pwproj, *pcls, *pw1, *pl1, *pw2, *pl2, *pwb;
    cudaGetSymbolAddress((void**)&pxbf,  g_xbf);
    cudaGetSymbolAddress((void**)&pattbf,g_attbf);
    cudaGetSymbolAddress((void**)&pwqkv, g_wqkv);
    cudaGetSymbolAddress((void**)&pwproj,g_wproj);
    cudaGetSymbolAddress((void**)&pcls,  g_clsbf);
    cudaGetSymbolAddress((void**)&pw1,   g_w1bf);
    cudaGetSymbolAddress((void**)&pl1,   g_l1bf);
    cudaGetSymbolAddress((void**)&pw2,   g_w2bf);
    cudaGetSymbolAddress((void**)&pl2,   g_l2bf);
    cudaGetSymbolAddress((void**)&pwb,   g_wbbf);

    const int SM2 = NSTG * 3 * (int)APART;   // 92160
    const int SM1 = NSTG * 2 * (int)APART;   // 61440
    cudaFuncSetAttribute(gemm_mma<0,1>, cudaFuncAttributeMaxDynamicSharedMemorySize, SM1);
    cudaFuncSetAttribute(gemm_mma<1,2>, cudaFuncAttributeMaxDynamicSharedMemorySize, SM2);
    cudaFuncSetAttribute(gemm_mma<1,1>, cudaFuncAttributeMaxDynamicSharedMemorySize, SM1);
    cudaFuncSetAttribute(attn_kernel, cudaFuncAttributeMaxDynamicSharedMemorySize, ATT_SMEM);

    static cudaStream_t sB = nullptr;
    static cudaEvent_t evFork = nullptr, evJoin = nullptr;
    if (sB == nullptr) {
        cudaStreamCreateWithFlags(&sB, cudaStreamNonBlocking);
        cudaEventCreateWithFlags(&evFork, cudaEventDisableTiming);
        cudaEventCreateWithFlags(&evJoin, cudaEventDisableTiming);
    }

    cudaEventRecord(evFork, 0);
    cudaStreamWaitEvent(sB, evFork, 0);

    // --- side stream: bias path + proj weight conversion ---
    conv_split<<<1024, 192, 0, sB>>>(x, NT * CH, pcls, CH, 1024);
    conv16<<<512, 192, 0, sB>>>(sg_w1, CH, pw1, CH, 512);
    conv16<<<768, 192, 0, sB>>>(proj_w, CH, pwproj, CH, 768);
    gemm_mma<1,2><<<dim3(4, 8), 128, SM2, sB>>>(pcls, 1536, pw1, 768, p_lat1, 512, 1024, 512, 768);
    ln_silu512<<<1024, 256, 0, sB>>>(p_lat1, sg_ln1g, sg_ln1b);
    conv_split<<<1024, 128, 0, sB>>>(p_lat1, 512, pl1, 512, 1024);
    conv16<<<3072, 128, 0, sB>>>(sg_w2, 512, pw2, 512, 3072);
    gemm_mma<1,2><<<dim3(24, 8), 128, SM2, sB>>>(pl1, 1024, pw2, 512, p_lat2, 3072, 1024, 3072, 512);
    ln3072<<<1024, 256, 0, sB>>>(p_lat2, sg_ln2g, sg_ln2b);
    conv_split<<<12288, 64, 0, sB>>>(p_lat2, 256, pl2, 256, 12288);
    conv16<<<4352, 64, 0, sB>>>(sg_bw, 256, pwb, 256, 4225);
    gemm_mma<1,2><<<dim3(34, 96), 128, SM2, sB>>>(pl2, 512, pwb, 256, p_bias, 4225, 12288, 4225, 256);
    cudaEventRecord(evJoin, sB);

    // --- main stream: qkv path (single-pass fp16, fp16 q/k/v outputs) ---
    conv16<<<66560, 192>>>(x, CH, pxbf, CH, 66560);
    conv16<<<2304, 192>>>(qkv_w, CH, pwqkv, CH, 2304);
    gemm_mma<0,1><<<dim3(18, 520), 128, SM1>>>(pxbf, 768, pwqkv, 768, nullptr, 0, 66560, 2304, 768);

    cudaStreamWaitEvent(0, evJoin, 0);
    attn_kernel<<<NBATCH * NH, 128, ATT_SMEM>>>(qn_g, qn_b, kn_g, kn_b);

    // --- output projection ---
    gemm_mma<1,1><<<dim3(6, 520), 128, SM1>>>(pattbf, 768, pwproj, 768, out, 768, 66560, 768, 768);
}

// round 13
// speedup vs baseline: 5.5430x; 1.0360x over previous
#include <cuda_runtime.h>
#include <cuda_fp16.h>
#include <cstdint>

// ---------------- problem constants ----------------
#define NBATCH 1024
#define NT     65
#define CH     768
#define NH     12
#define DH     64

// ---------------- fp32 scratch ----------------
__device__ __align__(16) float g_lat1[524288];    // [1024,512]
__device__ __align__(16) float g_lat2[3145728];   // [1024,3072]

// ---------------- fp16 scratch ----------------
__device__ __align__(16) __half g_biash[51916800]; // [B*H,65*65] fp16
__device__ __align__(16) __half g_qh[51118080];    // [B,H,NT,DH] fp16 (pre-LN)
__device__ __align__(16) __half g_kh[51118080];
__device__ __align__(16) __half g_vh[51118080];
__device__ __align__(16) __half g_xbf[51118080];   // 66560 x 768
__device__ __align__(16) __half g_attbf[51118080]; // 66560 x 768 (by attn)
__device__ __align__(16) __half g_clsbf[1572864];  // 1024 x 1536 [hi|lo]
__device__ __align__(16) __half g_l1bf[1048576];   // 1024 x 1024 [hi|lo]
__device__ __align__(16) __half g_l2bf[6291456];   // 12288 x 512 [hi|lo]
__device__ __align__(16) __half g_wqkv[1769472];   // 2304 x 768
__device__ __align__(16) __half g_wproj[589824];   // 768 x 768
__device__ __align__(16) __half g_w1bf[393216];    // 512 x 768
__device__ __align__(16) __half g_w2bf[1572864];   // 3072 x 512
__device__ __align__(16) __half g_wbbf[1114112];   // 4352 x 256 (rows >= 4225 zero)

// ---------------- helpers ----------------
__device__ __forceinline__ uint32_t s2u(const void* p) {
    uint32_t a;
    asm("{ .reg .u64 t; cvta.to.shared.u64 t, %1; cvt.u32.u64 %0, t; }" : "=r"(a) : "l"(p));
    return a;
}
__device__ __forceinline__ void ldsm4(uint32_t* r, uint32_t addr) {
    asm volatile("ldmatrix.sync.aligned.m8n8.x4.shared.b16 {%0,%1,%2,%3}, [%4];"
        : "=r"(r[0]), "=r"(r[1]), "=r"(r[2]), "=r"(r[3]) : "r"(addr));
}
__device__ __forceinline__ void mma16816(float* d, const uint32_t* a, uint32_t b0, uint32_t b1) {
    asm volatile(
        "mma.sync.aligned.m16n8k16.row.col.f32.f16.f16.f32 "
        "{%0,%1,%2,%3}, {%4,%5,%6,%7}, {%8,%9}, {%0,%1,%2,%3};"
        : "+f"(d[0]), "+f"(d[1]), "+f"(d[2]), "+f"(d[3])
        : "r"(a[0]), "r"(a[1]), "r"(a[2]), "r"(a[3]), "r"(b0), "r"(b1));
}

// ---------------- fp32 -> fp16 hi|lo split ----------------
__global__ void conv_split(const float* __restrict__ src, int lds,
                           __half* __restrict__ dst, int K, int rowsValid)
{
    const int r = blockIdx.x;
    const float4* s = (const float4*)(src + (size_t)r * lds);
    __half2* dh = (__half2*)(dst + (size_t)r * 2 * K);
    __half2* dl = (__half2*)(dst + (size_t)r * 2 * K + K);
    const bool valid = r < rowsValid;
    for (int c = threadIdx.x; c < K / 4; c += blockDim.x) {
        float4 v = valid ? s[c] : make_float4(0.f, 0.f, 0.f, 0.f);
        __half hx = __float2half(v.x), hy = __float2half(v.y);
        __half hz = __float2half(v.z), hw = __float2half(v.w);
        dh[c * 2]     = __half2(hx, hy);
        dh[c * 2 + 1] = __half2(hz, hw);
        dl[c * 2]     = __half2(__float2half(v.x - __half2float(hx)),
                                __float2half(v.y - __half2float(hy)));
        dl[c * 2 + 1] = __half2(__float2half(v.z - __half2float(hz)),
                                __float2half(v.w - __half2float(hw)));
    }
}

// ---------------- fp32 -> fp16 plain ----------------
__global__ void conv16(const float* __restrict__ src, int lds,
                       __half* __restrict__ dst, int K, int rowsValid)
{
    const int r = blockIdx.x;
    const float4* s = (const float4*)(src + (size_t)r * lds);
    __half2* d = (__half2*)(dst + (size_t)r * K);
    const bool valid = r < rowsValid;
    for (int c = threadIdx.x; c < K / 4; c += blockDim.x) {
        float4 v = valid ? s[c] : make_float4(0.f, 0.f, 0.f, 0.f);
        d[c * 2]     = __half2(__float2half(v.x), __float2half(v.y));
        d[c * 2 + 1] = __half2(__float2half(v.z), __float2half(v.w));
    }
}

// ---------------- fp16 split GEMM: C = A @ B^T ----------------
// MODE 0: qkv scatter -> fp16 q/k/v. MODE 1: fp32 store. MODE 2: fp16 store.
#define KC    32
#define LDS_  40
#define APART 10240u
#define NSTG  3

template<int MODE, int PASSES>
__global__ __launch_bounds__(128, 2)
void gemm_mma(const __half* __restrict__ A, int lda,
              const __half* __restrict__ B, int ldb,
              void* __restrict__ Cv, int ldc, int M, int N, int K)
{
    constexpr int NPARTS = PASSES + 1;
    constexpr uint32_t STGB = NPARTS * APART;

    extern __shared__ char dynsm[];
    const uint32_t sbase = s2u(dynsm);

    const int tid = threadIdx.x, wid = tid >> 5, lane = tid & 31;
    const int wm = wid & 1, wn = wid >> 1;
    const int bm = blockIdx.y * 128, bn = blockIdx.x * 128;
    const int nk = K / KC;

    float acc[4][8][4];
#pragma unroll
    for (int i = 0; i < 4; i++)
#pragma unroll
        for (int j = 0; j < 8; j++)
#pragma unroll
            for (int e = 0; e < 4; e++) acc[i][j][e] = 0.f;

    auto loads = [&](int t) {
        const uint32_t ub = sbase + (uint32_t)(t % NSTG) * STGB;
        const int kOff = t * KC;
#pragma unroll
        for (int i = 0; i < 4 * NPARTS; i++) {
            const int idx = tid + i * 128;
            const int part = idx >> 9;
            const int id2 = idx & 511;
            const int r = id2 >> 2, cc = id2 & 3;
            const uint32_t dst = ub + (uint32_t)part * APART +
                                 (uint32_t)(r * LDS_ + cc * 8) * 2;
            const void* g = (part == NPARTS - 1)
                ? (const void*)(B + (size_t)(bn + r) * ldb + kOff + cc * 8)
                : (const void*)(A + (size_t)(bm + r) * lda + part * K + kOff + cc * 8);
            asm volatile("cp.async.cg.shared.global [%0], [%1], 16;" :: "r"(dst), "l"(g));
        }
        asm volatile("cp.async.commit_group;");
    };

    loads(0);
    if (nk > 1) loads(1);

    for (int t = 0; t < nk; ++t) {
        if (t + 1 < nk) asm volatile("cp.async.wait_group 1;");
        else            asm volatile("cp.async.wait_group 0;");
        __syncthreads();
        if (t + 2 < nk) loads(t + 2);

        const uint32_t ub  = sbase + (uint32_t)(t % NSTG) * STGB;
        const uint32_t uAh = ub + (uint32_t)(wm * 64 * LDS_) * 2;
        const uint32_t uAl = uAh + APART;
        const uint32_t uB  = ub + (NPARTS - 1) * APART + (uint32_t)(wn * 64 * LDS_) * 2;
#pragma unroll
        for (int ks = 0; ks < 2; ++ks) {
            uint32_t ah[4][4], al[4][4], b[4][4];
#pragma unroll
            for (int mt = 0; mt < 4; ++mt) {
                const uint32_t ro = (uint32_t)((mt * 16 + (lane & 15)) * LDS_ +
                                               ks * 16 + (lane >> 4) * 8) * 2;
                ldsm4(ah[mt], uAh + ro);
                if (PASSES == 2) ldsm4(al[mt], uAl + ro);
            }
#pragma unroll
            for (int ng = 0; ng < 4; ++ng) {
                const uint32_t addr = uB +
                    (uint32_t)((ng * 16 + ((lane >> 4) & 1) * 8 + (lane & 7)) * LDS_ +
                               ks * 16 + ((lane >> 3) & 1) * 8) * 2;
                ldsm4(b[ng], addr);
            }
#pragma unroll
            for (int mt = 0; mt < 4; ++mt)
#pragma unroll
                for (int nt = 0; nt < 8; ++nt) {
                    const uint32_t b0 = b[nt >> 1][(nt & 1) * 2];
                    const uint32_t b1 = b[nt >> 1][(nt & 1) * 2 + 1];
                    mma16816(acc[mt][nt], ah[mt], b0, b1);
                    if (PASSES == 2) mma16816(acc[mt][nt], al[mt], b0, b1);
                }
        }
    }

    const int gr = lane >> 2, gc = (lane & 3) * 2;
#pragma unroll
    for (int mt = 0; mt < 4; ++mt) {
#pragma unroll
        for (int nt = 0; nt < 8; ++nt) {
            if (MODE == 0) {
#pragma unroll
                for (int hp = 0; hp < 2; ++hp) {
                    const int m = bm + wm * 64 + mt * 16 + gr + hp * 8;
                    const int n = bn + wn * 64 + nt * 8 + gc;
                    const int s   = n / CH;
                    const int rem = n - s * CH;
                    const int h   = rem >> 6;
                    const int d   = rem & 63;
                    const int bb  = m / NT;
                    const int tt  = m - bb * NT;
                    const size_t idx = (((size_t)(bb * NH + h)) * NT + tt) * DH + d;
                    __half* dst = (s == 0) ? g_qh : (s == 1) ? g_kh : g_vh;
                    *(__half2*)&dst[idx] =
                        __floats2half2_rn(acc[mt][nt][hp * 2], acc[mt][nt][hp * 2 + 1]);
                }
            } else if (MODE == 1) {
                float* C = (float*)Cv;
#pragma unroll
                for (int e = 0; e < 4; ++e) {
                    const int m = bm + wm * 64 + mt * 16 + gr + (e >> 1) * 8;
                    const int n = bn + wn * 64 + nt * 8 + gc + (e & 1);
                    if (n < N) C[(size_t)m * ldc + n] = acc[mt][nt][e];
                }
            } else {
                __half* C = (__half*)Cv;
#pragma unroll
                for (int e = 0; e < 4; ++e) {
                    const int m = bm + wm * 64 + mt * 16 + gr + (e >> 1) * 8;
                    const int n = bn + wn * 64 + nt * 8 + gc + (e & 1);
                    if (n < N) C[(size_t)m * ldc + n] = __float2half(acc[mt][nt][e]);
                }
            }
        }
    }
}

// ---------------- block reduce helper ----------------
__device__ __forceinline__ float2 block_reduce2(float s, float ss, float* shm)
{
#pragma unroll
    for (int o = 16; o; o >>= 1) {
        s  += __shfl_xor_sync(0xffffffffu, s,  o);
        ss += __shfl_xor_sync(0xffffffffu, ss, o);
    }
    const int w = threadIdx.x >> 5, lane = threadIdx.x & 31;
    if (lane == 0) { shm[w] = s; shm[8 + w] = ss; }
    __syncthreads();
    if (threadIdx.x < 32) {
        s  = (lane < 8) ? shm[lane]     : 0.f;
        ss = (lane < 8) ? shm[8 + lane] : 0.f;
#pragma unroll
        for (int o = 4; o; o >>= 1) {
            s  += __shfl_xor_sync(0xffffffffu, s,  o);
            ss += __shfl_xor_sync(0xffffffffu, ss, o);
        }
        if (lane == 0) { shm[0] = s; shm[1] = ss; }
    }
    __syncthreads();
    return make_float2(shm[0], shm[1]);
}

__global__ __launch_bounds__(256)
void ln_silu512(float* __restrict__ data, const float* __restrict__ g, const float* __restrict__ b)
{
    __shared__ float shm[16];
    const int row = blockIdx.x, tid = threadIdx.x;
    float* p = data + (size_t)row * 512;
    float x0 = p[tid], x1 = p[tid + 256];
    float2 r = block_reduce2(x0 + x1, x0 * x0 + x1 * x1, shm);
    const float mean = r.x * (1.f / 512.f);
    const float var  = r.y * (1.f / 512.f) - mean * mean;
    const float inv  = rsqrtf(var + 1e-5f);
    float y0 = (x0 - mean) * inv * g[tid]       + b[tid];
    float y1 = (x1 - mean) * inv * g[tid + 256] + b[tid + 256];
    p[tid]       = y0 / (1.f + __expf(-y0));
    p[tid + 256] = y1 / (1.f + __expf(-y1));
}

__global__ __launch_bounds__(256)
void ln3072(float* __restrict__ data, const float* __restrict__ g, const float* __restrict__ b)
{
    __shared__ float shm[16];
    const int row = blockIdx.x, tid = threadIdx.x;
    float* p = data + (size_t)row * 3072;
    float x[12];
    float s = 0.f, ss = 0.f;
#pragma unroll
    for (int i = 0; i < 12; i++) {
        x[i] = p[tid + i * 256];
        s += x[i]; ss += x[i] * x[i];
    }
    float2 r = block_reduce2(s, ss, shm);
    const float mean = r.x * (1.f / 3072.f);
    const float var  = r.y * (1.f / 3072.f) - mean * mean;
    const float inv  = rsqrtf(var + 1e-5f);
#pragma unroll
    for (int i = 0; i < 12; i++) {
        const int c = tid + i * 256;
        p[c] = (x[i] - mean) * inv * g[c] + b[c];
    }
}

// ---------------- tensor-core fused attention (fp16 q/k/v + fp16 bias) ----------------
// 160 threads = 5 warps, one 16-row m-tile per warp.
// smem (fp16): Q[80][72] | K[80][72] | Vt[64][88] | P[80][88]
#define ATT_SQ 72
#define ATT_SP 88
#define ATT_OQ 0
#define ATT_OK 11520
#define ATT_OV 23040
#define ATT_OP 34304
#define ATT_SMEM 48384

__global__ __launch_bounds__(160)
void attn_kernel(const float* __restrict__ qn_g, const float* __restrict__ qn_b,
                 const float* __restrict__ kn_g, const float* __restrict__ kn_b)
{
    extern __shared__ __align__(16) char asm_[];
    __half* hQ = (__half*)(asm_ + ATT_OQ);
    __half* hK = (__half*)(asm_ + ATT_OK);
    __half* hV = (__half*)(asm_ + ATT_OV);
    __half* hP = (__half*)(asm_ + ATT_OP);
    const uint32_t uQ = s2u(hQ), uK = s2u(hK), uV = s2u(hV), uP = s2u(hP);

    const int bh  = blockIdx.x;
    const int tid = threadIdx.x;
    const int w = tid >> 5, lane = tid & 31;
    const size_t base = (size_t)bh * (NT * DH);
    const __half* gq = g_qh + base;
    const __half* gk = g_kh + base;
    const __half* gv = g_vh + base;

    // zero pads
    {
        const uint4 z = make_uint4(0, 0, 0, 0);
        uint4* pV = (uint4*)(asm_ + ATT_OV);
        for (int i = tid; i < 704; i += 160) pV[i] = z;
        uint4* pQ = (uint4*)(asm_ + ATT_OQ + 65 * ATT_SQ * 2);
        uint4* pK = (uint4*)(asm_ + ATT_OK + 65 * ATT_SQ * 2);
        for (int i = tid; i < 135; i += 160) { pQ[i] = z; pK[i] = z; }
    }
    __syncthreads();

    // LN q (x1/8), k -> fp16 smem; V -> transposed fp16 smem
    {
        const float qg0 = qn_g[lane], qg1 = qn_g[lane + 32];
        const float qb0 = qn_b[lane], qb1 = qn_b[lane + 32];
        const float kg0 = kn_g[lane], kg1 = kn_g[lane + 32];
        const float kb0 = kn_b[lane], kb1 = kn_b[lane + 32];
        for (int r = w; r < NT; r += 5) {
            float x0 = __half2float(gq[r * DH + lane]);
            float x1 = __half2float(gq[r * DH + lane + 32]);
            float s = x0 + x1, ss = x0 * x0 + x1 * x1;
#pragma unroll
            for (int o = 16; o; o >>= 1) {
                s  += __shfl_xor_sync(0xffffffffu, s,  o);
                ss += __shfl_xor_sync(0xffffffffu, ss, o);
            }
            float mean = s * (1.f / 64.f);
            float inv  = rsqrtf(ss * (1.f / 64.f) - mean * mean + 1e-5f);
            hQ[r * ATT_SQ + lane]      = __float2half(((x0 - mean) * inv * qg0 + qb0) * 0.125f);
            hQ[r * ATT_SQ + lane + 32] = __float2half(((x1 - mean) * inv * qg1 + qb1) * 0.125f);

            x0 = __half2float(gk[r * DH + lane]);
            x1 = __half2float(gk[r * DH + lane + 32]);
            s = x0 + x1; ss = x0 * x0 + x1 * x1;
#pragma unroll
            for (int o = 16; o; o >>= 1) {
                s  += __shfl_xor_sync(0xffffffffu, s,  o);
                ss += __shfl_xor_sync(0xffffffffu, ss, o);
            }
            mean = s * (1.f / 64.f);
            inv  = rsqrtf(ss * (1.f / 64.f) - mean * mean + 1e-5f);
            hK[r * ATT_SQ + lane]      = __float2half((x0 - mean) * inv * kg0 + kb0);
            hK[r * ATT_SQ + lane + 32] = __float2half((x1 - mean) * inv * kg1 + kb1);

            hV[lane * ATT_SP + r]        = gv[r * DH + lane];
            hV[(lane + 32) * ATT_SP + r] = gv[r * DH + lane + 32];
        }
    }
    __syncthreads();

    const __half* bp = g_biash + (size_t)bh * (NT * NT);
    const int b = bh / NH, h = bh - b * NH;
    const int gr = lane >> 2, gc = (lane & 3) * 2;
    const int mt = w;   // one tile per warp

    // ---- S = Q @ K^T ----
    float acc[9][4];
#pragma unroll
    for (int nt = 0; nt < 9; ++nt)
#pragma unroll
        for (int e = 0; e < 4; ++e) acc[nt][e] = 0.f;
#pragma unroll
    for (int kt = 0; kt < 4; ++kt) {
        uint32_t a[4];
        ldsm4(a, uQ + (uint32_t)((mt * 16 + (lane & 15)) * ATT_SQ + kt * 16 + (lane >> 4) * 8) * 2);
        uint32_t bf[5][4];
#pragma unroll
        for (int ng = 0; ng < 5; ++ng)
            ldsm4(bf[ng], uK + (uint32_t)((ng * 16 + ((lane >> 4) & 1) * 8 + (lane & 7)) * ATT_SQ +
                                          kt * 16 + ((lane >> 3) & 1) * 8) * 2);
#pragma unroll
        for (int nt = 0; nt < 9; ++nt)
            mma16816(acc[nt], a, bf[nt >> 1][(nt & 1) * 2], bf[nt >> 1][(nt & 1) * 2 + 1]);
    }
    // ---- bias + column mask ----
#pragma unroll
    for (int nt = 0; nt < 9; ++nt)
#pragma unroll
        for (int e = 0; e < 4; ++e) {
            const int i = mt * 16 + gr + (e >> 1) * 8;
            const int j = nt * 8 + gc + (e & 1);
            if (j >= NT)      acc[nt][e] = -1e30f;
            else if (i < NT)  acc[nt][e] += __half2float(bp[i * NT + j]);
        }
    // ---- softmax ----
#pragma unroll
    for (int hp = 0; hp < 2; ++hp) {
        const int e0 = hp * 2;
        float mx = -1e30f;
#pragma unroll
        for (int nt = 0; nt < 9; ++nt)
            mx = fmaxf(mx, fmaxf(acc[nt][e0], acc[nt][e0 + 1]));
        mx = fmaxf(mx, __shfl_xor_sync(0xffffffffu, mx, 1));
        mx = fmaxf(mx, __shfl_xor_sync(0xffffffffu, mx, 2));
        float sum = 0.f;
#pragma unroll
        for (int nt = 0; nt < 9; ++nt) {
            acc[nt][e0]     = __expf(acc[nt][e0]     - mx);
            acc[nt][e0 + 1] = __expf(acc[nt][e0 + 1] - mx);
            sum += acc[nt][e0] + acc[nt][e0 + 1];
        }
        sum += __shfl_xor_sync(0xffffffffu, sum, 1);
        sum += __shfl_xor_sync(0xffffffffu, sum, 2);
        const float inv = 1.f / sum;
        const int row = mt * 16 + gr + hp * 8;
#pragma unroll
        for (int nt = 0; nt < 9; ++nt)
            *(__half2*)&hP[row * ATT_SP + nt * 8 + gc] =
                __floats2half2_rn(acc[nt][e0] * inv, acc[nt][e0 + 1] * inv);
        *(__half2*)&hP[row * ATT_SP + 72 + gc] = __floats2half2_rn(0.f, 0.f);
    }
    __syncwarp();

    // ---- O = P @ Vt ----
    float oc[8][4];
#pragma unroll
    for (int nt = 0; nt < 8; ++nt)
#pragma unroll
        for (int e = 0; e < 4; ++e) oc[nt][e] = 0.f;
#pragma unroll
    for (int kt = 0; kt < 5; ++kt) {
        uint32_t a[4];
        ldsm4(a, uP + (uint32_t)((mt * 16 + (lane & 15)) * ATT_SP + kt * 16 + (lane >> 4) * 8) * 2);
        uint32_t bf[4][4];
#pragma unroll
        for (int ng = 0; ng < 4; ++ng)
            ldsm4(bf[ng], uV + (uint32_t)((ng * 16 + ((lane >> 4) & 1) * 8 + (lane & 7)) * ATT_SP +
                                          kt * 16 + ((lane >> 3) & 1) * 8) * 2);
#pragma unroll
        for (int nt = 0; nt < 8; ++nt)
            mma16816(oc[nt], a, bf[nt >> 1][(nt & 1) * 2], bf[nt >> 1][(nt & 1) * 2 + 1]);
    }
    // ---- store O fp16 ----
#pragma unroll
    for (int hp = 0; hp < 2; ++hp) {
        const int i = mt * 16 + gr + hp * 8;
        if (i < NT) {
            __half* oh = g_attbf + ((size_t)(b * NT + i)) * CH + h * DH;
#pragma unroll
            for (int nt = 0; nt < 8; ++nt)
                *(__half2*)&oh[nt * 8 + gc] =
                    __floats2half2_rn(oc[nt][hp * 2], oc[nt][hp * 2 + 1]);
        }
    }
}

// ---------------- host launcher ----------------
extern "C" void kernel_launch(void* const* d_in, const int* in_sizes, int n_in,
                              void* d_out, int out_size)
{
    const float* x       = (const float*)d_in[0];
    const float* qkv_w   = (const float*)d_in[1];
    const float* proj_w  = (const float*)d_in[2];
    const float* qn_g    = (const float*)d_in[3];
    const float* qn_b    = (const float*)d_in[4];
    const float* kn_g    = (const float*)d_in[5];
    const float* kn_b    = (const float*)d_in[6];
    const float* sg_w1   = (const float*)d_in[7];
    const float* sg_ln1g = (const float*)d_in[8];
    const float* sg_ln1b = (const float*)d_in[9];
    const float* sg_w2   = (const float*)d_in[10];
    const float* sg_ln2g = (const float*)d_in[11];
    const float* sg_ln2b = (const float*)d_in[12];
    const float* sg_bw   = (const float*)d_in[13];
    float* out = (float*)d_out;

    float *p_lat1, *p_lat2;
    cudaGetSymbolAddress((void**)&p_lat1, g_lat1);
    cudaGetSymbolAddress((void**)&p_lat2, g_lat2);
    __half *pbiash, *pxbf, *pattbf, *pwqkv, *pwproj, *pcls, *pw1, *pl1, *pw2, *pl2, *pwb;
    cudaGetSymbolAddress((void**)&pbiash,g_biash);
    cudaGetSymbolAddress((void**)&pxbf,  g_xbf);
    cudaGetSymbolAddress((void**)&pattbf,g_attbf);
    cudaGetSymbolAddress((void**)&pwqkv, g_wqkv);
    cudaGetSymbolAddress((void**)&pwproj,g_wproj);
    cudaGetSymbolAddress((void**)&pcls,  g_clsbf);
    cudaGetSymbolAddress((void**)&pw1,   g_w1bf);
    cudaGetSymbolAddress((void**)&pl1,   g_l1bf);
    cudaGetSymbolAddress((void**)&pw2,   g_w2bf);
    cudaGetSymbolAddress((void**)&pl2,   g_l2bf);
    cudaGetSymbolAddress((void**)&pwb,   g_wbbf);

    const int SM2 = NSTG * 3 * (int)APART;   // 92160
    const int SM1 = NSTG * 2 * (int)APART;   // 61440
    cudaFuncSetAttribute(gemm_mma<0,1>, cudaFuncAttributeMaxDynamicSharedMemorySize, SM1);
    cudaFuncSetAttribute(gemm_mma<1,2>, cudaFuncAttributeMaxDynamicSharedMemorySize, SM2);
    cudaFuncSetAttribute(gemm_mma<2,2>, cudaFuncAttributeMaxDynamicSharedMemorySize, SM2);
    cudaFuncSetAttribute(gemm_mma<1,1>, cudaFuncAttributeMaxDynamicSharedMemorySize, SM1);
    cudaFuncSetAttribute(attn_kernel, cudaFuncAttributeMaxDynamicSharedMemorySize, ATT_SMEM);

    static cudaStream_t sB = nullptr;
    static cudaEvent_t evFork = nullptr, evJoin = nullptr;
    if (sB == nullptr) {
        cudaStreamCreateWithFlags(&sB, cudaStreamNonBlocking);
        cudaEventCreateWithFlags(&evFork, cudaEventDisableTiming);
        cudaEventCreateWithFlags(&evJoin, cudaEventDisableTiming);
    }

    cudaEventRecord(evFork, 0);
    cudaStreamWaitEvent(sB, evFork, 0);

    // --- side stream: bias path + proj weight conversion ---
    conv_split<<<1024, 192, 0, sB>>>(x, NT * CH, pcls, CH, 1024);
    conv16<<<512, 192, 0, sB>>>(sg_w1, CH, pw1, CH, 512);
    conv16<<<768, 192, 0, sB>>>(proj_w, CH, pwproj, CH, 768);
    gemm_mma<1,2><<<dim3(4, 8), 128, SM2, sB>>>(pcls, 1536, pw1, 768, p_lat1, 512, 1024, 512, 768);
    ln_silu512<<<1024, 256, 0, sB>>>(p_lat1, sg_ln1g, sg_ln1b);
    conv_split<<<1024, 128, 0, sB>>>(p_lat1, 512, pl1, 512, 1024);
    conv16<<<3072, 128, 0, sB>>>(sg_w2, 512, pw2, 512, 3072);
    gemm_mma<1,2><<<dim3(24, 8), 128, SM2, sB>>>(pl1, 1024, pw2, 512, p_lat2, 3072, 1024, 3072, 512);
    ln3072<<<1024, 256, 0, sB>>>(p_lat2, sg_ln2g, sg_ln2b);
    conv_split<<<12288, 64, 0, sB>>>(p_lat2, 256, pl2, 256, 12288);
    conv16<<<4352, 64, 0, sB>>>(sg_bw, 256, pwb, 256, 4225);
    gemm_mma<2,2><<<dim3(34, 96), 128, SM2, sB>>>(pl2, 512, pwb, 256, pbiash, 4225, 12288, 4225, 256);
    cudaEventRecord(evJoin, sB);

    // --- main stream: qkv path (single-pass fp16, fp16 q/k/v outputs) ---
    conv16<<<66560, 192>>>(x, CH, pxbf, CH, 66560);
    conv16<<<2304, 192>>>(qkv_w, CH, pwqkv, CH, 2304);
    gemm_mma<0,1><<<dim3(18, 520), 128, SM1>>>(pxbf, 768, pwqkv, 768, nullptr, 0, 66560, 2304, 768);

    cudaStreamWaitEvent(0, evJoin, 0);
    attn_kernel<<<NBATCH * NH, 160, ATT_SMEM>>>(qn_g, qn_b, kn_g, kn_b);

    // --- output projection ---
    gemm_mma<1,1><<<dim3(6, 520), 128, SM1>>>(pattbf, 768, pwproj, 768, out, 768, 66560, 768, 768);
}

// round 14
// speedup vs baseline: 5.8089x; 1.0480x over previous
#include <cuda_runtime.h>
#include <cuda_fp16.h>
#include <cstdint>

// ---------------- problem constants ----------------
#define NBATCH 1024
#define NT     65
#define CH     768
#define NH     12
#define DH     64

// ---------------- fp32 scratch ----------------
__device__ __align__(16) float g_lat1[524288];    // [1024,512]
__device__ __align__(16) float g_lat2[3145728];   // [1024,3072]

// ---------------- fp16 scratch ----------------
__device__ __align__(16) __half g_biash[51916800]; // [B*H,65*65] fp16
__device__ __align__(16) __half g_qh[51118080];    // [B,H,NT,DH] fp16 (pre-LN)
__device__ __align__(16) __half g_kh[51118080];
__device__ __align__(16) __half g_vh[51118080];
__device__ __align__(16) __half g_xbf[51118080];   // 66560 x 768
__device__ __align__(16) __half g_attbf[51118080]; // 66560 x 768 (by attn)
__device__ __align__(16) __half g_clsbf[786432];   // 1024 x 768
__device__ __align__(16) __half g_l1bf[524288];    // 1024 x 512
__device__ __align__(16) __half g_l2bf[3145728];   // 12288 x 256
__device__ __align__(16) __half g_wqkv[1769472];   // 2304 x 768
__device__ __align__(16) __half g_wproj[589824];   // 768 x 768
__device__ __align__(16) __half g_w1bf[393216];    // 512 x 768
__device__ __align__(16) __half g_w2bf[1572864];   // 3072 x 512
__device__ __align__(16) __half g_wbbf[1114112];   // 4352 x 256 (rows >= 4225 zero)

// ---------------- helpers ----------------
__device__ __forceinline__ uint32_t s2u(const void* p) {
    uint32_t a;
    asm("{ .reg .u64 t; cvta.to.shared.u64 t, %1; cvt.u32.u64 %0, t; }" : "=r"(a) : "l"(p));
    return a;
}
__device__ __forceinline__ void ldsm4(uint32_t* r, uint32_t addr) {
    asm volatile("ldmatrix.sync.aligned.m8n8.x4.shared.b16 {%0,%1,%2,%3}, [%4];"
        : "=r"(r[0]), "=r"(r[1]), "=r"(r[2]), "=r"(r[3]) : "r"(addr));
}
__device__ __forceinline__ void mma16816(float* d, const uint32_t* a, uint32_t b0, uint32_t b1) {
    asm volatile(
        "mma.sync.aligned.m16n8k16.row.col.f32.f16.f16.f32 "
        "{%0,%1,%2,%3}, {%4,%5,%6,%7}, {%8,%9}, {%0,%1,%2,%3};"
        : "+f"(d[0]), "+f"(d[1]), "+f"(d[2]), "+f"(d[3])
        : "r"(a[0]), "r"(a[1]), "r"(a[2]), "r"(a[3]), "r"(b0), "r"(b1));
}

// ---------------- fp32 -> fp16 plain ----------------
__global__ void conv16(const float* __restrict__ src, int lds,
                       __half* __restrict__ dst, int K, int rowsValid)
{
    const int r = blockIdx.x;
    const float4* s = (const float4*)(src + (size_t)r * lds);
    __half2* d = (__half2*)(dst + (size_t)r * K);
    const bool valid = r < rowsValid;
    for (int c = threadIdx.x; c < K / 4; c += blockDim.x) {
        float4 v = valid ? s[c] : make_float4(0.f, 0.f, 0.f, 0.f);
        d[c * 2]     = __half2(__float2half(v.x), __float2half(v.y));
        d[c * 2 + 1] = __half2(__float2half(v.z), __float2half(v.w));
    }
}

// ---------------- fp16 split GEMM: C = A @ B^T ----------------
// MODE 0: qkv scatter -> fp16 q/k/v. MODE 1: fp32 store. MODE 2: fp16 store.
#define KC    32
#define LDS_  40
#define APART 10240u
#define NSTG  3

template<int MODE, int PASSES>
__global__ __launch_bounds__(128, 2)
void gemm_mma(const __half* __restrict__ A, int lda,
              const __half* __restrict__ B, int ldb,
              void* __restrict__ Cv, int ldc, int M, int N, int K)
{
    constexpr int NPARTS = PASSES + 1;
    constexpr uint32_t STGB = NPARTS * APART;

    extern __shared__ char dynsm[];
    const uint32_t sbase = s2u(dynsm);

    const int tid = threadIdx.x, wid = tid >> 5, lane = tid & 31;
    const int wm = wid & 1, wn = wid >> 1;
    const int bm = blockIdx.y * 128, bn = blockIdx.x * 128;
    const int nk = K / KC;

    float acc[4][8][4];
#pragma unroll
    for (int i = 0; i < 4; i++)
#pragma unroll
        for (int j = 0; j < 8; j++)
#pragma unroll
            for (int e = 0; e < 4; e++) acc[i][j][e] = 0.f;

    auto loads = [&](int t) {
        const uint32_t ub = sbase + (uint32_t)(t % NSTG) * STGB;
        const int kOff = t * KC;
#pragma unroll
        for (int i = 0; i < 4 * NPARTS; i++) {
            const int idx = tid + i * 128;
            const int part = idx >> 9;
            const int id2 = idx & 511;
            const int r = id2 >> 2, cc = id2 & 3;
            const uint32_t dst = ub + (uint32_t)part * APART +
                                 (uint32_t)(r * LDS_ + cc * 8) * 2;
            const void* g = (part == NPARTS - 1)
                ? (const void*)(B + (size_t)(bn + r) * ldb + kOff + cc * 8)
                : (const void*)(A + (size_t)(bm + r) * lda + part * K + kOff + cc * 8);
            asm volatile("cp.async.cg.shared.global [%0], [%1], 16;" :: "r"(dst), "l"(g));
        }
        asm volatile("cp.async.commit_group;");
    };

    loads(0);
    if (nk > 1) loads(1);

    for (int t = 0; t < nk; ++t) {
        if (t + 1 < nk) asm volatile("cp.async.wait_group 1;");
        else            asm volatile("cp.async.wait_group 0;");
        __syncthreads();
        if (t + 2 < nk) loads(t + 2);

        const uint32_t ub  = sbase + (uint32_t)(t % NSTG) * STGB;
        const uint32_t uAh = ub + (uint32_t)(wm * 64 * LDS_) * 2;
        const uint32_t uAl = uAh + APART;
        const uint32_t uB  = ub + (NPARTS - 1) * APART + (uint32_t)(wn * 64 * LDS_) * 2;
#pragma unroll
        for (int ks = 0; ks < 2; ++ks) {
            uint32_t ah[4][4], al[4][4], b[4][4];
#pragma unroll
            for (int mt = 0; mt < 4; ++mt) {
                const uint32_t ro = (uint32_t)((mt * 16 + (lane & 15)) * LDS_ +
                                               ks * 16 + (lane >> 4) * 8) * 2;
                ldsm4(ah[mt], uAh + ro);
                if (PASSES == 2) ldsm4(al[mt], uAl + ro);
            }
#pragma unroll
            for (int ng = 0; ng < 4; ++ng) {
                const uint32_t addr = uB +
                    (uint32_t)((ng * 16 + ((lane >> 4) & 1) * 8 + (lane & 7)) * LDS_ +
                               ks * 16 + ((lane >> 3) & 1) * 8) * 2;
                ldsm4(b[ng], addr);
            }
#pragma unroll
            for (int mt = 0; mt < 4; ++mt)
#pragma unroll
                for (int nt = 0; nt < 8; ++nt) {
                    const uint32_t b0 = b[nt >> 1][(nt & 1) * 2];
                    const uint32_t b1 = b[nt >> 1][(nt & 1) * 2 + 1];
                    mma16816(acc[mt][nt], ah[mt], b0, b1);
                    if (PASSES == 2) mma16816(acc[mt][nt], al[mt], b0, b1);
                }
        }
    }

    const int gr = lane >> 2, gc = (lane & 3) * 2;
#pragma unroll
    for (int mt = 0; mt < 4; ++mt) {
#pragma unroll
        for (int nt = 0; nt < 8; ++nt) {
            if (MODE == 0) {
#pragma unroll
                for (int hp = 0; hp < 2; ++hp) {
                    const int m = bm + wm * 64 + mt * 16 + gr + hp * 8;
                    const int n = bn + wn * 64 + nt * 8 + gc;
                    const int s   = n / CH;
                    const int rem = n - s * CH;
                    const int h   = rem >> 6;
                    const int d   = rem & 63;
                    const int bb  = m / NT;
                    const int tt  = m - bb * NT;
                    const size_t idx = (((size_t)(bb * NH + h)) * NT + tt) * DH + d;
                    __half* dst = (s == 0) ? g_qh : (s == 1) ? g_kh : g_vh;
                    *(__half2*)&dst[idx] =
                        __floats2half2_rn(acc[mt][nt][hp * 2], acc[mt][nt][hp * 2 + 1]);
                }
            } else if (MODE == 1) {
                float* C = (float*)Cv;
#pragma unroll
                for (int e = 0; e < 4; ++e) {
                    const int m = bm + wm * 64 + mt * 16 + gr + (e >> 1) * 8;
                    const int n = bn + wn * 64 + nt * 8 + gc + (e & 1);
                    if (n < N) C[(size_t)m * ldc + n] = acc[mt][nt][e];
                }
            } else {
                __half* C = (__half*)Cv;
#pragma unroll
                for (int e = 0; e < 4; ++e) {
                    const int m = bm + wm * 64 + mt * 16 + gr + (e >> 1) * 8;
                    const int n = bn + wn * 64 + nt * 8 + gc + (e & 1);
                    if (n < N) C[(size_t)m * ldc + n] = __float2half(acc[mt][nt][e]);
                }
            }
        }
    }
}

// ---------------- block reduce helper ----------------
__device__ __forceinline__ float2 block_reduce2(float s, float ss, float* shm)
{
#pragma unroll
    for (int o = 16; o; o >>= 1) {
        s  += __shfl_xor_sync(0xffffffffu, s,  o);
        ss += __shfl_xor_sync(0xffffffffu, ss, o);
    }
    const int w = threadIdx.x >> 5, lane = threadIdx.x & 31;
    if (lane == 0) { shm[w] = s; shm[8 + w] = ss; }
    __syncthreads();
    if (threadIdx.x < 32) {
        s  = (lane < 8) ? shm[lane]     : 0.f;
        ss = (lane < 8) ? shm[8 + lane] : 0.f;
#pragma unroll
        for (int o = 4; o; o >>= 1) {
            s  += __shfl_xor_sync(0xffffffffu, s,  o);
            ss += __shfl_xor_sync(0xffffffffu, ss, o);
        }
        if (lane == 0) { shm[0] = s; shm[1] = ss; }
    }
    __syncthreads();
    return make_float2(shm[0], shm[1]);
}

__global__ __launch_bounds__(256)
void ln_silu512(float* __restrict__ data, const float* __restrict__ g, const float* __restrict__ b)
{
    __shared__ float shm[16];
    const int row = blockIdx.x, tid = threadIdx.x;
    float* p = data + (size_t)row * 512;
    float x0 = p[tid], x1 = p[tid + 256];
    float2 r = block_reduce2(x0 + x1, x0 * x0 + x1 * x1, shm);
    const float mean = r.x * (1.f / 512.f);
    const float var  = r.y * (1.f / 512.f) - mean * mean;
    const float inv  = rsqrtf(var + 1e-5f);
    float y0 = (x0 - mean) * inv * g[tid]       + b[tid];
    float y1 = (x1 - mean) * inv * g[tid + 256] + b[tid + 256];
    p[tid]       = y0 / (1.f + __expf(-y0));
    p[tid + 256] = y1 / (1.f + __expf(-y1));
}

__global__ __launch_bounds__(256)
void ln3072(float* __restrict__ data, const float* __restrict__ g, const float* __restrict__ b)
{
    __shared__ float shm[16];
    const int row = blockIdx.x, tid = threadIdx.x;
    float* p = data + (size_t)row * 3072;
    float x[12];
    float s = 0.f, ss = 0.f;
#pragma unroll
    for (int i = 0; i < 12; i++) {
        x[i] = p[tid + i * 256];
        s += x[i]; ss += x[i] * x[i];
    }
    float2 r = block_reduce2(s, ss, shm);
    const float mean = r.x * (1.f / 3072.f);
    const float var  = r.y * (1.f / 3072.f) - mean * mean;
    const float inv  = rsqrtf(var + 1e-5f);
#pragma unroll
    for (int i = 0; i < 12; i++) {
        const int c = tid + i * 256;
        p[c] = (x[i] - mean) * inv * g[c] + b[c];
    }
}

// ---------------- tensor-core fused attention (fp16 q/k/v + fp16 bias) ----------------
// 160 threads = 5 warps, one 16-row m-tile per warp.
// smem (fp16): Q[80][72] | K[80][72] | Vt[64][88] | P[80][88]
#define ATT_SQ 72
#define ATT_SP 88
#define ATT_OQ 0
#define ATT_OK 11520
#define ATT_OV 23040
#define ATT_OP 34304
#define ATT_SMEM 48384

__global__ __launch_bounds__(160)
void attn_kernel(const float* __restrict__ qn_g, const float* __restrict__ qn_b,
                 const float* __restrict__ kn_g, const float* __restrict__ kn_b)
{
    extern __shared__ __align__(16) char asm_[];
    __half* hQ = (__half*)(asm_ + ATT_OQ);
    __half* hK = (__half*)(asm_ + ATT_OK);
    __half* hV = (__half*)(asm_ + ATT_OV);
    __half* hP = (__half*)(asm_ + ATT_OP);
    const uint32_t uQ = s2u(hQ), uK = s2u(hK), uV = s2u(hV), uP = s2u(hP);

    const int bh  = blockIdx.x;
    const int tid = threadIdx.x;
    const int w = tid >> 5, lane = tid & 31;
    const size_t base = (size_t)bh * (NT * DH);
    const __half* gq = g_qh + base;
    const __half* gk = g_kh + base;
    const __half* gv = g_vh + base;

    // zero pads
    {
        const uint4 z = make_uint4(0, 0, 0, 0);
        uint4* pV = (uint4*)(asm_ + ATT_OV);
        for (int i = tid; i < 704; i += 160) pV[i] = z;
        uint4* pQ = (uint4*)(asm_ + ATT_OQ + 65 * ATT_SQ * 2);
        uint4* pK = (uint4*)(asm_ + ATT_OK + 65 * ATT_SQ * 2);
        for (int i = tid; i < 135; i += 160) { pQ[i] = z; pK[i] = z; }
    }
    __syncthreads();

    // LN q (x1/8), k -> fp16 smem; V -> transposed fp16 smem
    {
        const float qg0 = qn_g[lane], qg1 = qn_g[lane + 32];
        const float qb0 = qn_b[lane], qb1 = qn_b[lane + 32];
        const float kg0 = kn_g[lane], kg1 = kn_g[lane + 32];
        const float kb0 = kn_b[lane], kb1 = kn_b[lane + 32];
        for (int r = w; r < NT; r += 5) {
            float x0 = __half2float(gq[r * DH + lane]);
            float x1 = __half2float(gq[r * DH + lane + 32]);
            float s = x0 + x1, ss = x0 * x0 + x1 * x1;
#pragma unroll
            for (int o = 16; o; o >>= 1) {
                s  += __shfl_xor_sync(0xffffffffu, s,  o);
                ss += __shfl_xor_sync(0xffffffffu, ss, o);
            }
            float mean = s * (1.f / 64.f);
            float inv  = rsqrtf(ss * (1.f / 64.f) - mean * mean + 1e-5f);
            hQ[r * ATT_SQ + lane]      = __float2half(((x0 - mean) * inv * qg0 + qb0) * 0.125f);
            hQ[r * ATT_SQ + lane + 32] = __float2half(((x1 - mean) * inv * qg1 + qb1) * 0.125f);

            x0 = __half2float(gk[r * DH + lane]);
            x1 = __half2float(gk[r * DH + lane + 32]);
            s = x0 + x1; ss = x0 * x0 + x1 * x1;
#pragma unroll
            for (int o = 16; o; o >>= 1) {
                s  += __shfl_xor_sync(0xffffffffu, s,  o);
                ss += __shfl_xor_sync(0xffffffffu, ss, o);
            }
            mean = s * (1.f / 64.f);
            inv  = rsqrtf(ss * (1.f / 64.f) - mean * mean + 1e-5f);
            hK[r * ATT_SQ + lane]      = __float2half((x0 - mean) * inv * kg0 + kb0);
            hK[r * ATT_SQ + lane + 32] = __float2half((x1 - mean) * inv * kg1 + kb1);

            hV[lane * ATT_SP + r]        = gv[r * DH + lane];
            hV[(lane + 32) * ATT_SP + r] = gv[r * DH + lane + 32];
        }
    }
    __syncthreads();

    const __half* bp = g_biash + (size_t)bh * (NT * NT);
    const int b = bh / NH, h = bh - b * NH;
    const int gr = lane >> 2, gc = (lane & 3) * 2;
    const int mt = w;

    // ---- S = Q @ K^T ----
    float acc[9][4];
#pragma unroll
    for (int nt = 0; nt < 9; ++nt)
#pragma unroll
        for (int e = 0; e < 4; ++e) acc[nt][e] = 0.f;
#pragma unroll
    for (int kt = 0; kt < 4; ++kt) {
        uint32_t a[4];
        ldsm4(a, uQ + (uint32_t)((mt * 16 + (lane & 15)) * ATT_SQ + kt * 16 + (lane >> 4) * 8) * 2);
        uint32_t bf[5][4];
#pragma unroll
        for (int ng = 0; ng < 5; ++ng)
            ldsm4(bf[ng], uK + (uint32_t)((ng * 16 + ((lane >> 4) & 1) * 8 + (lane & 7)) * ATT_SQ +
                                          kt * 16 + ((lane >> 3) & 1) * 8) * 2);
#pragma unroll
        for (int nt = 0; nt < 9; ++nt)
            mma16816(acc[nt], a, bf[nt >> 1][(nt & 1) * 2], bf[nt >> 1][(nt & 1) * 2 + 1]);
    }
    // ---- bias + column mask ----
#pragma unroll
    for (int nt = 0; nt < 9; ++nt)
#pragma unroll
        for (int e = 0; e < 4; ++e) {
            const int i = mt * 16 + gr + (e >> 1) * 8;
            const int j = nt * 8 + gc + (e & 1);
            if (j >= NT)      acc[nt][e] = -1e30f;
            else if (i < NT)  acc[nt][e] += __half2float(bp[i * NT + j]);
        }
    // ---- softmax ----
#pragma unroll
    for (int hp = 0; hp < 2; ++hp) {
        const int e0 = hp * 2;
        float mx = -1e30f;
#pragma unroll
        for (int nt = 0; nt < 9; ++nt)
            mx = fmaxf(mx, fmaxf(acc[nt][e0], acc[nt][e0 + 1]));
        mx = fmaxf(mx, __shfl_xor_sync(0xffffffffu, mx, 1));
        mx = fmaxf(mx, __shfl_xor_sync(0xffffffffu, mx, 2));
        float sum = 0.f;
#pragma unroll
        for (int nt = 0; nt < 9; ++nt) {
            acc[nt][e0]     = __expf(acc[nt][e0]     - mx);
            acc[nt][e0 + 1] = __expf(acc[nt][e0 + 1] - mx);
            sum += acc[nt][e0] + acc[nt][e0 + 1];
        }
        sum += __shfl_xor_sync(0xffffffffu, sum, 1);
        sum += __shfl_xor_sync(0xffffffffu, sum, 2);
        const float inv = 1.f / sum;
        const int row = mt * 16 + gr + hp * 8;
#pragma unroll
        for (int nt = 0; nt < 9; ++nt)
            *(__half2*)&hP[row * ATT_SP + nt * 8 + gc] =
                __floats2half2_rn(acc[nt][e0] * inv, acc[nt][e0 + 1] * inv);
        *(__half2*)&hP[row * ATT_SP + 72 + gc] = __floats2half2_rn(0.f, 0.f);
    }
    __syncwarp();

    // ---- O = P @ Vt ----
    float oc[8][4];
#pragma unroll
    for (int nt = 0; nt < 8; ++nt)
#pragma unroll
        for (int e = 0; e < 4; ++e) oc[nt][e] = 0.f;
#pragma unroll
    for (int kt = 0; kt < 5; ++kt) {
        uint32_t a[4];
        ldsm4(a, uP + (uint32_t)((mt * 16 + (lane & 15)) * ATT_SP + kt * 16 + (lane >> 4) * 8) * 2);
        uint32_t bf[4][4];
#pragma unroll
        for (int ng = 0; ng < 4; ++ng)
            ldsm4(bf[ng], uV + (uint32_t)((ng * 16 + ((lane >> 4) & 1) * 8 + (lane & 7)) * ATT_SP +
                                          kt * 16 + ((lane >> 3) & 1) * 8) * 2);
#pragma unroll
        for (int nt = 0; nt < 8; ++nt)
            mma16816(oc[nt], a, bf[nt >> 1][(nt & 1) * 2], bf[nt >> 1][(nt & 1) * 2 + 1]);
    }
    // ---- store O fp16 ----
#pragma unroll
    for (int hp = 0; hp < 2; ++hp) {
        const int i = mt * 16 + gr + hp * 8;
        if (i < NT) {
            __half* oh = g_attbf + ((size_t)(b * NT + i)) * CH + h * DH;
#pragma unroll
            for (int nt = 0; nt < 8; ++nt)
                *(__half2*)&oh[nt * 8 + gc] =
                    __floats2half2_rn(oc[nt][hp * 2], oc[nt][hp * 2 + 1]);
        }
    }
}

// ---------------- host launcher ----------------
extern "C" void kernel_launch(void* const* d_in, const int* in_sizes, int n_in,
                              void* d_out, int out_size)
{
    const float* x       = (const float*)d_in[0];
    const float* qkv_w   = (const float*)d_in[1];
    const float* proj_w  = (const float*)d_in[2];
    const float* qn_g    = (const float*)d_in[3];
    const float* qn_b    = (const float*)d_in[4];
    const float* kn_g    = (const float*)d_in[5];
    const float* kn_b    = (const float*)d_in[6];
    const float* sg_w1   = (const float*)d_in[7];
    const float* sg_ln1g = (const float*)d_in[8];
    const float* sg_ln1b = (const float*)d_in[9];
    const float* sg_w2   = (const float*)d_in[10];
    const float* sg_ln2g = (const float*)d_in[11];
    const float* sg_ln2b = (const float*)d_in[12];
    const float* sg_bw   = (const float*)d_in[13];
    float* out = (float*)d_out;

    float *p_lat1, *p_lat2;
    cudaGetSymbolAddress((void**)&p_lat1, g_lat1);
    cudaGetSymbolAddress((void**)&p_lat2, g_lat2);
    __half *pbiash, *pxbf, *pattbf, *pwqkv, *pwproj, *pcls, *pw1, *pl1, *pw2, *pl2, *pwb;
    cudaGetSymbolAddress((void**)&pbiash,g_biash);
    cudaGetSymbolAddress((void**)&pxbf,  g_xbf);
    cudaGetSymbolAddress((void**)&pattbf,g_attbf);
    cudaGetSymbolAddress((void**)&pwqkv, g_wqkv);
    cudaGetSymbolAddress((void**)&pwproj,g_wproj);
    cudaGetSymbolAddress((void**)&pcls,  g_clsbf);
    cudaGetSymbolAddress((void**)&pw1,   g_w1bf);
    cudaGetSymbolAddress((void**)&pl1,   g_l1bf);
    cudaGetSymbolAddress((void**)&pw2,   g_w2bf);
    cudaGetSymbolAddress((void**)&pl2,   g_l2bf);
    cudaGetSymbolAddress((void**)&pwb,   g_wbbf);

    const int SM1 = NSTG * 2 * (int)APART;   // 61440 (1-pass)
    cudaFuncSetAttribute(gemm_mma<0,1>, cudaFuncAttributeMaxDynamicSharedMemorySize, SM1);
    cudaFuncSetAttribute(gemm_mma<1,1>, cudaFuncAttributeMaxDynamicSharedMemorySize, SM1);
    cudaFuncSetAttribute(gemm_mma<2,1>, cudaFuncAttributeMaxDynamicSharedMemorySize, SM1);
    cudaFuncSetAttribute(attn_kernel, cudaFuncAttributeMaxDynamicSharedMemorySize, ATT_SMEM);

    static cudaStream_t sB = nullptr;
    static cudaEvent_t evFork = nullptr, evJoin = nullptr;
    if (sB == nullptr) {
        cudaStreamCreateWithFlags(&sB, cudaStreamNonBlocking);
        cudaEventCreateWithFlags(&evFork, cudaEventDisableTiming);
        cudaEventCreateWithFlags(&evJoin, cudaEventDisableTiming);
    }

    cudaEventRecord(evFork, 0);
    cudaStreamWaitEvent(sB, evFork, 0);

    // --- side stream: bias path (all single-pass fp16) + proj weight conversion ---
    conv16<<<1024, 192, 0, sB>>>(x, NT * CH, pcls, CH, 1024);
    conv16<<<512, 192, 0, sB>>>(sg_w1, CH, pw1, CH, 512);
    conv16<<<768, 192, 0, sB>>>(proj_w, CH, pwproj, CH, 768);
    gemm_mma<1,1><<<dim3(4, 8), 128, SM1, sB>>>(pcls, 768, pw1, 768, p_lat1, 512, 1024, 512, 768);
    ln_silu512<<<1024, 256, 0, sB>>>(p_lat1, sg_ln1g, sg_ln1b);
    conv16<<<1024, 128, 0, sB>>>(p_lat1, 512, pl1, 512, 1024);
    conv16<<<3072, 128, 0, sB>>>(sg_w2, 512, pw2, 512, 3072);
    gemm_mma<1,1><<<dim3(24, 8), 128, SM1, sB>>>(pl1, 512, pw2, 512, p_lat2, 3072, 1024, 3072, 512);
    ln3072<<<1024, 256, 0, sB>>>(p_lat2, sg_ln2g, sg_ln2b);
    conv16<<<12288, 64, 0, sB>>>(p_lat2, 256, pl2, 256, 12288);
    conv16<<<4352, 64, 0, sB>>>(sg_bw, 256, pwb, 256, 4225);
    gemm_mma<2,1><<<dim3(34, 96), 128, SM1, sB>>>(pl2, 256, pwb, 256, pbiash, 4225, 12288, 4225, 256);
    cudaEventRecord(evJoin, sB);

    // --- main stream: qkv path (single-pass fp16, fp16 q/k/v outputs) ---
    conv16<<<66560, 192>>>(x, CH, pxbf, CH, 66560);
    conv16<<<2304, 192>>>(qkv_w, CH, pwqkv, CH, 2304);
    gemm_mma<0,1><<<dim3(18, 520), 128, SM1>>>(pxbf, 768, pwqkv, 768, nullptr, 0, 66560, 2304, 768);

    cudaStreamWaitEvent(0, evJoin, 0);
    attn_kernel<<<NBATCH * NH, 160, ATT_SMEM>>>(qn_g, qn_b, kn_g, kn_b);

    // --- output projection ---
    gemm_mma<1,1><<<dim3(6, 520), 128, SM1>>>(pattbf, 768, pwproj, 768, out, 768, 66560, 768, 768);
}

// round 15
// speedup vs baseline: 6.5507x; 1.1277x over previous
#include <cuda_runtime.h>
#include <cuda_fp16.h>
#include <cstdint>

// ---------------- problem constants ----------------
#define NBATCH 1024
#define NT     65
#define CH     768
#define NH     12
#define DH     64
#define BLDC   4232   // padded bias row stride (16B-aligned rows)

// ---------------- fp32 scratch ----------------
__device__ __align__(16) float g_lat1[524288];    // [1024,512]
__device__ __align__(16) float g_lat2[3145728];   // [1024,3072]

// ---------------- fp16 scratch ----------------
__device__ __align__(16) __half g_biash[52002816]; // [B*H][4232] fp16 (4225 used)
__device__ __align__(16) __half g_qkvh[153354240]; // [66560][2304] packed q|k|v fp16
__device__ __align__(16) __half g_xbf[51118080];   // 66560 x 768
__device__ __align__(16) __half g_attbf[51118080]; // 66560 x 768 (by attn)
__device__ __align__(16) __half g_clsbf[786432];   // 1024 x 768
__device__ __align__(16) __half g_l1bf[524288];    // 1024 x 512
__device__ __align__(16) __half g_l2bf[3145728];   // 12288 x 256
__device__ __align__(16) __half g_wqkv[1769472];   // 2304 x 768
__device__ __align__(16) __half g_wproj[589824];   // 768 x 768
__device__ __align__(16) __half g_w1bf[393216];    // 512 x 768
__device__ __align__(16) __half g_w2bf[1572864];   // 3072 x 512
__device__ __align__(16) __half g_wbbf[1114112];   // 4352 x 256 (rows >= 4225 zero)

// ---------------- helpers ----------------
__device__ __forceinline__ uint32_t s2u(const void* p) {
    uint32_t a;
    asm("{ .reg .u64 t; cvta.to.shared.u64 t, %1; cvt.u32.u64 %0, t; }" : "=r"(a) : "l"(p));
    return a;
}
__device__ __forceinline__ void ldsm4(uint32_t* r, uint32_t addr) {
    asm volatile("ldmatrix.sync.aligned.m8n8.x4.shared.b16 {%0,%1,%2,%3}, [%4];"
        : "=r"(r[0]), "=r"(r[1]), "=r"(r[2]), "=r"(r[3]) : "r"(addr));
}
__device__ __forceinline__ void mma16816(float* d, const uint32_t* a, uint32_t b0, uint32_t b1) {
    asm volatile(
        "mma.sync.aligned.m16n8k16.row.col.f32.f16.f16.f32 "
        "{%0,%1,%2,%3}, {%4,%5,%6,%7}, {%8,%9}, {%0,%1,%2,%3};"
        : "+f"(d[0]), "+f"(d[1]), "+f"(d[2]), "+f"(d[3])
        : "r"(a[0]), "r"(a[1]), "r"(a[2]), "r"(a[3]), "r"(b0), "r"(b1));
}

// ---------------- fp32 -> fp16 plain ----------------
__global__ void conv16(const float* __restrict__ src, int lds,
                       __half* __restrict__ dst, int K, int rowsValid)
{
    const int r = blockIdx.x;
    const float4* s = (const float4*)(src + (size_t)r * lds);
    __half2* d = (__half2*)(dst + (size_t)r * K);
    const bool valid = r < rowsValid;
    for (int c = threadIdx.x; c < K / 4; c += blockDim.x) {
        float4 v = valid ? s[c] : make_float4(0.f, 0.f, 0.f, 0.f);
        d[c * 2]     = __half2(__float2half(v.x), __float2half(v.y));
        d[c * 2 + 1] = __half2(__float2half(v.z), __float2half(v.w));
    }
}

// ---------------- fp16 GEMM: C = A @ B^T ----------------
// MODE 1: fp32 store (float2, guarded). MODE 2: fp16 smem-staged coalesced store.
#define KC    32
#define LDS_  40
#define APART 10240u
#define NSTG  3
#define TS_   136   // staging tile fp16 stride (padded)

template<int MODE, int PASSES>
__global__ __launch_bounds__(128, 2)
void gemm_mma(const __half* __restrict__ A, int lda,
              const __half* __restrict__ B, int ldb,
              void* __restrict__ Cv, int ldc, int M, int N, int K)
{
    constexpr int NPARTS = PASSES + 1;
    constexpr uint32_t STGB = NPARTS * APART;

    extern __shared__ char dynsm[];
    const uint32_t sbase = s2u(dynsm);

    const int tid = threadIdx.x, wid = tid >> 5, lane = tid & 31;
    const int wm = wid & 1, wn = wid >> 1;
    const int bm = blockIdx.y * 128, bn = blockIdx.x * 128;
    const int nk = K / KC;

    float acc[4][8][4];
#pragma unroll
    for (int i = 0; i < 4; i++)
#pragma unroll
        for (int j = 0; j < 8; j++)
#pragma unroll
            for (int e = 0; e < 4; e++) acc[i][j][e] = 0.f;

    auto loads = [&](int t) {
        const uint32_t ub = sbase + (uint32_t)(t % NSTG) * STGB;
        const int kOff = t * KC;
#pragma unroll
        for (int i = 0; i < 4 * NPARTS; i++) {
            const int idx = tid + i * 128;
            const int part = idx >> 9;
            const int id2 = idx & 511;
            const int r = id2 >> 2, cc = id2 & 3;
            const uint32_t dst = ub + (uint32_t)part * APART +
                                 (uint32_t)(r * LDS_ + cc * 8) * 2;
            const void* g = (part == NPARTS - 1)
                ? (const void*)(B + (size_t)(bn + r) * ldb + kOff + cc * 8)
                : (const void*)(A + (size_t)(bm + r) * lda + part * K + kOff + cc * 8);
            asm volatile("cp.async.cg.shared.global [%0], [%1], 16;" :: "r"(dst), "l"(g));
        }
        asm volatile("cp.async.commit_group;");
    };

    loads(0);
    if (nk > 1) loads(1);

    for (int t = 0; t < nk; ++t) {
        if (t + 1 < nk) asm volatile("cp.async.wait_group 1;");
        else            asm volatile("cp.async.wait_group 0;");
        __syncthreads();
        if (t + 2 < nk) loads(t + 2);

        const uint32_t ub  = sbase + (uint32_t)(t % NSTG) * STGB;
        const uint32_t uAh = ub + (uint32_t)(wm * 64 * LDS_) * 2;
        const uint32_t uAl = uAh + APART;
        const uint32_t uB  = ub + (NPARTS - 1) * APART + (uint32_t)(wn * 64 * LDS_) * 2;
#pragma unroll
        for (int ks = 0; ks < 2; ++ks) {
            uint32_t ah[4][4], al[4][4], b[4][4];
#pragma unroll
            for (int mt = 0; mt < 4; ++mt) {
                const uint32_t ro = (uint32_t)((mt * 16 + (lane & 15)) * LDS_ +
                                               ks * 16 + (lane >> 4) * 8) * 2;
                ldsm4(ah[mt], uAh + ro);
                if (PASSES == 2) ldsm4(al[mt], uAl + ro);
            }
#pragma unroll
            for (int ng = 0; ng < 4; ++ng) {
                const uint32_t addr = uB +
                    (uint32_t)((ng * 16 + ((lane >> 4) & 1) * 8 + (lane & 7)) * LDS_ +
                               ks * 16 + ((lane >> 3) & 1) * 8) * 2;
                ldsm4(b[ng], addr);
            }
#pragma unroll
            for (int mt = 0; mt < 4; ++mt)
#pragma unroll
                for (int nt = 0; nt < 8; ++nt) {
                    const uint32_t b0 = b[nt >> 1][(nt & 1) * 2];
                    const uint32_t b1 = b[nt >> 1][(nt & 1) * 2 + 1];
                    mma16816(acc[mt][nt], ah[mt], b0, b1);
                    if (PASSES == 2) mma16816(acc[mt][nt], al[mt], b0, b1);
                }
        }
    }

    const int gr = lane >> 2, gc = (lane & 3) * 2;
    if (MODE == 1) {
        float* C = (float*)Cv;
#pragma unroll
        for (int mt = 0; mt < 4; ++mt)
#pragma unroll
            for (int nt = 0; nt < 8; ++nt)
#pragma unroll
                for (int hp = 0; hp < 2; ++hp) {
                    const int m = bm + wm * 64 + mt * 16 + gr + hp * 8;
                    const int n = bn + wn * 64 + nt * 8 + gc;
                    if (n + 1 < N) {
                        float2 v2 = make_float2(acc[mt][nt][hp * 2], acc[mt][nt][hp * 2 + 1]);
                        *(float2*)&C[(size_t)m * ldc + n] = v2;
                    } else if (n < N) {
                        C[(size_t)m * ldc + n] = acc[mt][nt][hp * 2];
                    }
                }
    } else {
        // staged fp16 epilogue: smem tile -> 16B coalesced writes
        __syncthreads();
        __half* tile = (__half*)dynsm;
#pragma unroll
        for (int mt = 0; mt < 4; ++mt)
#pragma unroll
            for (int nt = 0; nt < 8; ++nt)
#pragma unroll
                for (int hp = 0; hp < 2; ++hp) {
                    const int ml = wm * 64 + mt * 16 + gr + hp * 8;
                    const int nl = wn * 64 + nt * 8 + gc;
                    *(__half2*)&tile[ml * TS_ + nl] =
                        __floats2half2_rn(acc[mt][nt][hp * 2], acc[mt][nt][hp * 2 + 1]);
                }
        __syncthreads();
        __half* C = (__half*)Cv;
        for (int i = tid; i < 2048; i += 128) {
            const int r = i >> 4;
            const int c = (i & 15) << 3;
            const int n = bn + c;
            const size_t off = (size_t)(bm + r) * ldc + n;
            if (n + 7 < N) {
                *(uint4*)&C[off] = *(const uint4*)&tile[r * TS_ + c];
            } else if (n < N) {
#pragma unroll
                for (int e = 0; e < 8; ++e)
                    if (n + e < N) C[off + e] = tile[r * TS_ + c + e];
            }
        }
    }
}

// ---------------- block reduce helper ----------------
__device__ __forceinline__ float2 block_reduce2(float s, float ss, float* shm)
{
#pragma unroll
    for (int o = 16; o; o >>= 1) {
        s  += __shfl_xor_sync(0xffffffffu, s,  o);
        ss += __shfl_xor_sync(0xffffffffu, ss, o);
    }
    const int w = threadIdx.x >> 5, lane = threadIdx.x & 31;
    if (lane == 0) { shm[w] = s; shm[8 + w] = ss; }
    __syncthreads();
    if (threadIdx.x < 32) {
        s  = (lane < 8) ? shm[lane]     : 0.f;
        ss = (lane < 8) ? shm[8 + lane] : 0.f;
#pragma unroll
        for (int o = 4; o; o >>= 1) {
            s  += __shfl_xor_sync(0xffffffffu, s,  o);
            ss += __shfl_xor_sync(0xffffffffu, ss, o);
        }
        if (lane == 0) { shm[0] = s; shm[1] = ss; }
    }
    __syncthreads();
    return make_float2(shm[0], shm[1]);
}

__global__ __launch_bounds__(256)
void ln_silu512(float* __restrict__ data, const float* __restrict__ g, const float* __restrict__ b)
{
    __shared__ float shm[16];
    const int row = blockIdx.x, tid = threadIdx.x;
    float* p = data + (size_t)row * 512;
    float x0 = p[tid], x1 = p[tid + 256];
    float2 r = block_reduce2(x0 + x1, x0 * x0 + x1 * x1, shm);
    const float mean = r.x * (1.f / 512.f);
    const float var  = r.y * (1.f / 512.f) - mean * mean;
    const float inv  = rsqrtf(var + 1e-5f);
    float y0 = (x0 - mean) * inv * g[tid]       + b[tid];
    float y1 = (x1 - mean) * inv * g[tid + 256] + b[tid + 256];
    p[tid]       = y0 / (1.f + __expf(-y0));
    p[tid + 256] = y1 / (1.f + __expf(-y1));
}

__global__ __launch_bounds__(256)
void ln3072(float* __restrict__ data, const float* __restrict__ g, const float* __restrict__ b)
{
    __shared__ float shm[16];
    const int row = blockIdx.x, tid = threadIdx.x;
    float* p = data + (size_t)row * 3072;
    float x[12];
    float s = 0.f, ss = 0.f;
#pragma unroll
    for (int i = 0; i < 12; i++) {
        x[i] = p[tid + i * 256];
        s += x[i]; ss += x[i] * x[i];
    }
    float2 r = block_reduce2(s, ss, shm);
    const float mean = r.x * (1.f / 3072.f);
    const float var  = r.y * (1.f / 3072.f) - mean * mean;
    const float inv  = rsqrtf(var + 1e-5f);
#pragma unroll
    for (int i = 0; i < 12; i++) {
        const int c = tid + i * 256;
        p[c] = (x[i] - mean) * inv * g[c] + b[c];
    }
}

// ---------------- tensor-core fused attention (packed fp16 qkv + fp16 bias) ----------------
// 160 threads = 5 warps, one 16-row m-tile per warp.
// smem (fp16): Q[80][72] | K[80][72] | Vt[64][88] | P[80][88]
#define ATT_SQ 72
#define ATT_SP 88
#define ATT_OQ 0
#define ATT_OK 11520
#define ATT_OV 23040
#define ATT_OP 34304
#define ATT_SMEM 48384

__global__ __launch_bounds__(160)
void attn_kernel(const float* __restrict__ qn_g, const float* __restrict__ qn_b,
                 const float* __restrict__ kn_g, const float* __restrict__ kn_b)
{
    extern __shared__ __align__(16) char asm_[];
    __half* hQ = (__half*)(asm_ + ATT_OQ);
    __half* hK = (__half*)(asm_ + ATT_OK);
    __half* hV = (__half*)(asm_ + ATT_OV);
    __half* hP = (__half*)(asm_ + ATT_OP);
    const uint32_t uQ = s2u(hQ), uK = s2u(hK), uV = s2u(hV), uP = s2u(hP);

    const int bh  = blockIdx.x;
    const int tid = threadIdx.x;
    const int w = tid >> 5, lane = tid & 31;
    const int b = bh / NH, h = bh - b * NH;

    // packed qkv rows: row t of batch b at g_qkvh[(b*NT+t)*2304]; q|k|v at +0,+768,+1536
    const __half* gq = g_qkvh + (size_t)(b * NT) * 2304 + h * DH;
    const __half* gk = gq + CH;
    const __half* gv = gk + CH;

    // zero pads
    {
        const uint4 z = make_uint4(0, 0, 0, 0);
        uint4* pV = (uint4*)(asm_ + ATT_OV);
        for (int i = tid; i < 704; i += 160) pV[i] = z;
        uint4* pQ = (uint4*)(asm_ + ATT_OQ + 65 * ATT_SQ * 2);
        uint4* pK = (uint4*)(asm_ + ATT_OK + 65 * ATT_SQ * 2);
        for (int i = tid; i < 135; i += 160) { pQ[i] = z; pK[i] = z; }
    }
    __syncthreads();

    // LN q (x1/8), k -> fp16 smem; V -> transposed fp16 smem
    {
        const float qg0 = qn_g[lane], qg1 = qn_g[lane + 32];
        const float qb0 = qn_b[lane], qb1 = qn_b[lane + 32];
        const float kg0 = kn_g[lane], kg1 = kn_g[lane + 32];
        const float kb0 = kn_b[lane], kb1 = kn_b[lane + 32];
        for (int r = w; r < NT; r += 5) {
            float x0 = __half2float(gq[r * 2304 + lane]);
            float x1 = __half2float(gq[r * 2304 + lane + 32]);
            float s = x0 + x1, ss = x0 * x0 + x1 * x1;
#pragma unroll
            for (int o = 16; o; o >>= 1) {
                s  += __shfl_xor_sync(0xffffffffu, s,  o);
                ss += __shfl_xor_sync(0xffffffffu, ss, o);
            }
            float mean = s * (1.f / 64.f);
            float inv  = rsqrtf(ss * (1.f / 64.f) - mean * mean + 1e-5f);
            hQ[r * ATT_SQ + lane]      = __float2half(((x0 - mean) * inv * qg0 + qb0) * 0.125f);
            hQ[r * ATT_SQ + lane + 32] = __float2half(((x1 - mean) * inv * qg1 + qb1) * 0.125f);

            x0 = __half2float(gk[r * 2304 + lane]);
            x1 = __half2float(gk[r * 2304 + lane + 32]);
            s = x0 + x1; ss = x0 * x0 + x1 * x1;
#pragma unroll
            for (int o = 16; o; o >>= 1) {
                s  += __shfl_xor_sync(0xffffffffu, s,  o);
                ss += __shfl_xor_sync(0xffffffffu, ss, o);
            }
            mean = s * (1.f / 64.f);
            inv  = rsqrtf(ss * (1.f / 64.f) - mean * mean + 1e-5f);
            hK[r * ATT_SQ + lane]      = __float2half((x0 - mean) * inv * kg0 + kb0);
            hK[r * ATT_SQ + lane + 32] = __float2half((x1 - mean) * inv * kg1 + kb1);

            hV[lane * ATT_SP + r]        = gv[r * 2304 + lane];
            hV[(lane + 32) * ATT_SP + r] = gv[r * 2304 + lane + 32];
        }
    }
    __syncthreads();

    const __half* bp = g_biash + (size_t)bh * BLDC;
    const int gr = lane >> 2, gc = (lane & 3) * 2;
    const int mt = w;

    // ---- S = Q @ K^T ----
    float acc[9][4];
#pragma unroll
    for (int nt = 0; nt < 9; ++nt)
#pragma unroll
        for (int e = 0; e < 4; ++e) acc[nt][e] = 0.f;
#pragma unroll
    for (int kt = 0; kt < 4; ++kt) {
        uint32_t a[4];
        ldsm4(a, uQ + (uint32_t)((mt * 16 + (lane & 15)) * ATT_SQ + kt * 16 + (lane >> 4) * 8) * 2);
        uint32_t bf[5][4];
#pragma unroll
        for (int ng = 0; ng < 5; ++ng)
            ldsm4(bf[ng], uK + (uint32_t)((ng * 16 + ((lane >> 4) & 1) * 8 + (lane & 7)) * ATT_SQ +
                                          kt * 16 + ((lane >> 3) & 1) * 8) * 2);
#pragma unroll
        for (int nt = 0; nt < 9; ++nt)
            mma16816(acc[nt], a, bf[nt >> 1][(nt & 1) * 2], bf[nt >> 1][(nt & 1) * 2 + 1]);
    }
    // ---- bias + column mask ----
#pragma unroll
    for (int nt = 0; nt < 9; ++nt)
#pragma unroll
        for (int e = 0; e < 4; ++e) {
            const int i = mt * 16 + gr + (e >> 1) * 8;
            const int j = nt * 8 + gc + (e & 1);
            if (j >= NT)      acc[nt][e] = -1e30f;
            else if (i < NT)  acc[nt][e] += __half2float(bp[i * NT + j]);
        }
    // ---- softmax ----
#pragma unroll
    for (int hp = 0; hp < 2; ++hp) {
        const int e0 = hp * 2;
        float mx = -1e30f;
#pragma unroll
        for (int nt = 0; nt < 9; ++nt)
            mx = fmaxf(mx, fmaxf(acc[nt][e0], acc[nt][e0 + 1]));
        mx = fmaxf(mx, __shfl_xor_sync(0xffffffffu, mx, 1));
        mx = fmaxf(mx, __shfl_xor_sync(0xffffffffu, mx, 2));
        float sum = 0.f;
#pragma unroll
        for (int nt = 0; nt < 9; ++nt) {
            acc[nt][e0]     = __expf(acc[nt][e0]     - mx);
            acc[nt][e0 + 1] = __expf(acc[nt][e0 + 1] - mx);
            sum += acc[nt][e0] + acc[nt][e0 + 1];
        }
        sum += __shfl_xor_sync(0xffffffffu, sum, 1);
        sum += __shfl_xor_sync(0xffffffffu, sum, 2);
        const float inv = 1.f / sum;
        const int row = mt * 16 + gr + hp * 8;
#pragma unroll
        for (int nt = 0; nt < 9; ++nt)
            *(__half2*)&hP[row * ATT_SP + nt * 8 + gc] =
                __floats2half2_rn(acc[nt][e0] * inv, acc[nt][e0 + 1] * inv);
        *(__half2*)&hP[row * ATT_SP + 72 + gc] = __floats2half2_rn(0.f, 0.f);
    }
    __syncwarp();

    // ---- O = P @ Vt ----
    float oc[8][4];
#pragma unroll
    for (int nt = 0; nt < 8; ++nt)
#pragma unroll
        for (int e = 0; e < 4; ++e) oc[nt][e] = 0.f;
#pragma unroll
    for (int kt = 0; kt < 5; ++kt) {
        uint32_t a[4];
        ldsm4(a, uP + (uint32_t)((mt * 16 + (lane & 15)) * ATT_SP + kt * 16 + (lane >> 4) * 8) * 2);
        uint32_t bf[4][4];
#pragma unroll
        for (int ng = 0; ng < 4; ++ng)
            ldsm4(bf[ng], uV + (uint32_t)((ng * 16 + ((lane >> 4) & 1) * 8 + (lane & 7)) * ATT_SP +
                                          kt * 16 + ((lane >> 3) & 1) * 8) * 2);
#pragma unroll
        for (int nt = 0; nt < 8; ++nt)
            mma16816(oc[nt], a, bf[nt >> 1][(nt & 1) * 2], bf[nt >> 1][(nt & 1) * 2 + 1]);
    }
    // ---- store O fp16 ----
#pragma unroll
    for (int hp = 0; hp < 2; ++hp) {
        const int i = mt * 16 + gr + hp * 8;
        if (i < NT) {
            __half* oh = g_attbf + ((size_t)(b * NT + i)) * CH + h * DH;
#pragma unroll
            for (int nt = 0; nt < 8; ++nt)
                *(__half2*)&oh[nt * 8 + gc] =
                    __floats2half2_rn(oc[nt][hp * 2], oc[nt][hp * 2 + 1]);
        }
    }
}

// ---------------- host launcher ----------------
extern "C" void kernel_launch(void* const* d_in, const int* in_sizes, int n_in,
                              void* d_out, int out_size)
{
    const float* x       = (const float*)d_in[0];
    const float* qkv_w   = (const float*)d_in[1];
    const float* proj_w  = (const float*)d_in[2];
    const float* qn_g    = (const float*)d_in[3];
    const float* qn_b    = (const float*)d_in[4];
    const float* kn_g    = (const float*)d_in[5];
    const float* kn_b    = (const float*)d_in[6];
    const float* sg_w1   = (const float*)d_in[7];
    const float* sg_ln1g = (const float*)d_in[8];
    const float* sg_ln1b = (const float*)d_in[9];
    const float* sg_w2   = (const float*)d_in[10];
    const float* sg_ln2g = (const float*)d_in[11];
    const float* sg_ln2b = (const float*)d_in[12];
    const float* sg_bw   = (const float*)d_in[13];
    float* out = (float*)d_out;

    float *p_lat1, *p_lat2;
    cudaGetSymbolAddress((void**)&p_lat1, g_lat1);
    cudaGetSymbolAddress((void**)&p_lat2, g_lat2);
    __half *pbiash, *pqkvh, *pxbf, *pattbf, *pwqkv, *pwproj, *pcls, *pw1, *pl1, *pw2, *pl2, *pwb;
    cudaGetSymbolAddress((void**)&pbiash,g_biash);
    cudaGetSymbolAddress((void**)&pqkvh, g_qkvh);
    cudaGetSymbolAddress((void**)&pxbf,  g_xbf);
    cudaGetSymbolAddress((void**)&pattbf,g_attbf);
    cudaGetSymbolAddress((void**)&pwqkv, g_wqkv);
    cudaGetSymbolAddress((void**)&pwproj,g_wproj);
    cudaGetSymbolAddress((void**)&pcls,  g_clsbf);
    cudaGetSymbolAddress((void**)&pw1,   g_w1bf);
    cudaGetSymbolAddress((void**)&pl1,   g_l1bf);
    cudaGetSymbolAddress((void**)&pw2,   g_w2bf);
    cudaGetSymbolAddress((void**)&pl2,   g_l2bf);
    cudaGetSymbolAddress((void**)&pwb,   g_wbbf);

    const int SM1 = NSTG * 2 * (int)APART;   // 61440 (1-pass)
    cudaFuncSetAttribute(gemm_mma<1,1>, cudaFuncAttributeMaxDynamicSharedMemorySize, SM1);
    cudaFuncSetAttribute(gemm_mma<2,1>, cudaFuncAttributeMaxDynamicSharedMemorySize, SM1);
    cudaFuncSetAttribute(attn_kernel, cudaFuncAttributeMaxDynamicSharedMemorySize, ATT_SMEM);

    static cudaStream_t sB = nullptr;
    static cudaEvent_t evFork = nullptr, evJoin = nullptr;
    if (sB == nullptr) {
        cudaStreamCreateWithFlags(&sB, cudaStreamNonBlocking);
        cudaEventCreateWithFlags(&evFork, cudaEventDisableTiming);
        cudaEventCreateWithFlags(&evJoin, cudaEventDisableTiming);
    }

    cudaEventRecord(evFork, 0);
    cudaStreamWaitEvent(sB, evFork, 0);

    // --- side stream: bias path (single-pass fp16) + proj weight conversion ---
    conv16<<<1024, 192, 0, sB>>>(x, NT * CH, pcls, CH, 1024);
    conv16<<<512, 192, 0, sB>>>(sg_w1, CH, pw1, CH, 512);
    conv16<<<768, 192, 0, sB>>>(proj_w, CH, pwproj, CH, 768);
    gemm_mma<1,1><<<dim3(4, 8), 128, SM1, sB>>>(pcls, 768, pw1, 768, p_lat1, 512, 1024, 512, 768);
    ln_silu512<<<1024, 256, 0, sB>>>(p_lat1, sg_ln1g, sg_ln1b);
    conv16<<<1024, 128, 0, sB>>>(p_lat1, 512, pl1, 512, 1024);
    conv16<<<3072, 128, 0, sB>>>(sg_w2, 512, pw2, 512, 3072);
    gemm_mma<1,1><<<dim3(24, 8), 128, SM1, sB>>>(pl1, 512, pw2, 512, p_lat2, 3072, 1024, 3072, 512);
    ln3072<<<1024, 256, 0, sB>>>(p_lat2, sg_ln2g, sg_ln2b);
    conv16<<<12288, 64, 0, sB>>>(p_lat2, 256, pl2, 256, 12288);
    conv16<<<4352, 64, 0, sB>>>(sg_bw, 256, pwb, 256, 4225);
    gemm_mma<2,1><<<dim3(34, 96), 128, SM1, sB>>>(pl2, 256, pwb, 256, pbiash, BLDC, 12288, 4225, 256);
    cudaEventRecord(evJoin, sB);

    // --- main stream: qkv path (single-pass fp16, packed fp16 output) ---
    conv16<<<66560, 192>>>(x, CH, pxbf, CH, 66560);
    conv16<<<2304, 192>>>(qkv_w, CH, pwqkv, CH, 2304);
    gemm_mma<2,1><<<dim3(18, 520), 128, SM1>>>(pxbf, 768, pwqkv, 768, pqkvh, 2304, 66560, 2304, 768);

    cudaStreamWaitEvent(0, evJoin, 0);
    attn_kernel<<<NBATCH * NH, 160, ATT_SMEM>>>(qn_g, qn_b, kn_g, kn_b);

    // --- output projection ---
    gemm_mma<1,1><<<dim3(6, 520), 128, SM1>>>(pattbf, 768, pwproj, 768, out, 768, 66560, 768, 768);
}